// round 1
// baseline (speedup 1.0000x reference)
#include <cuda_runtime.h>
#include <cuda_bf16.h>
#include <math.h>

// ---------------------------------------------------------------------------
// Problem constants
// ---------------------------------------------------------------------------
#define BB    2
#define QQ    1024
#define HH    32
#define KVH   8
#define HD    64
#define HS    2048
#define K2HS  4096          // 2*HS
#define LCK   2
#define NREP  4             // H / KVH
#define SCALE 0.125f        // 1/sqrt(HD)

#define NEG_INF (__int_as_float(0xff800000))

// ---------------------------------------------------------------------------
// Scratch (no cudaMalloc allowed)
// ---------------------------------------------------------------------------
__device__ float g_q  [BB * QQ * HH  * HD];   // [b,q,h,d]   16 MB
__device__ float g_k  [BB * QQ * KVH * HD];   // [b,q,kvh,d]  4 MB
__device__ float g_v  [BB * QQ * KVH * HD];   //              4 MB
__device__ float g_att[BB * QQ * HH  * HD];   // [b,q,h*d]   16 MB

// ---------------------------------------------------------------------------
// Generic NT SGEMM: C[m,n] = sum_k A[m,k] * Bw[n,k]
// A: [M,K] row-major, Bw: [N,K] row-major, C: [M,N] row-major
// BM=BN=128, BK=16, 256 threads, 8x8 per thread.
// Requires M%128==0, N%128==0, K%16==0 (true for all our shapes).
// ---------------------------------------------------------------------------
__global__ __launch_bounds__(256)
void sgemm_nt(const float* __restrict__ A, const float* __restrict__ Bw,
              float* __restrict__ C, int M, int N, int K)
{
    __shared__ float As[16][132];   // transposed: As[k][m]
    __shared__ float Bs[16][132];   // transposed: Bs[k][n]

    const int tid = threadIdx.x;
    const int tx = tid & 15;        // n direction
    const int ty = tid >> 4;        // m direction
    const int bm = blockIdx.y * 128;
    const int bn = blockIdx.x * 128;

    const float* Ab = A  + (size_t)bm * K;
    const float* Bb = Bw + (size_t)bn * K;

    float acc[8][8];
    #pragma unroll
    for (int i = 0; i < 8; i++)
        #pragma unroll
        for (int j = 0; j < 8; j++) acc[i][j] = 0.f;

    for (int kt = 0; kt < K; kt += 16) {
        // load 128x16 tiles of A and B, store transposed
        #pragma unroll
        for (int r = 0; r < 2; r++) {
            int idx = tid + 256 * r;        // 0..511
            int row = idx >> 2;             // 0..127
            int c4  = idx & 3;              // 0..3 (float4 column)
            float4 a = *(const float4*)(Ab + (size_t)row * K + kt + c4 * 4);
            As[c4 * 4 + 0][row] = a.x;
            As[c4 * 4 + 1][row] = a.y;
            As[c4 * 4 + 2][row] = a.z;
            As[c4 * 4 + 3][row] = a.w;
            float4 b = *(const float4*)(Bb + (size_t)row * K + kt + c4 * 4);
            Bs[c4 * 4 + 0][row] = b.x;
            Bs[c4 * 4 + 1][row] = b.y;
            Bs[c4 * 4 + 2][row] = b.z;
            Bs[c4 * 4 + 3][row] = b.w;
        }
        __syncthreads();

        #pragma unroll
        for (int k = 0; k < 16; k++) {
            float ar[8], br[8];
            *(float4*)(ar)     = *(const float4*)&As[k][ty * 8];
            *(float4*)(ar + 4) = *(const float4*)&As[k][ty * 8 + 4];
            *(float4*)(br)     = *(const float4*)&Bs[k][tx * 8];
            *(float4*)(br + 4) = *(const float4*)&Bs[k][tx * 8 + 4];
            #pragma unroll
            for (int i = 0; i < 8; i++)
                #pragma unroll
                for (int j = 0; j < 8; j++)
                    acc[i][j] += ar[i] * br[j];
        }
        __syncthreads();
    }

    #pragma unroll
    for (int i = 0; i < 8; i++) {
        float* cp = C + (size_t)(bm + ty * 8 + i) * N + bn + tx * 8;
        *(float4*)(cp)     = make_float4(acc[i][0], acc[i][1], acc[i][2], acc[i][3]);
        *(float4*)(cp + 4) = make_float4(acc[i][4], acc[i][5], acc[i][6], acc[i][7]);
    }
}

// ---------------------------------------------------------------------------
// RoPE in-place on q and k. One thread per (token, head, d<32) pair.
// Angle generated in double precision (robust vs fast-math sin/cos).
// ---------------------------------------------------------------------------
__global__ void rope_kernel(float* __restrict__ q, float* __restrict__ k,
                            const int* __restrict__ pos_ids)
{
    const int NQ = BB * QQ * HH  * 32;   // 2,097,152
    const int NK = BB * QQ * KVH * 32;   //   524,288
    int i = blockIdx.x * blockDim.x + threadIdx.x;
    if (i >= NQ + NK) return;

    float* base;
    int m, d;
    if (i < NQ) {
        d = i & 31;
        int h = (i >> 5) & (HH - 1);
        m = i >> 10;                              // token index b*Q+q
        base = q + (size_t)m * (HH * HD) + h * HD + d;
    } else {
        int j = i - NQ;
        d = j & 31;
        int h = (j >> 5) & (KVH - 1);
        m = j >> 8;
        base = k + (size_t)m * (KVH * HD) + h * HD + d;
    }

    int pos = pos_ids[m] + LCK;
    double inv = pow(10000.0, -(double)d / 32.0);
    double ang = (double)pos * inv;
    float c = (float)cos(ang);
    float s = (float)sin(ang);

    float a = base[0], b2 = base[32];
    base[0]  = a  * c - b2 * s;
    base[32] = b2 * c + a  * s;
}

// ---------------------------------------------------------------------------
// Attention: one block per (qtile of 64, h, b). 256 threads (16x16 grid,
// 4x4 micro-tile per thread). Flash-style streaming over cache_k[0] key
// tiles + two diagonal tail steps (cache_k[1], fresh k with GQA).
// ---------------------------------------------------------------------------
#define SROW 68   // padded row stride (floats), 16B aligned, bank-friendly
#define ATTN_SMEM_FLOATS (4 * 64 * SROW + 4 * 64 + 2 * 4 * 64)
#define ATTN_SMEM_BYTES  (ATTN_SMEM_FLOATS * 4)

__global__ __launch_bounds__(256)
void attn_kernel(const float* __restrict__ gq, const float* __restrict__ gk,
                 const float* __restrict__ gv,
                 const float* __restrict__ cache_k,
                 const float* __restrict__ cache_v,
                 float* __restrict__ gatt)
{
    extern __shared__ float sm[];
    float* Qs   = sm;                    // [64][SROW] transposed: Qs[d][q]
    float* Ks   = Qs + 64 * SROW;        // transposed [d][key] for S; natural for tail
    float* Vs   = Ks + 64 * SROW;        // natural [key][d]
    float* St   = Vs + 64 * SROW;        // [key][q]  (S then P)
    float* mrow = St + 64 * SROW;        // [64]
    float* lrow = mrow + 64;
    float* arow = lrow + 64;             // alpha
    float* prow = arow + 64;             // tail weight
    float* pmax = prow + 64;             // [4][64]
    float* psum = pmax + 4 * 64;         // [4][64]

    const int tid = threadIdx.x;
    const int tx = tid & 15;             // d / key direction
    const int ty = tid >> 4;             // q direction
    const int qt = blockIdx.x;
    const int h  = blockIdx.y;
    const int b  = blockIdx.z;
    const int qb = qt * 64;

    // ---- load Q tile (pre-scaled), transposed ----
    const float* qptr = gq + ((size_t)(b * QQ + qb)) * (HH * HD) + h * HD;
    #pragma unroll
    for (int r = 0; r < 4; r++) {
        int idx = tid + 256 * r;          // 0..1023
        int row = idx >> 4, c4 = idx & 15;
        float4 v = *(const float4*)(qptr + (size_t)row * (HH * HD) + c4 * 4);
        Qs[(c4 * 4 + 0) * SROW + row] = v.x * SCALE;
        Qs[(c4 * 4 + 1) * SROW + row] = v.y * SCALE;
        Qs[(c4 * 4 + 2) * SROW + row] = v.z * SCALE;
        Qs[(c4 * 4 + 3) * SROW + row] = v.w * SCALE;
    }
    if (tid < 64) { mrow[tid] = NEG_INF; lrow[tid] = 0.f; }
    __syncthreads();

    float acc[4][4];
    #pragma unroll
    for (int i = 0; i < 4; i++)
        #pragma unroll
        for (int j = 0; j < 4; j++) acc[i][j] = 0.f;

    const float* k0 = cache_k + ((size_t)b * HH + h) * QQ * HD;   // cache_k[0][b][h]
    const float* v0 = cache_v + ((size_t)b * HH + h) * QQ * HD;

    const int row = tid & 63;
    const int seg = tid >> 6;

    // ---- main causal loop over key tiles of cache_k[0] ----
    for (int kt = 0; kt <= qt; kt++) {
        const int kb = kt * 64;
        // load K (transposed) and V (natural)
        #pragma unroll
        for (int r = 0; r < 4; r++) {
            int idx = tid + 256 * r;
            int krow = idx >> 4, c4 = idx & 15;
            float4 kv = *(const float4*)(k0 + (size_t)(kb + krow) * HD + c4 * 4);
            Ks[(c4 * 4 + 0) * SROW + krow] = kv.x;
            Ks[(c4 * 4 + 1) * SROW + krow] = kv.y;
            Ks[(c4 * 4 + 2) * SROW + krow] = kv.z;
            Ks[(c4 * 4 + 3) * SROW + krow] = kv.w;
            float4 vv = *(const float4*)(v0 + (size_t)(kb + krow) * HD + c4 * 4);
            *(float4*)&Vs[krow * SROW + c4 * 4] = vv;
        }
        __syncthreads();

        // S = (Q*scale) @ K^T  (4x4 per thread)
        float s[4][4];
        #pragma unroll
        for (int i = 0; i < 4; i++)
            #pragma unroll
            for (int j = 0; j < 4; j++) s[i][j] = 0.f;
        #pragma unroll 16
        for (int d = 0; d < 64; d++) {
            float4 aq = *(const float4*)&Qs[d * SROW + ty * 4];
            float4 bk = *(const float4*)&Ks[d * SROW + tx * 4];
            float ar[4] = {aq.x, aq.y, aq.z, aq.w};
            float br[4] = {bk.x, bk.y, bk.z, bk.w};
            #pragma unroll
            for (int i = 0; i < 4; i++)
                #pragma unroll
                for (int j = 0; j < 4; j++)
                    s[i][j] += ar[i] * br[j];
        }
        if (kt == qt) {   // causal mask on diagonal tile
            #pragma unroll
            for (int i = 0; i < 4; i++)
                #pragma unroll
                for (int j = 0; j < 4; j++)
                    if (tx * 4 + j > ty * 4 + i) s[i][j] = -1e30f;
        }
        // store S transposed: St[key][q]
        #pragma unroll
        for (int j = 0; j < 4; j++) {
            float4 t = make_float4(s[0][j], s[1][j], s[2][j], s[3][j]);
            *(float4*)&St[(tx * 4 + j) * SROW + ty * 4] = t;
        }
        __syncthreads();

        // softmax phase 1: partial row max (4 segs x 16 keys)
        float pm = NEG_INF;
        #pragma unroll
        for (int kk = 0; kk < 16; kk++)
            pm = fmaxf(pm, St[(seg * 16 + kk) * SROW + row]);
        pmax[seg * 64 + row] = pm;
        __syncthreads();

        // phase 2: combine, compute alpha
        if (tid < 64) {
            float mn = fmaxf(fmaxf(pmax[tid], pmax[64 + tid]),
                             fmaxf(pmax[128 + tid], pmax[192 + tid]));
            mn = fmaxf(mn, mrow[tid]);
            arow[tid] = __expf(mrow[tid] - mn);
            mrow[tid] = mn;
        }
        __syncthreads();

        // phase 3: exponentiate, partial sums
        float mr = mrow[row];
        float ps = 0.f;
        #pragma unroll
        for (int kk = 0; kk < 16; kk++) {
            int kidx = (seg * 16 + kk) * SROW + row;
            float p = __expf(St[kidx] - mr);
            St[kidx] = p;
            ps += p;
        }
        psum[seg * 64 + row] = ps;
        __syncthreads();

        // phase 4: l update (tid<64) runs concurrently with rescale+PV
        if (tid < 64)
            lrow[tid] = lrow[tid] * arow[tid] +
                        psum[tid] + psum[64 + tid] + psum[128 + tid] + psum[192 + tid];

        // rescale accumulators
        #pragma unroll
        for (int i = 0; i < 4; i++) {
            float a = arow[ty * 4 + i];
            #pragma unroll
            for (int j = 0; j < 4; j++) acc[i][j] *= a;
        }
        // PV: acc += P^T-tile @ V-tile
        #pragma unroll 16
        for (int kk = 0; kk < 64; kk++) {
            float4 ap = *(const float4*)&St[kk * SROW + ty * 4];
            float4 bv = *(const float4*)&Vs[kk * SROW + tx * 4];
            float ar[4] = {ap.x, ap.y, ap.z, ap.w};
            float br[4] = {bv.x, bv.y, bv.z, bv.w};
            #pragma unroll
            for (int i = 0; i < 4; i++)
                #pragma unroll
                for (int j = 0; j < 4; j++)
                    acc[i][j] += ar[i] * br[j];
        }
        __syncthreads();
    }

    // ---- two diagonal tail steps: cache_k[1]/cache_v[1], then fresh k/v ----
    #pragma unroll 1
    for (int e = 0; e < 2; e++) {
        const float* tk;
        const float* tv;
        size_t stride;
        if (e == 0) {
            size_t off = (((size_t)(LCK - 1) * BB + b) * HH + h) * QQ * HD + (size_t)qb * HD;
            // cache_k[1][b][h][qb..qb+63][:] (layout [LCK,B,H,Q,HD], index 1)
            off = (((size_t)BB + b) * HH + h) * QQ * HD + (size_t)qb * HD;
            tk = cache_k + off;
            tv = cache_v + off;
            stride = HD;
        } else {
            size_t off = (size_t)(b * QQ + qb) * (KVH * HD) + (size_t)(h >> 2) * HD;
            tk = gk + off;
            tv = gv + off;
            stride = KVH * HD;
        }
        #pragma unroll
        for (int r = 0; r < 4; r++) {
            int idx = tid + 256 * r;
            int krow = idx >> 4, c4 = idx & 15;
            *(float4*)&Ks[krow * SROW + c4 * 4] = *(const float4*)(tk + (size_t)krow * stride + c4 * 4);
            *(float4*)&Vs[krow * SROW + c4 * 4] = *(const float4*)(tv + (size_t)krow * stride + c4 * 4);
        }
        __syncthreads();

        if (tid < 64) {
            float sdot = 0.f;
            #pragma unroll 16
            for (int d = 0; d < 64; d++)
                sdot += Qs[d * SROW + tid] * Ks[tid * SROW + d];
            float mo = mrow[tid];
            float mn = fmaxf(mo, sdot);
            float a = __expf(mo - mn);
            float p = __expf(sdot - mn);
            mrow[tid] = mn;
            lrow[tid] = lrow[tid] * a + p;
            arow[tid] = a;
            prow[tid] = p;
        }
        __syncthreads();

        #pragma unroll
        for (int i = 0; i < 4; i++) {
            float a = arow[ty * 4 + i];
            float p = prow[ty * 4 + i];
            float4 vv = *(const float4*)&Vs[(ty * 4 + i) * SROW + tx * 4];
            acc[i][0] = acc[i][0] * a + p * vv.x;
            acc[i][1] = acc[i][1] * a + p * vv.y;
            acc[i][2] = acc[i][2] * a + p * vv.z;
            acc[i][3] = acc[i][3] * a + p * vv.w;
        }
        __syncthreads();
    }

    // ---- normalize and write: gatt[b, qpos, h*64 + d] ----
    float* outp = gatt + ((size_t)(b * QQ + qb)) * (HH * HD) + h * HD;
    #pragma unroll
    for (int i = 0; i < 4; i++) {
        float invl = 1.0f / lrow[ty * 4 + i];
        float4 o = make_float4(acc[i][0] * invl, acc[i][1] * invl,
                               acc[i][2] * invl, acc[i][3] * invl);
        *(float4*)(outp + (size_t)(ty * 4 + i) * (HH * HD) + tx * 4) = o;
    }
}

// ---------------------------------------------------------------------------
// Launch
// ---------------------------------------------------------------------------
extern "C" void kernel_launch(void* const* d_in, const int* in_sizes, int n_in,
                              void* d_out, int out_size)
{
    (void)in_sizes; (void)n_in; (void)out_size;

    const float* hidden = (const float*)d_in[0];   // [B,Q,4096]
    const float* Wq     = (const float*)d_in[1];   // [2048,4096]
    const float* Wk     = (const float*)d_in[2];   // [512,4096]
    const float* Wv     = (const float*)d_in[3];   // [512,4096]
    const float* Wo     = (const float*)d_in[4];   // [2048,2048]
    const float* ck     = (const float*)d_in[5];   // [2,2,32,1024,64]
    const float* cv     = (const float*)d_in[6];
    // d_in[7]: attention_mask (exactly causal) — handled by index masking
    const int*   pos    = (const int*)d_in[8];     // [B,Q]
    float* out = (float*)d_out;                    // [B,Q,2048]

    float *gq, *gk, *gv, *gatt;
    cudaGetSymbolAddress((void**)&gq,   g_q);
    cudaGetSymbolAddress((void**)&gk,   g_k);
    cudaGetSymbolAddress((void**)&gv,   g_v);
    cudaGetSymbolAddress((void**)&gatt, g_att);

    cudaFuncSetAttribute(attn_kernel,
                         cudaFuncAttributeMaxDynamicSharedMemorySize,
                         ATTN_SMEM_BYTES);

    const int M = BB * QQ;   // 2048

    // QKV projections
    sgemm_nt<<<dim3((HH * HD) / 128, M / 128), 256>>>(hidden, Wq, gq, M, HH * HD,  K2HS);
    sgemm_nt<<<dim3((KVH * HD) / 128, M / 128), 256>>>(hidden, Wk, gk, M, KVH * HD, K2HS);
    sgemm_nt<<<dim3((KVH * HD) / 128, M / 128), 256>>>(hidden, Wv, gv, M, KVH * HD, K2HS);

    // RoPE (q and k in-place)
    {
        int total = BB * QQ * (HH + KVH) * 32;
        rope_kernel<<<(total + 255) / 256, 256>>>(gq, gk, pos);
    }

    // Attention
    attn_kernel<<<dim3(QQ / 64, HH, BB), 256, ATTN_SMEM_BYTES>>>(gq, gk, gv, ck, cv, gatt);

    // Output projection -> d_out
    sgemm_nt<<<dim3(HS / 128, M / 128), 256>>>(gatt, Wo, out, M, HS, HH * HD);
}

// round 3
// speedup vs baseline: 2.1784x; 2.1784x over previous
#include <cuda_runtime.h>
#include <cuda_bf16.h>
#include <math.h>
#include <stdint.h>

// ---------------------------------------------------------------------------
// Problem constants
// ---------------------------------------------------------------------------
#define BB    2
#define QQ    1024
#define HH    32
#define KVH   8
#define HD    64
#define HS    2048
#define K2HS  4096          // 2*HS
#define LCK   2
#define SCALE 0.125f        // 1/sqrt(HD)

#define NEG_INF (__int_as_float(0xff800000))

// ---------------------------------------------------------------------------
// Scratch (no cudaMalloc allowed)
// ---------------------------------------------------------------------------
__device__ float g_q  [BB * QQ * HH  * HD];
__device__ float g_k  [BB * QQ * KVH * HD];
__device__ float g_v  [BB * QQ * KVH * HD];
__device__ float g_att[BB * QQ * HH  * HD];

// bf16 split-precision operands
__device__ __nv_bfloat16 c_hid_h[2048 * 4096];
__device__ __nv_bfloat16 c_hid_l[2048 * 4096];
__device__ __nv_bfloat16 c_wq_h [2048 * 4096];
__device__ __nv_bfloat16 c_wq_l [2048 * 4096];
__device__ __nv_bfloat16 c_wk_h [512  * 4096];
__device__ __nv_bfloat16 c_wk_l [512  * 4096];
__device__ __nv_bfloat16 c_wv_h [512  * 4096];
__device__ __nv_bfloat16 c_wv_l [512  * 4096];
__device__ __nv_bfloat16 c_wo_h [2048 * 2048];
__device__ __nv_bfloat16 c_wo_l [2048 * 2048];
__device__ __nv_bfloat16 c_at_h [2048 * 2048];
__device__ __nv_bfloat16 c_at_l [2048 * 2048];

// ---------------------------------------------------------------------------
// PTX helpers (mma.sync / ldmatrix / cp.async) — all plain-sm_100 legal
// ---------------------------------------------------------------------------
__device__ __forceinline__ uint32_t smem_u32(const void* p) {
    uint32_t a;
    asm("{ .reg .u64 t; cvta.to.shared.u64 t, %1; cvt.u32.u64 %0, t; }"
        : "=r"(a) : "l"(p));
    return a;
}

#define CP_ASYNC16(dst, src) \
    asm volatile("cp.async.cg.shared.global [%0], [%1], 16;" \
                 :: "r"((uint32_t)(dst)), "l"(src))
#define CP_COMMIT() asm volatile("cp.async.commit_group;" ::: "memory")
#define CP_WAIT2()  asm volatile("cp.async.wait_group 2;" ::: "memory")

__device__ __forceinline__ void ldsm4(uint32_t* r, uint32_t addr) {
    asm volatile("ldmatrix.sync.aligned.m8n8.x4.shared.b16 {%0,%1,%2,%3}, [%4];"
        : "=r"(r[0]), "=r"(r[1]), "=r"(r[2]), "=r"(r[3]) : "r"(addr));
}

__device__ __forceinline__ void mma_bf16(float* d, const uint32_t* a, const uint32_t* b) {
    asm volatile(
        "mma.sync.aligned.m16n8k16.row.col.f32.bf16.bf16.f32 "
        "{%0,%1,%2,%3}, {%4,%5,%6,%7}, {%8,%9}, {%0,%1,%2,%3};"
        : "+f"(d[0]), "+f"(d[1]), "+f"(d[2]), "+f"(d[3])
        : "r"(a[0]), "r"(a[1]), "r"(a[2]), "r"(a[3]), "r"(b[0]), "r"(b[1]));
}

// ---------------------------------------------------------------------------
// fp32 -> (bf16 hi, bf16 lo) split conversion
// ---------------------------------------------------------------------------
__global__ void convert_hl(const float* __restrict__ x, __nv_bfloat16* __restrict__ h,
                           __nv_bfloat16* __restrict__ l, int n4)
{
    int i = blockIdx.x * blockDim.x + threadIdx.x;
    if (i >= n4) return;
    float4 v = ((const float4*)x)[i];
    __nv_bfloat16 h0 = __float2bfloat16(v.x);
    __nv_bfloat16 h1 = __float2bfloat16(v.y);
    __nv_bfloat16 h2 = __float2bfloat16(v.z);
    __nv_bfloat16 h3 = __float2bfloat16(v.w);
    __nv_bfloat16 l0 = __float2bfloat16(v.x - __bfloat162float(h0));
    __nv_bfloat16 l1 = __float2bfloat16(v.y - __bfloat162float(h1));
    __nv_bfloat16 l2 = __float2bfloat16(v.z - __bfloat162float(h2));
    __nv_bfloat16 l3 = __float2bfloat16(v.w - __bfloat162float(h3));
    __nv_bfloat162* hp = (__nv_bfloat162*)h + i * 2;
    __nv_bfloat162* lp = (__nv_bfloat162*)l + i * 2;
    hp[0] = __halves2bfloat162(h0, h1);
    hp[1] = __halves2bfloat162(h2, h3);
    lp[0] = __halves2bfloat162(l0, l1);
    lp[1] = __halves2bfloat162(l2, l3);
}

// ---------------------------------------------------------------------------
// split-bf16 NT GEMM via mma.sync (tensor pipe).
// C[m,n] = sum_k A[m,k]*B[n,k].  Tile 128x128, BK=32, 3-stage cp.async.
// 8 warps: 4 (m) x 2 (n); warp tile 32x64.
// SMEM row stride 80B -> conflict-free ldmatrix (5 mod 8 bank groups).
// Up to 3 output segments sharing A (fused QKV).
// ---------------------------------------------------------------------------
#define ROWB   80
#define TILEB  (128 * ROWB)          // 10240
#define STAGEB (4 * TILEB)           // 40960
#define NSTAGE 3
#define GSMEM_BYTES (NSTAGE * STAGEB)  // 122880

__device__ __forceinline__ void load_stage(
    uint32_t sb, int buf, const char* Ah, const char* Al,
    const char* Bh, const char* Bl, int bm, int bn, int kb, int K, int tid)
{
    uint32_t st = sb + buf * STAGEB;
    #pragma unroll
    for (int t4 = 0; t4 < 4; t4++) {
        const char* base = (t4 == 0) ? Ah : (t4 == 1) ? Al : (t4 == 2) ? Bh : Bl;
        int rb = (t4 < 2) ? bm : bn;
        #pragma unroll
        for (int j = 0; j < 2; j++) {
            int c   = tid + 256 * j;        // 0..511
            int row = c >> 2;               // 0..127
            int ch  = c & 3;                // 16B chunk
            uint32_t sa = st + t4 * TILEB + row * ROWB + ch * 16;
            const char* ga = base + ((size_t)(rb + row) * K + kb + ch * 8) * 2;
            CP_ASYNC16(sa, ga);
        }
    }
    CP_COMMIT();
}

__global__ __launch_bounds__(256, 1)
void gemm_tc(const __nv_bfloat16* __restrict__ Ah_, const __nv_bfloat16* __restrict__ Al_,
             const __nv_bfloat16* B0h, const __nv_bfloat16* B0l, float* C0, int N0,
             const __nv_bfloat16* B1h, const __nv_bfloat16* B1l, float* C1, int N1,
             const __nv_bfloat16* B2h, const __nv_bfloat16* B2l, float* C2, int N2,
             int K)
{
    extern __shared__ __align__(16) char smx[];
    uint32_t sb = smem_u32(smx);
    const int tid  = threadIdx.x;
    const int wid  = tid >> 5;
    const int lane = tid & 31;
    const int wm   = wid >> 1;          // 0..3
    const int wn   = wid & 1;           // 0..1
    const int bm   = blockIdx.y * 128;

    // output-segment select (fused QKV)
    int xt = blockIdx.x;
    const __nv_bfloat16 *Bh, *Bl; float* C; int ldc, bn;
    int t0 = N0 >> 7, t1 = N1 >> 7;
    if (xt < t0)           { Bh = B0h; Bl = B0l; C = C0; ldc = N0; bn = xt << 7; }
    else if (xt < t0 + t1) { Bh = B1h; Bl = B1l; C = C1; ldc = N1; bn = (xt - t0) << 7; }
    else                   { Bh = B2h; Bl = B2l; C = C2; ldc = N2; bn = (xt - t0 - t1) << 7; }

    const char* cAh = (const char*)Ah_;
    const char* cAl = (const char*)Al_;
    const char* cBh = (const char*)Bh;
    const char* cBl = (const char*)Bl;

    float acc[2][8][4];
    #pragma unroll
    for (int i = 0; i < 2; i++)
        #pragma unroll
        for (int j = 0; j < 8; j++)
            #pragma unroll
            for (int q = 0; q < 4; q++) acc[i][j][q] = 0.f;

    const int nk = K >> 5;              // BK=32 steps (>= 64 here)
    load_stage(sb, 0, cAh, cAl, cBh, cBl, bm, bn, 0,  K, tid);
    load_stage(sb, 1, cAh, cAl, cBh, cBl, bm, bn, 32, K, tid);
    load_stage(sb, 2, cAh, cAl, cBh, cBl, bm, bn, 64, K, tid);

    const int lr = lane & 15;
    const int lc = lane >> 4;

    for (int t = 0; t < nk; t++) {
        CP_WAIT2();
        __syncthreads();
        uint32_t st = sb + (t % 3) * STAGEB;

        #pragma unroll
        for (int k0 = 0; k0 < 32; k0 += 16) {
            uint32_t ah[2][4], al[2][4], bh[4][4], bl[4][4];
            uint32_t ao = (uint32_t)((wm * 32 + lr) * ROWB + (k0 + lc * 8) * 2);
            ldsm4(ah[0], st + ao);
            ldsm4(ah[1], st + ao + 16 * ROWB);
            ldsm4(al[0], st + TILEB + ao);
            ldsm4(al[1], st + TILEB + ao + 16 * ROWB);
            uint32_t bo = (uint32_t)((wn * 64 + lr) * ROWB + (k0 + lc * 8) * 2);
            #pragma unroll
            for (int nt = 0; nt < 4; nt++) {
                ldsm4(bh[nt], st + 2 * TILEB + bo + nt * 16 * ROWB);
                ldsm4(bl[nt], st + 3 * TILEB + bo + nt * 16 * ROWB);
            }
            #pragma unroll
            for (int mt = 0; mt < 2; mt++) {
                #pragma unroll
                for (int nt = 0; nt < 4; nt++) {
                    uint32_t b0h[2] = {bh[nt][0], bh[nt][2]};
                    uint32_t b1h[2] = {bh[nt][1], bh[nt][3]};
                    uint32_t b0l[2] = {bl[nt][0], bl[nt][2]};
                    uint32_t b1l[2] = {bl[nt][1], bl[nt][3]};
                    mma_bf16(acc[mt][2 * nt],     ah[mt], b0h);
                    mma_bf16(acc[mt][2 * nt],     al[mt], b0h);
                    mma_bf16(acc[mt][2 * nt],     ah[mt], b0l);
                    mma_bf16(acc[mt][2 * nt + 1], ah[mt], b1h);
                    mma_bf16(acc[mt][2 * nt + 1], al[mt], b1h);
                    mma_bf16(acc[mt][2 * nt + 1], ah[mt], b1l);
                }
            }
        }
        __syncthreads();
        if (t + 3 < nk)
            load_stage(sb, t % 3, cAh, cAl, cBh, cBl, bm, bn, (t + 3) * 32, K, tid);
        else
            CP_COMMIT();
    }

    // epilogue
    const int lg = lane >> 2;           // 0..7
    const int lq = lane & 3;            // 0..3
    #pragma unroll
    for (int mt = 0; mt < 2; mt++) {
        int row = bm + wm * 32 + mt * 16 + lg;
        #pragma unroll
        for (int nf = 0; nf < 8; nf++) {
            float* p = C + (size_t)row * ldc + bn + wn * 64 + nf * 8 + 2 * lq;
            *(float2*)p               = make_float2(acc[mt][nf][0], acc[mt][nf][1]);
            *(float2*)(p + 8 * ldc)   = make_float2(acc[mt][nf][2], acc[mt][nf][3]);
        }
    }
}

// ---------------------------------------------------------------------------
// RoPE in-place on q and k
// ---------------------------------------------------------------------------
__global__ void rope_kernel(float* __restrict__ q, float* __restrict__ k,
                            const int* __restrict__ pos_ids)
{
    const int NQ = BB * QQ * HH  * 32;
    const int NK = BB * QQ * KVH * 32;
    int i = blockIdx.x * blockDim.x + threadIdx.x;
    if (i >= NQ + NK) return;

    float* base;
    int m, d;
    if (i < NQ) {
        d = i & 31;
        int h = (i >> 5) & (HH - 1);
        m = i >> 10;
        base = q + (size_t)m * (HH * HD) + h * HD + d;
    } else {
        int j = i - NQ;
        d = j & 31;
        int h = (j >> 5) & (KVH - 1);
        m = j >> 8;
        base = k + (size_t)m * (KVH * HD) + h * HD + d;
    }

    int pos = pos_ids[m] + LCK;
    double inv = pow(10000.0, -(double)d / 32.0);
    double ang = (double)pos * inv;
    float c = (float)cos(ang);
    float s = (float)sin(ang);

    float a = base[0], b2 = base[32];
    base[0]  = a  * c - b2 * s;
    base[32] = b2 * c + a  * s;
}

// ---------------------------------------------------------------------------
// Attention (unchanged, passing at rel_err 3e-6)
// ---------------------------------------------------------------------------
#define SROW 68
#define ATTN_SMEM_FLOATS (4 * 64 * SROW + 4 * 64 + 2 * 4 * 64)
#define ATTN_SMEM_BYTES  (ATTN_SMEM_FLOATS * 4)

__global__ __launch_bounds__(256)
void attn_kernel(const float* __restrict__ gq, const float* __restrict__ gk,
                 const float* __restrict__ gv,
                 const float* __restrict__ cache_k,
                 const float* __restrict__ cache_v,
                 float* __restrict__ gatt)
{
    extern __shared__ float sm[];
    float* Qs   = sm;
    float* Ks   = Qs + 64 * SROW;
    float* Vs   = Ks + 64 * SROW;
    float* St   = Vs + 64 * SROW;
    float* mrow = St + 64 * SROW;
    float* lrow = mrow + 64;
    float* arow = lrow + 64;
    float* prow = arow + 64;
    float* pmax = prow + 64;
    float* psum = pmax + 4 * 64;

    const int tid = threadIdx.x;
    const int tx = tid & 15;
    const int ty = tid >> 4;
    const int qt = blockIdx.x;
    const int h  = blockIdx.y;
    const int b  = blockIdx.z;
    const int qb = qt * 64;

    const float* qptr = gq + ((size_t)(b * QQ + qb)) * (HH * HD) + h * HD;
    #pragma unroll
    for (int r = 0; r < 4; r++) {
        int idx = tid + 256 * r;
        int row = idx >> 4, c4 = idx & 15;
        float4 v = *(const float4*)(qptr + (size_t)row * (HH * HD) + c4 * 4);
        Qs[(c4 * 4 + 0) * SROW + row] = v.x * SCALE;
        Qs[(c4 * 4 + 1) * SROW + row] = v.y * SCALE;
        Qs[(c4 * 4 + 2) * SROW + row] = v.z * SCALE;
        Qs[(c4 * 4 + 3) * SROW + row] = v.w * SCALE;
    }
    if (tid < 64) { mrow[tid] = NEG_INF; lrow[tid] = 0.f; }
    __syncthreads();

    float acc[4][4];
    #pragma unroll
    for (int i = 0; i < 4; i++)
        #pragma unroll
        for (int j = 0; j < 4; j++) acc[i][j] = 0.f;

    const float* k0 = cache_k + ((size_t)b * HH + h) * QQ * HD;
    const float* v0 = cache_v + ((size_t)b * HH + h) * QQ * HD;

    const int row = tid & 63;
    const int seg = tid >> 6;

    for (int kt = 0; kt <= qt; kt++) {
        const int kb = kt * 64;
        #pragma unroll
        for (int r = 0; r < 4; r++) {
            int idx = tid + 256 * r;
            int krow = idx >> 4, c4 = idx & 15;
            float4 kv = *(const float4*)(k0 + (size_t)(kb + krow) * HD + c4 * 4);
            Ks[(c4 * 4 + 0) * SROW + krow] = kv.x;
            Ks[(c4 * 4 + 1) * SROW + krow] = kv.y;
            Ks[(c4 * 4 + 2) * SROW + krow] = kv.z;
            Ks[(c4 * 4 + 3) * SROW + krow] = kv.w;
            float4 vv = *(const float4*)(v0 + (size_t)(kb + krow) * HD + c4 * 4);
            *(float4*)&Vs[krow * SROW + c4 * 4] = vv;
        }
        __syncthreads();

        float s[4][4];
        #pragma unroll
        for (int i = 0; i < 4; i++)
            #pragma unroll
            for (int j = 0; j < 4; j++) s[i][j] = 0.f;
        #pragma unroll 16
        for (int d = 0; d < 64; d++) {
            float4 aq = *(const float4*)&Qs[d * SROW + ty * 4];
            float4 bk = *(const float4*)&Ks[d * SROW + tx * 4];
            float ar[4] = {aq.x, aq.y, aq.z, aq.w};
            float br[4] = {bk.x, bk.y, bk.z, bk.w};
            #pragma unroll
            for (int i = 0; i < 4; i++)
                #pragma unroll
                for (int j = 0; j < 4; j++)
                    s[i][j] += ar[i] * br[j];
        }
        if (kt == qt) {
            #pragma unroll
            for (int i = 0; i < 4; i++)
                #pragma unroll
                for (int j = 0; j < 4; j++)
                    if (tx * 4 + j > ty * 4 + i) s[i][j] = -1e30f;
        }
        #pragma unroll
        for (int j = 0; j < 4; j++) {
            float4 t = make_float4(s[0][j], s[1][j], s[2][j], s[3][j]);
            *(float4*)&St[(tx * 4 + j) * SROW + ty * 4] = t;
        }
        __syncthreads();

        float pm = NEG_INF;
        #pragma unroll
        for (int kk = 0; kk < 16; kk++)
            pm = fmaxf(pm, St[(seg * 16 + kk) * SROW + row]);
        pmax[seg * 64 + row] = pm;
        __syncthreads();

        if (tid < 64) {
            float mn = fmaxf(fmaxf(pmax[tid], pmax[64 + tid]),
                             fmaxf(pmax[128 + tid], pmax[192 + tid]));
            mn = fmaxf(mn, mrow[tid]);
            arow[tid] = __expf(mrow[tid] - mn);
            mrow[tid] = mn;
        }
        __syncthreads();

        float mr = mrow[row];
        float ps = 0.f;
        #pragma unroll
        for (int kk = 0; kk < 16; kk++) {
            int kidx = (seg * 16 + kk) * SROW + row;
            float p = __expf(St[kidx] - mr);
            St[kidx] = p;
            ps += p;
        }
        psum[seg * 64 + row] = ps;
        __syncthreads();

        if (tid < 64)
            lrow[tid] = lrow[tid] * arow[tid] +
                        psum[tid] + psum[64 + tid] + psum[128 + tid] + psum[192 + tid];

        #pragma unroll
        for (int i = 0; i < 4; i++) {
            float a = arow[ty * 4 + i];
            #pragma unroll
            for (int j = 0; j < 4; j++) acc[i][j] *= a;
        }
        #pragma unroll 16
        for (int kk = 0; kk < 64; kk++) {
            float4 ap = *(const float4*)&St[kk * SROW + ty * 4];
            float4 bv = *(const float4*)&Vs[kk * SROW + tx * 4];
            float ar[4] = {ap.x, ap.y, ap.z, ap.w};
            float br[4] = {bv.x, bv.y, bv.z, bv.w};
            #pragma unroll
            for (int i = 0; i < 4; i++)
                #pragma unroll
                for (int j = 0; j < 4; j++)
                    acc[i][j] += ar[i] * br[j];
        }
        __syncthreads();
    }

    #pragma unroll 1
    for (int e = 0; e < 2; e++) {
        const float* tk;
        const float* tv;
        size_t stride;
        if (e == 0) {
            size_t off = (((size_t)BB + b) * HH + h) * QQ * HD + (size_t)qb * HD;
            tk = cache_k + off;
            tv = cache_v + off;
            stride = HD;
        } else {
            size_t off = (size_t)(b * QQ + qb) * (KVH * HD) + (size_t)(h >> 2) * HD;
            tk = gk + off;
            tv = gv + off;
            stride = KVH * HD;
        }
        #pragma unroll
        for (int r = 0; r < 4; r++) {
            int idx = tid + 256 * r;
            int krow = idx >> 4, c4 = idx & 15;
            *(float4*)&Ks[krow * SROW + c4 * 4] = *(const float4*)(tk + (size_t)krow * stride + c4 * 4);
            *(float4*)&Vs[krow * SROW + c4 * 4] = *(const float4*)(tv + (size_t)krow * stride + c4 * 4);
        }
        __syncthreads();

        if (tid < 64) {
            float sdot = 0.f;
            #pragma unroll 16
            for (int d = 0; d < 64; d++)
                sdot += Qs[d * SROW + tid] * Ks[tid * SROW + d];
            float mo = mrow[tid];
            float mn = fmaxf(mo, sdot);
            float a = __expf(mo - mn);
            float p = __expf(sdot - mn);
            mrow[tid] = mn;
            lrow[tid] = lrow[tid] * a + p;
            arow[tid] = a;
            prow[tid] = p;
        }
        __syncthreads();

        #pragma unroll
        for (int i = 0; i < 4; i++) {
            float a = arow[ty * 4 + i];
            float p = prow[ty * 4 + i];
            float4 vv = *(const float4*)&Vs[(ty * 4 + i) * SROW + tx * 4];
            acc[i][0] = acc[i][0] * a + p * vv.x;
            acc[i][1] = acc[i][1] * a + p * vv.y;
            acc[i][2] = acc[i][2] * a + p * vv.z;
            acc[i][3] = acc[i][3] * a + p * vv.w;
        }
        __syncthreads();
    }

    float* outp = gatt + ((size_t)(b * QQ + qb)) * (HH * HD) + h * HD;
    #pragma unroll
    for (int i = 0; i < 4; i++) {
        float invl = 1.0f / lrow[ty * 4 + i];
        float4 o = make_float4(acc[i][0] * invl, acc[i][1] * invl,
                               acc[i][2] * invl, acc[i][3] * invl);
        *(float4*)(outp + (size_t)(ty * 4 + i) * (HH * HD) + tx * 4) = o;
    }
}

// ---------------------------------------------------------------------------
// Launch
// ---------------------------------------------------------------------------
extern "C" void kernel_launch(void* const* d_in, const int* in_sizes, int n_in,
                              void* d_out, int out_size)
{
    (void)in_sizes; (void)n_in; (void)out_size;

    const float* hidden = (const float*)d_in[0];
    const float* Wq     = (const float*)d_in[1];
    const float* Wk     = (const float*)d_in[2];
    const float* Wv     = (const float*)d_in[3];
    const float* Wo     = (const float*)d_in[4];
    const float* ck     = (const float*)d_in[5];
    const float* cv     = (const float*)d_in[6];
    const int*   pos    = (const int*)d_in[8];
    float* out = (float*)d_out;

    float *gq, *gk, *gv, *gatt;
    cudaGetSymbolAddress((void**)&gq,   g_q);
    cudaGetSymbolAddress((void**)&gk,   g_k);
    cudaGetSymbolAddress((void**)&gv,   g_v);
    cudaGetSymbolAddress((void**)&gatt, g_att);

    __nv_bfloat16 *hid_h, *hid_l, *wq_h, *wq_l, *wk_h, *wk_l, *wv_h, *wv_l;
    __nv_bfloat16 *wo_h, *wo_l, *at_h, *at_l;
    cudaGetSymbolAddress((void**)&hid_h, c_hid_h);
    cudaGetSymbolAddress((void**)&hid_l, c_hid_l);
    cudaGetSymbolAddress((void**)&wq_h,  c_wq_h);
    cudaGetSymbolAddress((void**)&wq_l,  c_wq_l);
    cudaGetSymbolAddress((void**)&wk_h,  c_wk_h);
    cudaGetSymbolAddress((void**)&wk_l,  c_wk_l);
    cudaGetSymbolAddress((void**)&wv_h,  c_wv_h);
    cudaGetSymbolAddress((void**)&wv_l,  c_wv_l);
    cudaGetSymbolAddress((void**)&wo_h,  c_wo_h);
    cudaGetSymbolAddress((void**)&wo_l,  c_wo_l);
    cudaGetSymbolAddress((void**)&at_h,  c_at_h);
    cudaGetSymbolAddress((void**)&at_l,  c_at_l);

    cudaFuncSetAttribute(attn_kernel,
                         cudaFuncAttributeMaxDynamicSharedMemorySize, ATTN_SMEM_BYTES);
    cudaFuncSetAttribute(gemm_tc,
                         cudaFuncAttributeMaxDynamicSharedMemorySize, GSMEM_BYTES);

    const int M = BB * QQ;   // 2048

    // fp32 -> bf16 hi/lo splits
    {
        int n;
        n = 2048 * 4096; convert_hl<<<(n / 4 + 255) / 256, 256>>>(hidden, hid_h, hid_l, n / 4);
        n = 2048 * 4096; convert_hl<<<(n / 4 + 255) / 256, 256>>>(Wq, wq_h, wq_l, n / 4);
        n = 512  * 4096; convert_hl<<<(n / 4 + 255) / 256, 256>>>(Wk, wk_h, wk_l, n / 4);
        n = 512  * 4096; convert_hl<<<(n / 4 + 255) / 256, 256>>>(Wv, wv_h, wv_l, n / 4);
        n = 2048 * 2048; convert_hl<<<(n / 4 + 255) / 256, 256>>>(Wo, wo_h, wo_l, n / 4);
    }

    // fused QKV projection: 24 N-tiles (16 q + 4 k + 4 v) x 16 M-tiles
    gemm_tc<<<dim3(24, M / 128), 256, GSMEM_BYTES>>>(
        hid_h, hid_l,
        wq_h, wq_l, gq, HH * HD,
        wk_h, wk_l, gk, KVH * HD,
        wv_h, wv_l, gv, KVH * HD,
        K2HS);

    // RoPE
    {
        int total = BB * QQ * (HH + KVH) * 32;
        rope_kernel<<<(total + 255) / 256, 256>>>(gq, gk, pos);
    }

    // Attention
    attn_kernel<<<dim3(QQ / 64, HH, BB), 256, ATTN_SMEM_BYTES>>>(gq, gk, gv, ck, cv, gatt);

    // attention output -> bf16 hi/lo, then output projection
    {
        int n = 2048 * 2048;
        convert_hl<<<(n / 4 + 255) / 256, 256>>>(gatt, at_h, at_l, n / 4);
    }
    gemm_tc<<<dim3(16, M / 128), 256, GSMEM_BYTES>>>(
        at_h, at_l,
        wo_h, wo_l, out, HS,
        (const __nv_bfloat16*)0, (const __nv_bfloat16*)0, (float*)0, 0,
        (const __nv_bfloat16*)0, (const __nv_bfloat16*)0, (float*)0, 0,
        HH * HD);
}

// round 4
// speedup vs baseline: 2.6552x; 1.2189x over previous
#include <cuda_runtime.h>
#include <cuda_bf16.h>
#include <math.h>
#include <stdint.h>

// ---------------------------------------------------------------------------
// Problem constants
// ---------------------------------------------------------------------------
#define BB    2
#define QQ    1024
#define HH    32
#define KVH   8
#define HD    64
#define HS    2048
#define K2HS  4096
#define LCK   2
#define SCALE 0.125f

#define NEG_INF (__int_as_float(0xff800000))

// ---------------------------------------------------------------------------
// Scratch (no cudaMalloc allowed)
// ---------------------------------------------------------------------------
__device__ float g_q  [BB * QQ * HH  * HD];
__device__ float g_k  [BB * QQ * KVH * HD];
__device__ float g_v  [BB * QQ * KVH * HD];

// bf16 split-precision operands
__device__ __nv_bfloat16 c_hid_h[2048 * 4096];
__device__ __nv_bfloat16 c_hid_l[2048 * 4096];
__device__ __nv_bfloat16 c_wq_h [2048 * 4096];
__device__ __nv_bfloat16 c_wq_l [2048 * 4096];
__device__ __nv_bfloat16 c_wk_h [512  * 4096];
__device__ __nv_bfloat16 c_wk_l [512  * 4096];
__device__ __nv_bfloat16 c_wv_h [512  * 4096];
__device__ __nv_bfloat16 c_wv_l [512  * 4096];
__device__ __nv_bfloat16 c_wo_h [2048 * 2048];
__device__ __nv_bfloat16 c_wo_l [2048 * 2048];
__device__ __nv_bfloat16 c_at_h [2048 * 2048];
__device__ __nv_bfloat16 c_at_l [2048 * 2048];
// attention operands (bf16 splits)
__device__ __nv_bfloat16 c_qh [2048 * 2048];
__device__ __nv_bfloat16 c_ql [2048 * 2048];
__device__ __nv_bfloat16 c_k0h[BB * HH * QQ * HD];
__device__ __nv_bfloat16 c_k0l[BB * HH * QQ * HD];
__device__ __nv_bfloat16 c_v0h[BB * HH * QQ * HD];
__device__ __nv_bfloat16 c_v0l[BB * HH * QQ * HD];

// ---------------------------------------------------------------------------
// PTX helpers — plain-sm_100 legal only
// ---------------------------------------------------------------------------
__device__ __forceinline__ uint32_t smem_u32(const void* p) {
    uint32_t a;
    asm("{ .reg .u64 t; cvta.to.shared.u64 t, %1; cvt.u32.u64 %0, t; }"
        : "=r"(a) : "l"(p));
    return a;
}

#define CP_ASYNC16(dst, src) \
    asm volatile("cp.async.cg.shared.global [%0], [%1], 16;" \
                 :: "r"((uint32_t)(dst)), "l"(src))
#define CP_COMMIT() asm volatile("cp.async.commit_group;" ::: "memory")
#define CP_WAIT0()  asm volatile("cp.async.wait_group 0;" ::: "memory")
#define CP_WAIT1()  asm volatile("cp.async.wait_group 1;" ::: "memory")
#define CP_WAIT2()  asm volatile("cp.async.wait_group 2;" ::: "memory")

__device__ __forceinline__ void ldsm4(uint32_t* r, uint32_t addr) {
    asm volatile("ldmatrix.sync.aligned.m8n8.x4.shared.b16 {%0,%1,%2,%3}, [%4];"
        : "=r"(r[0]), "=r"(r[1]), "=r"(r[2]), "=r"(r[3]) : "r"(addr));
}
__device__ __forceinline__ void ldsm4t(uint32_t* r, uint32_t addr) {
    asm volatile("ldmatrix.sync.aligned.m8n8.x4.trans.shared.b16 {%0,%1,%2,%3}, [%4];"
        : "=r"(r[0]), "=r"(r[1]), "=r"(r[2]), "=r"(r[3]) : "r"(addr));
}

__device__ __forceinline__ void mma_bf16(float* d, const uint32_t* a, const uint32_t* b) {
    asm volatile(
        "mma.sync.aligned.m16n8k16.row.col.f32.bf16.bf16.f32 "
        "{%0,%1,%2,%3}, {%4,%5,%6,%7}, {%8,%9}, {%0,%1,%2,%3};"
        : "+f"(d[0]), "+f"(d[1]), "+f"(d[2]), "+f"(d[3])
        : "r"(a[0]), "r"(a[1]), "r"(a[2]), "r"(a[3]), "r"(b[0]), "r"(b[1]));
}

__device__ __forceinline__ uint32_t packbf(float hi, float lo) {
    uint32_t r;
    asm("cvt.rn.bf16x2.f32 %0, %1, %2;" : "=r"(r) : "f"(hi), "f"(lo));
    return r;
}

// ---------------------------------------------------------------------------
// fp32 -> (bf16 hi, bf16 lo) split conversion, with scale
// ---------------------------------------------------------------------------
__global__ void convert_hl(const float* __restrict__ x, __nv_bfloat16* __restrict__ h,
                           __nv_bfloat16* __restrict__ l, int n4, float scale)
{
    int i = blockIdx.x * blockDim.x + threadIdx.x;
    if (i >= n4) return;
    float4 v = ((const float4*)x)[i];
    v.x *= scale; v.y *= scale; v.z *= scale; v.w *= scale;
    __nv_bfloat16 h0 = __float2bfloat16(v.x);
    __nv_bfloat16 h1 = __float2bfloat16(v.y);
    __nv_bfloat16 h2 = __float2bfloat16(v.z);
    __nv_bfloat16 h3 = __float2bfloat16(v.w);
    __nv_bfloat16 l0 = __float2bfloat16(v.x - __bfloat162float(h0));
    __nv_bfloat16 l1 = __float2bfloat16(v.y - __bfloat162float(h1));
    __nv_bfloat16 l2 = __float2bfloat16(v.z - __bfloat162float(h2));
    __nv_bfloat16 l3 = __float2bfloat16(v.w - __bfloat162float(h3));
    __nv_bfloat162* hp = (__nv_bfloat162*)h + i * 2;
    __nv_bfloat162* lp = (__nv_bfloat162*)l + i * 2;
    hp[0] = __halves2bfloat162(h0, h1);
    hp[1] = __halves2bfloat162(h2, h3);
    lp[0] = __halves2bfloat162(l0, l1);
    lp[1] = __halves2bfloat162(l2, l3);
}

// ---------------------------------------------------------------------------
// split-bf16 NT GEMM via mma.sync (validated round 3)
// ---------------------------------------------------------------------------
#define ROWB   80
#define TILEB  (128 * ROWB)
#define STAGEB (4 * TILEB)
#define GSMEM_BYTES (3 * STAGEB)

__device__ __forceinline__ void load_stage(
    uint32_t sb, int buf, const char* Ah, const char* Al,
    const char* Bh, const char* Bl, int bm, int bn, int kb, int K, int tid)
{
    uint32_t st = sb + buf * STAGEB;
    #pragma unroll
    for (int t4 = 0; t4 < 4; t4++) {
        const char* base = (t4 == 0) ? Ah : (t4 == 1) ? Al : (t4 == 2) ? Bh : Bl;
        int rb = (t4 < 2) ? bm : bn;
        #pragma unroll
        for (int j = 0; j < 2; j++) {
            int c   = tid + 256 * j;
            int row = c >> 2;
            int ch  = c & 3;
            uint32_t sa = st + t4 * TILEB + row * ROWB + ch * 16;
            const char* ga = base + ((size_t)(rb + row) * K + kb + ch * 8) * 2;
            CP_ASYNC16(sa, ga);
        }
    }
    CP_COMMIT();
}

__global__ __launch_bounds__(256, 1)
void gemm_tc(const __nv_bfloat16* __restrict__ Ah_, const __nv_bfloat16* __restrict__ Al_,
             const __nv_bfloat16* B0h, const __nv_bfloat16* B0l, float* C0, int N0,
             const __nv_bfloat16* B1h, const __nv_bfloat16* B1l, float* C1, int N1,
             const __nv_bfloat16* B2h, const __nv_bfloat16* B2l, float* C2, int N2,
             int K)
{
    extern __shared__ __align__(16) char smx[];
    uint32_t sb = smem_u32(smx);
    const int tid  = threadIdx.x;
    const int wid  = tid >> 5;
    const int lane = tid & 31;
    const int wm   = wid >> 1;
    const int wn   = wid & 1;
    const int bm   = blockIdx.y * 128;

    int xt = blockIdx.x;
    const __nv_bfloat16 *Bh, *Bl; float* C; int ldc, bn;
    int t0 = N0 >> 7, t1 = N1 >> 7;
    if (xt < t0)           { Bh = B0h; Bl = B0l; C = C0; ldc = N0; bn = xt << 7; }
    else if (xt < t0 + t1) { Bh = B1h; Bl = B1l; C = C1; ldc = N1; bn = (xt - t0) << 7; }
    else                   { Bh = B2h; Bl = B2l; C = C2; ldc = N2; bn = (xt - t0 - t1) << 7; }

    const char* cAh = (const char*)Ah_;
    const char* cAl = (const char*)Al_;
    const char* cBh = (const char*)Bh;
    const char* cBl = (const char*)Bl;

    float acc[2][8][4];
    #pragma unroll
    for (int i = 0; i < 2; i++)
        #pragma unroll
        for (int j = 0; j < 8; j++)
            #pragma unroll
            for (int q = 0; q < 4; q++) acc[i][j][q] = 0.f;

    const int nk = K >> 5;
    load_stage(sb, 0, cAh, cAl, cBh, cBl, bm, bn, 0,  K, tid);
    load_stage(sb, 1, cAh, cAl, cBh, cBl, bm, bn, 32, K, tid);
    load_stage(sb, 2, cAh, cAl, cBh, cBl, bm, bn, 64, K, tid);

    const int lr = lane & 15;
    const int lc = lane >> 4;

    for (int t = 0; t < nk; t++) {
        CP_WAIT2();
        __syncthreads();
        uint32_t st = sb + (t % 3) * STAGEB;

        #pragma unroll
        for (int k0 = 0; k0 < 32; k0 += 16) {
            uint32_t ah[2][4], al[2][4], bh[4][4], bl[4][4];
            uint32_t ao = (uint32_t)((wm * 32 + lr) * ROWB + (k0 + lc * 8) * 2);
            ldsm4(ah[0], st + ao);
            ldsm4(ah[1], st + ao + 16 * ROWB);
            ldsm4(al[0], st + TILEB + ao);
            ldsm4(al[1], st + TILEB + ao + 16 * ROWB);
            uint32_t bo = (uint32_t)((wn * 64 + lr) * ROWB + (k0 + lc * 8) * 2);
            #pragma unroll
            for (int nt = 0; nt < 4; nt++) {
                ldsm4(bh[nt], st + 2 * TILEB + bo + nt * 16 * ROWB);
                ldsm4(bl[nt], st + 3 * TILEB + bo + nt * 16 * ROWB);
            }
            #pragma unroll
            for (int mt = 0; mt < 2; mt++) {
                #pragma unroll
                for (int nt = 0; nt < 4; nt++) {
                    uint32_t b0h[2] = {bh[nt][0], bh[nt][2]};
                    uint32_t b1h[2] = {bh[nt][1], bh[nt][3]};
                    uint32_t b0l[2] = {bl[nt][0], bl[nt][2]};
                    uint32_t b1l[2] = {bl[nt][1], bl[nt][3]};
                    mma_bf16(acc[mt][2 * nt],     ah[mt], b0h);
                    mma_bf16(acc[mt][2 * nt],     al[mt], b0h);
                    mma_bf16(acc[mt][2 * nt],     ah[mt], b0l);
                    mma_bf16(acc[mt][2 * nt + 1], ah[mt], b1h);
                    mma_bf16(acc[mt][2 * nt + 1], al[mt], b1h);
                    mma_bf16(acc[mt][2 * nt + 1], ah[mt], b1l);
                }
            }
        }
        __syncthreads();
        if (t + 3 < nk)
            load_stage(sb, t % 3, cAh, cAl, cBh, cBl, bm, bn, (t + 3) * 32, K, tid);
        else
            CP_COMMIT();
    }

    const int lg = lane >> 2;
    const int lq = lane & 3;
    #pragma unroll
    for (int mt = 0; mt < 2; mt++) {
        int row = bm + wm * 32 + mt * 16 + lg;
        #pragma unroll
        for (int nf = 0; nf < 8; nf++) {
            float* p = C + (size_t)row * ldc + bn + wn * 64 + nf * 8 + 2 * lq;
            *(float2*)p               = make_float2(acc[mt][nf][0], acc[mt][nf][1]);
            *(float2*)(p + 8 * ldc)   = make_float2(acc[mt][nf][2], acc[mt][nf][3]);
        }
    }
}

// ---------------------------------------------------------------------------
// RoPE in-place on q and k
// ---------------------------------------------------------------------------
__global__ void rope_kernel(float* __restrict__ q, float* __restrict__ k,
                            const int* __restrict__ pos_ids)
{
    const int NQ = BB * QQ * HH  * 32;
    const int NK = BB * QQ * KVH * 32;
    int i = blockIdx.x * blockDim.x + threadIdx.x;
    if (i >= NQ + NK) return;

    float* base;
    int m, d;
    if (i < NQ) {
        d = i & 31;
        int h = (i >> 5) & (HH - 1);
        m = i >> 10;
        base = q + (size_t)m * (HH * HD) + h * HD + d;
    } else {
        int j = i - NQ;
        d = j & 31;
        int h = (j >> 5) & (KVH - 1);
        m = j >> 8;
        base = k + (size_t)m * (KVH * HD) + h * HD + d;
    }

    int pos = pos_ids[m] + LCK;
    double inv = pow(10000.0, -(double)d / 32.0);
    double ang = (double)pos * inv;
    float c = (float)cos(ang);
    float s = (float)sin(ang);

    float a = base[0], b2 = base[32];
    base[0]  = a  * c - b2 * s;
    base[32] = b2 * c + a  * s;
}

// ---------------------------------------------------------------------------
// Tensor-core flash attention (split-bf16 mma.sync).
// Block: (qtile 128, h, b), 256 threads (8 warps, 16 q-rows each).
// K/V double-buffered cp.async stages; online softmax on fragments.
// Writes output directly as bf16 hi/lo for the Wo GEMM.
// ---------------------------------------------------------------------------
#define BQ    128
#define BKEY  128
#define QROWB 144
#define SM_QH 0
#define SM_QL 18432
#define SM_ST 36864
#define STG_SZ 73728
#define OFF_KH 0
#define OFF_KL 18432
#define OFF_VH 36864
#define OFF_VL 55296
#define ATTN_SMEM2 (SM_ST + 2 * STG_SZ)   // 184320

__device__ __forceinline__ void attn_ldkv(uint32_t sb, int stg,
    const char* kh, const char* kl, const char* vh, const char* vl,
    size_t base2, int tid)
{
    uint32_t st = sb + SM_ST + stg * STG_SZ;
    #pragma unroll
    for (int j = 0; j < 4; j++) {
        int c = tid + 256 * j;
        int row = c >> 3, ch = c & 7;
        size_t off = base2 + (size_t)row * 128 + ch * 16;
        uint32_t d = row * QROWB + ch * 16;
        CP_ASYNC16(st + OFF_KH + d, kh + off);
        CP_ASYNC16(st + OFF_KL + d, kl + off);
        CP_ASYNC16(st + OFF_VH + d, vh + off);
        CP_ASYNC16(st + OFF_VL + d, vl + off);
    }
    CP_COMMIT();
}

__global__ __launch_bounds__(256, 1)
void attn_mma(const __nv_bfloat16* __restrict__ qh_g, const __nv_bfloat16* __restrict__ ql_g,
              const __nv_bfloat16* __restrict__ k0h, const __nv_bfloat16* __restrict__ k0l,
              const __nv_bfloat16* __restrict__ v0h, const __nv_bfloat16* __restrict__ v0l,
              const float* __restrict__ cache_k, const float* __restrict__ cache_v,
              const float* __restrict__ gk, const float* __restrict__ gv,
              __nv_bfloat16* __restrict__ outh, __nv_bfloat16* __restrict__ outl)
{
    extern __shared__ __align__(16) char smp[];
    uint32_t sb = smem_u32(smp);
    const int tid = threadIdx.x, wid = tid >> 5, lane = tid & 31;
    const int lg = lane >> 2, lq = lane & 3;
    const int qt = blockIdx.x, h = blockIdx.y, b = blockIdx.z;
    const int qb = qt * BQ;

    // Q tile loads (group 0)
    {
        const char* ch_ = (const char*)qh_g;
        const char* cl_ = (const char*)ql_g;
        #pragma unroll
        for (int j = 0; j < 4; j++) {
            int c = tid + 256 * j;
            int row = c >> 3, ch = c & 7;
            size_t off = (((size_t)(b * QQ + qb + row)) * 2048 + h * 64 + ch * 8) * 2;
            uint32_t d = row * QROWB + ch * 16;
            CP_ASYNC16(sb + SM_QH + d, ch_ + off);
            CP_ASYNC16(sb + SM_QL + d, cl_ + off);
        }
        CP_COMMIT();
    }

    const char* ck0h = (const char*)k0h;
    const char* ck0l = (const char*)k0l;
    const char* cv0h = (const char*)v0h;
    const char* cv0l = (const char*)v0l;
    size_t kvb2 = ((size_t)(b * HH + h)) * QQ * 64 * 2;
    attn_ldkv(sb, 0, ck0h, ck0l, cv0h, cv0l, kvb2, tid);
    if (qt >= 1)
        attn_ldkv(sb, 1, ck0h, ck0l, cv0h, cv0l, kvb2 + (size_t)BKEY * 128, tid);

    float s[16][4], o[8][4];
    #pragma unroll
    for (int nf = 0; nf < 8; nf++)
        #pragma unroll
        for (int c = 0; c < 4; c++) o[nf][c] = 0.f;
    float mr0 = NEG_INF, mr1 = NEG_INF, lr0 = 0.f, lr1 = 0.f;
    uint32_t qah[4][4], qal[4][4];

    for (int kt = 0; kt <= qt; kt++) {
        if (kt < qt) { CP_WAIT1(); } else { CP_WAIT0(); }
        __syncthreads();
        uint32_t st = sb + SM_ST + (kt & 1) * STG_SZ;

        if (kt == 0) {
            #pragma unroll
            for (int kc = 0; kc < 4; kc++) {
                uint32_t ao = (wid * 16 + (lane & 15)) * QROWB + (kc * 16 + (lane >> 4) * 8) * 2;
                ldsm4(qah[kc], sb + SM_QH + ao);
                ldsm4(qal[kc], sb + SM_QL + ao);
            }
        }

        // ---- S = Qs @ K^T (split bf16) ----
        #pragma unroll
        for (int nf = 0; nf < 16; nf++)
            #pragma unroll
            for (int c = 0; c < 4; c++) s[nf][c] = 0.f;
        #pragma unroll
        for (int kc = 0; kc < 4; kc++) {
            #pragma unroll
            for (int kg = 0; kg < 8; kg++) {
                uint32_t bo = (kg * 16 + (lane & 15)) * QROWB + (kc * 16 + (lane >> 4) * 8) * 2;
                uint32_t bh_[4], bl_[4];
                ldsm4(bh_, st + OFF_KH + bo);
                ldsm4(bl_, st + OFF_KL + bo);
                uint32_t b0h[2] = {bh_[0], bh_[2]}, b1h[2] = {bh_[1], bh_[3]};
                uint32_t b0l[2] = {bl_[0], bl_[2]}, b1l[2] = {bl_[1], bl_[3]};
                mma_bf16(s[2 * kg],     qah[kc], b0h);
                mma_bf16(s[2 * kg],     qal[kc], b0h);
                mma_bf16(s[2 * kg],     qah[kc], b0l);
                mma_bf16(s[2 * kg + 1], qah[kc], b1h);
                mma_bf16(s[2 * kg + 1], qal[kc], b1h);
                mma_bf16(s[2 * kg + 1], qah[kc], b1l);
            }
        }

        // ---- causal mask on diagonal tile ----
        if (kt == qt) {
            int r0 = wid * 16 + lg;
            #pragma unroll
            for (int nf = 0; nf < 16; nf++) {
                int k0c = nf * 8 + 2 * lq;
                if (k0c     > r0)     s[nf][0] = -1e30f;
                if (k0c + 1 > r0)     s[nf][1] = -1e30f;
                if (k0c     > r0 + 8) s[nf][2] = -1e30f;
                if (k0c + 1 > r0 + 8) s[nf][3] = -1e30f;
            }
        }

        // ---- online softmax ----
        float mx0 = NEG_INF, mx1 = NEG_INF;
        #pragma unroll
        for (int nf = 0; nf < 16; nf++) {
            mx0 = fmaxf(mx0, fmaxf(s[nf][0], s[nf][1]));
            mx1 = fmaxf(mx1, fmaxf(s[nf][2], s[nf][3]));
        }
        mx0 = fmaxf(mx0, __shfl_xor_sync(0xffffffffu, mx0, 1));
        mx0 = fmaxf(mx0, __shfl_xor_sync(0xffffffffu, mx0, 2));
        mx1 = fmaxf(mx1, __shfl_xor_sync(0xffffffffu, mx1, 1));
        mx1 = fmaxf(mx1, __shfl_xor_sync(0xffffffffu, mx1, 2));
        float mn0 = fmaxf(mr0, mx0), mn1 = fmaxf(mr1, mx1);
        float al0 = __expf(mr0 - mn0), al1 = __expf(mr1 - mn1);
        mr0 = mn0; mr1 = mn1;
        float sum0 = 0.f, sum1 = 0.f;
        #pragma unroll
        for (int nf = 0; nf < 16; nf++) {
            s[nf][0] = __expf(s[nf][0] - mn0); sum0 += s[nf][0];
            s[nf][1] = __expf(s[nf][1] - mn0); sum0 += s[nf][1];
            s[nf][2] = __expf(s[nf][2] - mn1); sum1 += s[nf][2];
            s[nf][3] = __expf(s[nf][3] - mn1); sum1 += s[nf][3];
        }
        sum0 += __shfl_xor_sync(0xffffffffu, sum0, 1);
        sum0 += __shfl_xor_sync(0xffffffffu, sum0, 2);
        sum1 += __shfl_xor_sync(0xffffffffu, sum1, 1);
        sum1 += __shfl_xor_sync(0xffffffffu, sum1, 2);
        lr0 = lr0 * al0 + sum0;
        lr1 = lr1 * al1 + sum1;
        #pragma unroll
        for (int nf = 0; nf < 8; nf++) {
            o[nf][0] *= al0; o[nf][1] *= al0; o[nf][2] *= al1; o[nf][3] *= al1;
        }

        // ---- O += P @ V (split bf16) ----
        #pragma unroll
        for (int kc2 = 0; kc2 < 8; kc2++) {
            uint32_t pah[4], pal[4];
            #pragma unroll
            for (int t2 = 0; t2 < 2; t2++) {
                float* sv = s[2 * kc2 + t2];
                __nv_bfloat16 h0 = __float2bfloat16(sv[0]);
                __nv_bfloat16 h1 = __float2bfloat16(sv[1]);
                __nv_bfloat16 h2 = __float2bfloat16(sv[2]);
                __nv_bfloat16 h3 = __float2bfloat16(sv[3]);
                pah[2 * t2]     = ((uint32_t)__bfloat16_as_ushort(h1) << 16) | __bfloat16_as_ushort(h0);
                pah[2 * t2 + 1] = ((uint32_t)__bfloat16_as_ushort(h3) << 16) | __bfloat16_as_ushort(h2);
                pal[2 * t2]     = packbf(sv[1] - __bfloat162float(h1), sv[0] - __bfloat162float(h0));
                pal[2 * t2 + 1] = packbf(sv[3] - __bfloat162float(h3), sv[2] - __bfloat162float(h2));
            }
            #pragma unroll
            for (int dg = 0; dg < 4; dg++) {
                uint32_t vo = (kc2 * 16 + (lane & 15)) * QROWB + dg * 32 + (lane >> 4) * 16;
                uint32_t vh_[4], vl_[4];
                ldsm4t(vh_, st + OFF_VH + vo);
                ldsm4t(vl_, st + OFF_VL + vo);
                uint32_t b0h[2] = {vh_[0], vh_[1]}, b1h[2] = {vh_[2], vh_[3]};
                uint32_t b0l[2] = {vl_[0], vl_[1]}, b1l[2] = {vl_[2], vl_[3]};
                mma_bf16(o[2 * dg],     pah, b0h);
                mma_bf16(o[2 * dg],     pal, b0h);
                mma_bf16(o[2 * dg],     pah, b0l);
                mma_bf16(o[2 * dg + 1], pah, b1h);
                mma_bf16(o[2 * dg + 1], pal, b1h);
                mma_bf16(o[2 * dg + 1], pah, b1l);
            }
        }
        __syncthreads();
        if (kt + 2 <= qt)
            attn_ldkv(sb, kt & 1, ck0h, ck0l, cv0h, cv0l,
                      kvb2 + (size_t)(kt + 2) * BKEY * 128, tid);
    }

    // ---- two diagonal tail keys per row ----
    #pragma unroll 1
    for (int e = 0; e < 2; e++) {
        const float* tk; const float* tv; int stride;
        if (e == 0) {
            size_t off = (((size_t)BB + b) * HH + h) * QQ * HD + (size_t)qb * HD;
            tk = cache_k + off; tv = cache_v + off; stride = 64;
        } else {
            size_t off = ((size_t)(b * QQ + qb)) * 512 + (h >> 2) * 64;
            tk = gk + off; tv = gv + off; stride = 512;
        }
        #pragma unroll
        for (int half = 0; half < 2; half++) {
            int rl = wid * 16 + lg + half * 8;
            const __nv_bfloat16* qhp = (const __nv_bfloat16*)(smp + SM_QH + rl * QROWB);
            const __nv_bfloat16* qlp = (const __nv_bfloat16*)(smp + SM_QL + rl * QROWB);
            float dot = 0.f;
            #pragma unroll
            for (int dd = 0; dd < 16; dd++) {
                int d = lq * 16 + dd;
                float qv = __bfloat162float(qhp[d]) + __bfloat162float(qlp[d]);
                dot += qv * tk[(size_t)rl * stride + d];
            }
            dot += __shfl_xor_sync(0xffffffffu, dot, 1);
            dot += __shfl_xor_sync(0xffffffffu, dot, 2);
            float mo = half ? mr1 : mr0;
            float mn = fmaxf(mo, dot);
            float a = __expf(mo - mn), p = __expf(dot - mn);
            if (half) { mr1 = mn; lr1 = lr1 * a + p; }
            else      { mr0 = mn; lr0 = lr0 * a + p; }
            #pragma unroll
            for (int nf = 0; nf < 8; nf++) {
                int d0 = nf * 8 + 2 * lq;
                float v0 = tv[(size_t)rl * stride + d0];
                float v1 = tv[(size_t)rl * stride + d0 + 1];
                o[nf][2 * half]     = o[nf][2 * half]     * a + p * v0;
                o[nf][2 * half + 1] = o[nf][2 * half + 1] * a + p * v1;
            }
        }
    }

    // ---- normalize, split to bf16 hi/lo, write ----
    float inv0 = 1.f / lr0, inv1 = 1.f / lr1;
    #pragma unroll
    for (int half = 0; half < 2; half++) {
        int qrow = qb + wid * 16 + lg + half * 8;
        float inv = half ? inv1 : inv0;
        size_t base = ((size_t)(b * QQ) + qrow) * 2048 + h * 64;
        #pragma unroll
        for (int nf = 0; nf < 8; nf++) {
            float x0 = o[nf][2 * half] * inv;
            float x1 = o[nf][2 * half + 1] * inv;
            __nv_bfloat16 h0 = __float2bfloat16(x0), h1 = __float2bfloat16(x1);
            __nv_bfloat162 hp; hp.x = h0; hp.y = h1;
            *(__nv_bfloat162*)(outh + base + nf * 8 + 2 * lq) = hp;
            __nv_bfloat162 lp;
            lp.x = __float2bfloat16(x0 - __bfloat162float(h0));
            lp.y = __float2bfloat16(x1 - __bfloat162float(h1));
            *(__nv_bfloat162*)(outl + base + nf * 8 + 2 * lq) = lp;
        }
    }
}

// ---------------------------------------------------------------------------
// Launch
// ---------------------------------------------------------------------------
extern "C" void kernel_launch(void* const* d_in, const int* in_sizes, int n_in,
                              void* d_out, int out_size)
{
    (void)in_sizes; (void)n_in; (void)out_size;

    const float* hidden = (const float*)d_in[0];
    const float* Wq     = (const float*)d_in[1];
    const float* Wk     = (const float*)d_in[2];
    const float* Wv     = (const float*)d_in[3];
    const float* Wo     = (const float*)d_in[4];
    const float* ck     = (const float*)d_in[5];
    const float* cv     = (const float*)d_in[6];
    const int*   pos    = (const int*)d_in[8];
    float* out = (float*)d_out;

    float *gq, *gk, *gv;
    cudaGetSymbolAddress((void**)&gq, g_q);
    cudaGetSymbolAddress((void**)&gk, g_k);
    cudaGetSymbolAddress((void**)&gv, g_v);

    __nv_bfloat16 *hid_h, *hid_l, *wq_h, *wq_l, *wk_h, *wk_l, *wv_h, *wv_l;
    __nv_bfloat16 *wo_h, *wo_l, *at_h, *at_l, *qh, *ql, *k0h, *k0l, *v0h, *v0l;
    cudaGetSymbolAddress((void**)&hid_h, c_hid_h);
    cudaGetSymbolAddress((void**)&hid_l, c_hid_l);
    cudaGetSymbolAddress((void**)&wq_h,  c_wq_h);
    cudaGetSymbolAddress((void**)&wq_l,  c_wq_l);
    cudaGetSymbolAddress((void**)&wk_h,  c_wk_h);
    cudaGetSymbolAddress((void**)&wk_l,  c_wk_l);
    cudaGetSymbolAddress((void**)&wv_h,  c_wv_h);
    cudaGetSymbolAddress((void**)&wv_l,  c_wv_l);
    cudaGetSymbolAddress((void**)&wo_h,  c_wo_h);
    cudaGetSymbolAddress((void**)&wo_l,  c_wo_l);
    cudaGetSymbolAddress((void**)&at_h,  c_at_h);
    cudaGetSymbolAddress((void**)&at_l,  c_at_l);
    cudaGetSymbolAddress((void**)&qh,    c_qh);
    cudaGetSymbolAddress((void**)&ql,    c_ql);
    cudaGetSymbolAddress((void**)&k0h,   c_k0h);
    cudaGetSymbolAddress((void**)&k0l,   c_k0l);
    cudaGetSymbolAddress((void**)&v0h,   c_v0h);
    cudaGetSymbolAddress((void**)&v0l,   c_v0l);

    cudaFuncSetAttribute(gemm_tc,
                         cudaFuncAttributeMaxDynamicSharedMemorySize, GSMEM_BYTES);
    cudaFuncSetAttribute(attn_mma,
                         cudaFuncAttributeMaxDynamicSharedMemorySize, ATTN_SMEM2);

    const int M = BB * QQ;   // 2048
    const int NK0 = BB * HH * QQ * HD;   // 4,194,304

    // fp32 -> bf16 hi/lo splits
    {
        int n;
        n = 2048 * 4096; convert_hl<<<(n / 4 + 255) / 256, 256>>>(hidden, hid_h, hid_l, n / 4, 1.f);
        n = 2048 * 4096; convert_hl<<<(n / 4 + 255) / 256, 256>>>(Wq, wq_h, wq_l, n / 4, 1.f);
        n = 512  * 4096; convert_hl<<<(n / 4 + 255) / 256, 256>>>(Wk, wk_h, wk_l, n / 4, 1.f);
        n = 512  * 4096; convert_hl<<<(n / 4 + 255) / 256, 256>>>(Wv, wv_h, wv_l, n / 4, 1.f);
        n = 2048 * 2048; convert_hl<<<(n / 4 + 255) / 256, 256>>>(Wo, wo_h, wo_l, n / 4, 1.f);
        convert_hl<<<(NK0 / 4 + 255) / 256, 256>>>(ck, k0h, k0l, NK0 / 4, 1.f);
        convert_hl<<<(NK0 / 4 + 255) / 256, 256>>>(cv, v0h, v0l, NK0 / 4, 1.f);
    }

    // fused QKV projection
    gemm_tc<<<dim3(24, M / 128), 256, GSMEM_BYTES>>>(
        hid_h, hid_l,
        wq_h, wq_l, gq, HH * HD,
        wk_h, wk_l, gk, KVH * HD,
        wv_h, wv_l, gv, KVH * HD,
        K2HS);

    // RoPE, then q -> bf16 split with softmax scale folded
    {
        int total = BB * QQ * (HH + KVH) * 32;
        rope_kernel<<<(total + 255) / 256, 256>>>(gq, gk, pos);
        int n = 2048 * 2048;
        convert_hl<<<(n / 4 + 255) / 256, 256>>>(gq, qh, ql, n / 4, SCALE);
    }

    // tensor-core attention (writes bf16 hi/lo directly)
    attn_mma<<<dim3(QQ / BQ, HH, BB), 256, ATTN_SMEM2>>>(
        qh, ql, k0h, k0l, v0h, v0l, ck, cv, gk, gv, at_h, at_l);

    // output projection
    gemm_tc<<<dim3(16, M / 128), 256, GSMEM_BYTES>>>(
        at_h, at_l,
        wo_h, wo_l, out, HS,
        (const __nv_bfloat16*)0, (const __nv_bfloat16*)0, (float*)0, 0,
        (const __nv_bfloat16*)0, (const __nv_bfloat16*)0, (float*)0, 0,
        HH * HD);
}

// round 7
// speedup vs baseline: 2.9266x; 1.1022x over previous
#include <cuda_runtime.h>
#include <cuda_bf16.h>
#include <math.h>
#include <stdint.h>

// ---------------------------------------------------------------------------
// Problem constants
// ---------------------------------------------------------------------------
#define BB    2
#define QQ    1024
#define HH    32
#define KVH   8
#define HD    64
#define HS    2048
#define K2HS  4096
#define LCK   2
#define SCALE 0.125f

#define NEG_INF (__int_as_float(0xff800000))

// ---------------------------------------------------------------------------
// Scratch (no cudaMalloc allowed)
// ---------------------------------------------------------------------------
__device__ float g_q  [BB * QQ * HH  * HD];
__device__ float g_k  [BB * QQ * KVH * HD];
__device__ float g_v  [BB * QQ * KVH * HD];

// bf16 split-precision operands
__device__ __nv_bfloat16 c_hid_h[2048 * 4096];
__device__ __nv_bfloat16 c_hid_l[2048 * 4096];
__device__ __nv_bfloat16 c_wq_h [2048 * 4096];
__device__ __nv_bfloat16 c_wq_l [2048 * 4096];
__device__ __nv_bfloat16 c_wk_h [512  * 4096];
__device__ __nv_bfloat16 c_wk_l [512  * 4096];
__device__ __nv_bfloat16 c_wv_h [512  * 4096];
__device__ __nv_bfloat16 c_wv_l [512  * 4096];
__device__ __nv_bfloat16 c_wo_h [2048 * 2048];
__device__ __nv_bfloat16 c_wo_l [2048 * 2048];
__device__ __nv_bfloat16 c_at_h [2048 * 2048];
__device__ __nv_bfloat16 c_at_l [2048 * 2048];
__device__ __nv_bfloat16 c_qh [2048 * 2048];
__device__ __nv_bfloat16 c_ql [2048 * 2048];
__device__ __nv_bfloat16 c_k0h[BB * HH * QQ * HD];
__device__ __nv_bfloat16 c_k0l[BB * HH * QQ * HD];
__device__ __nv_bfloat16 c_v0h[BB * HH * QQ * HD];
__device__ __nv_bfloat16 c_v0l[BB * HH * QQ * HD];

// ---------------------------------------------------------------------------
// PTX helpers — plain-sm_100 legal only
// ---------------------------------------------------------------------------
__device__ __forceinline__ uint32_t smem_u32(const void* p) {
    uint32_t a;
    asm("{ .reg .u64 t; cvta.to.shared.u64 t, %1; cvt.u32.u64 %0, t; }"
        : "=r"(a) : "l"(p));
    return a;
}

#define CP_ASYNC16(dst, src) \
    asm volatile("cp.async.cg.shared.global [%0], [%1], 16;" \
                 :: "r"((uint32_t)(dst)), "l"(src))
#define CP_COMMIT() asm volatile("cp.async.commit_group;" ::: "memory")
#define CP_WAIT0()  asm volatile("cp.async.wait_group 0;" ::: "memory")
#define CP_WAIT1()  asm volatile("cp.async.wait_group 1;" ::: "memory")

__device__ __forceinline__ void ldsm4(uint32_t* r, uint32_t addr) {
    asm volatile("ldmatrix.sync.aligned.m8n8.x4.shared.b16 {%0,%1,%2,%3}, [%4];"
        : "=r"(r[0]), "=r"(r[1]), "=r"(r[2]), "=r"(r[3]) : "r"(addr));
}
__device__ __forceinline__ void ldsm4t(uint32_t* r, uint32_t addr) {
    asm volatile("ldmatrix.sync.aligned.m8n8.x4.trans.shared.b16 {%0,%1,%2,%3}, [%4];"
        : "=r"(r[0]), "=r"(r[1]), "=r"(r[2]), "=r"(r[3]) : "r"(addr));
}

__device__ __forceinline__ void mma_bf16(float* d, const uint32_t* a, const uint32_t* b) {
    asm volatile(
        "mma.sync.aligned.m16n8k16.row.col.f32.bf16.bf16.f32 "
        "{%0,%1,%2,%3}, {%4,%5,%6,%7}, {%8,%9}, {%0,%1,%2,%3};"
        : "+f"(d[0]), "+f"(d[1]), "+f"(d[2]), "+f"(d[3])
        : "r"(a[0]), "r"(a[1]), "r"(a[2]), "r"(a[3]), "r"(b[0]), "r"(b[1]));
}

__device__ __forceinline__ uint32_t packbf(float hi, float lo) {
    uint32_t r;
    asm("cvt.rn.bf16x2.f32 %0, %1, %2;" : "=r"(r) : "f"(hi), "f"(lo));
    return r;
}

// ---------------------------------------------------------------------------
// fp32 -> (bf16 hi, bf16 lo) split conversion, with scale
// ---------------------------------------------------------------------------
__global__ void convert_hl(const float* __restrict__ x, __nv_bfloat16* __restrict__ h,
                           __nv_bfloat16* __restrict__ l, int n4, float scale)
{
    int i = blockIdx.x * blockDim.x + threadIdx.x;
    if (i >= n4) return;
    float4 v = ((const float4*)x)[i];
    v.x *= scale; v.y *= scale; v.z *= scale; v.w *= scale;
    __nv_bfloat16 h0 = __float2bfloat16(v.x);
    __nv_bfloat16 h1 = __float2bfloat16(v.y);
    __nv_bfloat16 h2 = __float2bfloat16(v.z);
    __nv_bfloat16 h3 = __float2bfloat16(v.w);
    __nv_bfloat16 l0 = __float2bfloat16(v.x - __bfloat162float(h0));
    __nv_bfloat16 l1 = __float2bfloat16(v.y - __bfloat162float(h1));
    __nv_bfloat16 l2 = __float2bfloat16(v.z - __bfloat162float(h2));
    __nv_bfloat16 l3 = __float2bfloat16(v.w - __bfloat162float(h3));
    __nv_bfloat162* hp = (__nv_bfloat162*)h + i * 2;
    __nv_bfloat162* lp = (__nv_bfloat162*)l + i * 2;
    hp[0] = __halves2bfloat162(h0, h1);
    hp[1] = __halves2bfloat162(h2, h3);
    lp[0] = __halves2bfloat162(l0, l1);
    lp[1] = __halves2bfloat162(l2, l3);
}

// ---------------------------------------------------------------------------
// split-bf16 NT GEMM via mma.sync.
// BK=64, 3 stages, one __syncthreads per K-step, loads overlap MMA.
// Row stride 144B (128B data + 16B pad) -> conflict-free ldmatrix.
// ---------------------------------------------------------------------------
#define ROWB   144
#define TILEB  (128 * ROWB)          // 18432
#define STAGEB (4 * TILEB)           // 73728
#define GSMEM_BYTES (3 * STAGEB)     // 221184

__device__ __forceinline__ void load_stage(
    uint32_t sb, int buf, const char* Ah, const char* Al,
    const char* Bh, const char* Bl, int bm, int bn, int kb, int K, int tid)
{
    uint32_t st = sb + buf * STAGEB;
    #pragma unroll
    for (int j = 0; j < 16; j++) {
        int c    = tid + 256 * j;           // 0..4095
        int tile = c >> 10;                 // 0..3
        int row  = (c >> 3) & 127;
        int ch   = c & 7;
        const char* base = (tile == 0) ? Ah : (tile == 1) ? Al : (tile == 2) ? Bh : Bl;
        int rb = (tile < 2) ? bm : bn;
        uint32_t sa = st + tile * TILEB + row * ROWB + ch * 16;
        const char* ga = base + ((size_t)(rb + row) * K + kb + ch * 8) * 2;
        CP_ASYNC16(sa, ga);
    }
    CP_COMMIT();
}

__global__ __launch_bounds__(256, 1)
void gemm_tc(const __nv_bfloat16* __restrict__ Ah_, const __nv_bfloat16* __restrict__ Al_,
             const __nv_bfloat16* B0h, const __nv_bfloat16* B0l, float* C0, int N0,
             const __nv_bfloat16* B1h, const __nv_bfloat16* B1l, float* C1, int N1,
             const __nv_bfloat16* B2h, const __nv_bfloat16* B2l, float* C2, int N2,
             int K)
{
    extern __shared__ __align__(16) char smx[];
    uint32_t sb = smem_u32(smx);
    const int tid  = threadIdx.x;
    const int wid  = tid >> 5;
    const int lane = tid & 31;
    const int wm   = wid >> 1;
    const int wn   = wid & 1;
    const int bm   = blockIdx.y * 128;

    int xt = blockIdx.x;
    const __nv_bfloat16 *Bh, *Bl; float* C; int ldc, bn;
    int t0 = N0 >> 7, t1 = N1 >> 7;
    if (xt < t0)           { Bh = B0h; Bl = B0l; C = C0; ldc = N0; bn = xt << 7; }
    else if (xt < t0 + t1) { Bh = B1h; Bl = B1l; C = C1; ldc = N1; bn = (xt - t0) << 7; }
    else                   { Bh = B2h; Bl = B2l; C = C2; ldc = N2; bn = (xt - t0 - t1) << 7; }

    const char* cAh = (const char*)Ah_;
    const char* cAl = (const char*)Al_;
    const char* cBh = (const char*)Bh;
    const char* cBl = (const char*)Bl;

    float acc[2][8][4];
    #pragma unroll
    for (int i = 0; i < 2; i++)
        #pragma unroll
        for (int j = 0; j < 8; j++)
            #pragma unroll
            for (int q = 0; q < 4; q++) acc[i][j][q] = 0.f;

    const int nk = K >> 6;              // BK=64 steps
    load_stage(sb, 0, cAh, cAl, cBh, cBl, bm, bn, 0,  K, tid);
    load_stage(sb, 1, cAh, cAl, cBh, cBl, bm, bn, 64, K, tid);

    const int lr = lane & 15;
    const int lc = lane >> 4;

    for (int t = 0; t < nk; t++) {
        CP_WAIT1();
        __syncthreads();
        if (t + 2 < nk)
            load_stage(sb, (t + 2) % 3, cAh, cAl, cBh, cBl, bm, bn, (t + 2) * 64, K, tid);
        else
            CP_COMMIT();
        uint32_t st = sb + (t % 3) * STAGEB;

        #pragma unroll
        for (int k0 = 0; k0 < 64; k0 += 16) {
            uint32_t ah[2][4], al[2][4], bh[4][4], bl[4][4];
            uint32_t ao = (uint32_t)((wm * 32 + lr) * ROWB + (k0 + lc * 8) * 2);
            ldsm4(ah[0], st + ao);
            ldsm4(ah[1], st + ao + 16 * ROWB);
            ldsm4(al[0], st + TILEB + ao);
            ldsm4(al[1], st + TILEB + ao + 16 * ROWB);
            uint32_t bo = (uint32_t)((wn * 64 + lr) * ROWB + (k0 + lc * 8) * 2);
            #pragma unroll
            for (int nt = 0; nt < 4; nt++) {
                ldsm4(bh[nt], st + 2 * TILEB + bo + nt * 16 * ROWB);
                ldsm4(bl[nt], st + 3 * TILEB + bo + nt * 16 * ROWB);
            }
            #pragma unroll
            for (int mt = 0; mt < 2; mt++) {
                #pragma unroll
                for (int nt = 0; nt < 4; nt++) {
                    uint32_t b0h[2] = {bh[nt][0], bh[nt][2]};
                    uint32_t b1h[2] = {bh[nt][1], bh[nt][3]};
                    uint32_t b0l[2] = {bl[nt][0], bl[nt][2]};
                    uint32_t b1l[2] = {bl[nt][1], bl[nt][3]};
                    mma_bf16(acc[mt][2 * nt],     ah[mt], b0h);
                    mma_bf16(acc[mt][2 * nt],     al[mt], b0h);
                    mma_bf16(acc[mt][2 * nt],     ah[mt], b0l);
                    mma_bf16(acc[mt][2 * nt + 1], ah[mt], b1h);
                    mma_bf16(acc[mt][2 * nt + 1], al[mt], b1h);
                    mma_bf16(acc[mt][2 * nt + 1], ah[mt], b1l);
                }
            }
        }
    }

    const int lg = lane >> 2;
    const int lq = lane & 3;
    #pragma unroll
    for (int mt = 0; mt < 2; mt++) {
        int row = bm + wm * 32 + mt * 16 + lg;
        #pragma unroll
        for (int nf = 0; nf < 8; nf++) {
            float* p = C + (size_t)row * ldc + bn + wn * 64 + nf * 8 + 2 * lq;
            *(float2*)p               = make_float2(acc[mt][nf][0], acc[mt][nf][1]);
            *(float2*)(p + 8 * ldc)   = make_float2(acc[mt][nf][2], acc[mt][nf][3]);
        }
    }
}

// ---------------------------------------------------------------------------
// RoPE in-place on q and k
// ---------------------------------------------------------------------------
__global__ void rope_kernel(float* __restrict__ q, float* __restrict__ k,
                            const int* __restrict__ pos_ids)
{
    const int NQ = BB * QQ * HH  * 32;
    const int NK = BB * QQ * KVH * 32;
    int i = blockIdx.x * blockDim.x + threadIdx.x;
    if (i >= NQ + NK) return;

    float* base;
    int m, d;
    if (i < NQ) {
        d = i & 31;
        int h = (i >> 5) & (HH - 1);
        m = i >> 10;
        base = q + (size_t)m * (HH * HD) + h * HD + d;
    } else {
        int j = i - NQ;
        d = j & 31;
        int h = (j >> 5) & (KVH - 1);
        m = j >> 8;
        base = k + (size_t)m * (KVH * HD) + h * HD + d;
    }

    int pos = pos_ids[m] + LCK;
    double inv = pow(10000.0, -(double)d / 32.0);
    double ang = (double)pos * inv;
    float c = (float)cos(ang);
    float s = (float)sin(ang);

    float a = base[0], b2 = base[32];
    base[0]  = a  * c - b2 * s;
    base[32] = b2 * c + a  * s;
}

// ---------------------------------------------------------------------------
// Tensor-core flash attention (split-bf16 mma.sync).
// ---------------------------------------------------------------------------
#define BQ    128
#define BKEY  128
#define QROWB 144
#define SM_QH 0
#define SM_QL 18432
#define SM_ST 36864
#define STG_SZ 73728
#define OFF_KH 0
#define OFF_KL 18432
#define OFF_VH 36864
#define OFF_VL 55296
#define ATTN_SMEM2 (SM_ST + 2 * STG_SZ)   // 184320

__device__ __forceinline__ void attn_ldkv(uint32_t sb, int stg,
    const char* kh, const char* kl, const char* vh, const char* vl,
    size_t base2, int tid)
{
    uint32_t st = sb + SM_ST + stg * STG_SZ;
    #pragma unroll
    for (int j = 0; j < 4; j++) {
        int c = tid + 256 * j;
        int row = c >> 3, ch = c & 7;
        size_t off = base2 + (size_t)row * 128 + ch * 16;
        uint32_t d = row * QROWB + ch * 16;
        CP_ASYNC16(st + OFF_KH + d, kh + off);
        CP_ASYNC16(st + OFF_KL + d, kl + off);
        CP_ASYNC16(st + OFF_VH + d, vh + off);
        CP_ASYNC16(st + OFF_VL + d, vl + off);
    }
    CP_COMMIT();
}

__global__ __launch_bounds__(256, 1)
void attn_mma(const __nv_bfloat16* __restrict__ qh_g, const __nv_bfloat16* __restrict__ ql_g,
              const __nv_bfloat16* __restrict__ k0h, const __nv_bfloat16* __restrict__ k0l,
              const __nv_bfloat16* __restrict__ v0h, const __nv_bfloat16* __restrict__ v0l,
              const float* __restrict__ cache_k, const float* __restrict__ cache_v,
              const float* __restrict__ gk, const float* __restrict__ gv,
              __nv_bfloat16* __restrict__ outh, __nv_bfloat16* __restrict__ outl)
{
    extern __shared__ __align__(16) char smp[];
    uint32_t sb = smem_u32(smp);
    const int tid = threadIdx.x, wid = tid >> 5, lane = tid & 31;
    const int lg = lane >> 2, lq = lane & 3;
    const int qt = blockIdx.x, h = blockIdx.y, b = blockIdx.z;
    const int qb = qt * BQ;

    {
        const char* ch_ = (const char*)qh_g;
        const char* cl_ = (const char*)ql_g;
        #pragma unroll
        for (int j = 0; j < 4; j++) {
            int c = tid + 256 * j;
            int row = c >> 3, ch = c & 7;
            size_t off = (((size_t)(b * QQ + qb + row)) * 2048 + h * 64 + ch * 8) * 2;
            uint32_t d = row * QROWB + ch * 16;
            CP_ASYNC16(sb + SM_QH + d, ch_ + off);
            CP_ASYNC16(sb + SM_QL + d, cl_ + off);
        }
        CP_COMMIT();
    }

    const char* ck0h = (const char*)k0h;
    const char* ck0l = (const char*)k0l;
    const char* cv0h = (const char*)v0h;
    const char* cv0l = (const char*)v0l;
    size_t kvb2 = ((size_t)(b * HH + h)) * QQ * 64 * 2;
    attn_ldkv(sb, 0, ck0h, ck0l, cv0h, cv0l, kvb2, tid);
    if (qt >= 1)
        attn_ldkv(sb, 1, ck0h, ck0l, cv0h, cv0l, kvb2 + (size_t)BKEY * 128, tid);

    float s[16][4], o[8][4];
    #pragma unroll
    for (int nf = 0; nf < 8; nf++)
        #pragma unroll
        for (int c = 0; c < 4; c++) o[nf][c] = 0.f;
    float mr0 = NEG_INF, mr1 = NEG_INF, lr0 = 0.f, lr1 = 0.f;
    uint32_t qah[4][4], qal[4][4];

    for (int kt = 0; kt <= qt; kt++) {
        if (kt < qt) { CP_WAIT1(); } else { CP_WAIT0(); }
        __syncthreads();
        uint32_t st = sb + SM_ST + (kt & 1) * STG_SZ;

        if (kt == 0) {
            #pragma unroll
            for (int kc = 0; kc < 4; kc++) {
                uint32_t ao = (wid * 16 + (lane & 15)) * QROWB + (kc * 16 + (lane >> 4) * 8) * 2;
                ldsm4(qah[kc], sb + SM_QH + ao);
                ldsm4(qal[kc], sb + SM_QL + ao);
            }
        }

        #pragma unroll
        for (int nf = 0; nf < 16; nf++)
            #pragma unroll
            for (int c = 0; c < 4; c++) s[nf][c] = 0.f;
        #pragma unroll
        for (int kc = 0; kc < 4; kc++) {
            #pragma unroll
            for (int kg = 0; kg < 8; kg++) {
                uint32_t bo = (kg * 16 + (lane & 15)) * QROWB + (kc * 16 + (lane >> 4) * 8) * 2;
                uint32_t bh_[4], bl_[4];
                ldsm4(bh_, st + OFF_KH + bo);
                ldsm4(bl_, st + OFF_KL + bo);
                uint32_t b0h[2] = {bh_[0], bh_[2]}, b1h[2] = {bh_[1], bh_[3]};
                uint32_t b0l[2] = {bl_[0], bl_[2]}, b1l[2] = {bl_[1], bl_[3]};
                mma_bf16(s[2 * kg],     qah[kc], b0h);
                mma_bf16(s[2 * kg],     qal[kc], b0h);
                mma_bf16(s[2 * kg],     qah[kc], b0l);
                mma_bf16(s[2 * kg + 1], qah[kc], b1h);
                mma_bf16(s[2 * kg + 1], qal[kc], b1h);
                mma_bf16(s[2 * kg + 1], qah[kc], b1l);
            }
        }

        if (kt == qt) {
            int r0 = wid * 16 + lg;
            #pragma unroll
            for (int nf = 0; nf < 16; nf++) {
                int k0c = nf * 8 + 2 * lq;
                if (k0c     > r0)     s[nf][0] = -1e30f;
                if (k0c + 1 > r0)     s[nf][1] = -1e30f;
                if (k0c     > r0 + 8) s[nf][2] = -1e30f;
                if (k0c + 1 > r0 + 8) s[nf][3] = -1e30f;
            }
        }

        float mx0 = NEG_INF, mx1 = NEG_INF;
        #pragma unroll
        for (int nf = 0; nf < 16; nf++) {
            mx0 = fmaxf(mx0, fmaxf(s[nf][0], s[nf][1]));
            mx1 = fmaxf(mx1, fmaxf(s[nf][2], s[nf][3]));
        }
        mx0 = fmaxf(mx0, __shfl_xor_sync(0xffffffffu, mx0, 1));
        mx0 = fmaxf(mx0, __shfl_xor_sync(0xffffffffu, mx0, 2));
        mx1 = fmaxf(mx1, __shfl_xor_sync(0xffffffffu, mx1, 1));
        mx1 = fmaxf(mx1, __shfl_xor_sync(0xffffffffu, mx1, 2));
        float mn0 = fmaxf(mr0, mx0), mn1 = fmaxf(mr1, mx1);
        float al0 = __expf(mr0 - mn0), al1 = __expf(mr1 - mn1);
        mr0 = mn0; mr1 = mn1;
        float sum0 = 0.f, sum1 = 0.f;
        #pragma unroll
        for (int nf = 0; nf < 16; nf++) {
            s[nf][0] = __expf(s[nf][0] - mn0); sum0 += s[nf][0];
            s[nf][1] = __expf(s[nf][1] - mn0); sum0 += s[nf][1];
            s[nf][2] = __expf(s[nf][2] - mn1); sum1 += s[nf][2];
            s[nf][3] = __expf(s[nf][3] - mn1); sum1 += s[nf][3];
        }
        sum0 += __shfl_xor_sync(0xffffffffu, sum0, 1);
        sum0 += __shfl_xor_sync(0xffffffffu, sum0, 2);
        sum1 += __shfl_xor_sync(0xffffffffu, sum1, 1);
        sum1 += __shfl_xor_sync(0xffffffffu, sum1, 2);
        lr0 = lr0 * al0 + sum0;
        lr1 = lr1 * al1 + sum1;
        #pragma unroll
        for (int nf = 0; nf < 8; nf++) {
            o[nf][0] *= al0; o[nf][1] *= al0; o[nf][2] *= al1; o[nf][3] *= al1;
        }

        #pragma unroll
        for (int kc2 = 0; kc2 < 8; kc2++) {
            uint32_t pah[4], pal[4];
            #pragma unroll
            for (int t2 = 0; t2 < 2; t2++) {
                float* sv = s[2 * kc2 + t2];
                __nv_bfloat16 h0 = __float2bfloat16(sv[0]);
                __nv_bfloat16 h1 = __float2bfloat16(sv[1]);
                __nv_bfloat16 h2 = __float2bfloat16(sv[2]);
                __nv_bfloat16 h3 = __float2bfloat16(sv[3]);
                pah[2 * t2]     = ((uint32_t)__bfloat16_as_ushort(h1) << 16) | __bfloat16_as_ushort(h0);
                pah[2 * t2 + 1] = ((uint32_t)__bfloat16_as_ushort(h3) << 16) | __bfloat16_as_ushort(h2);
                pal[2 * t2]     = packbf(sv[1] - __bfloat162float(h1), sv[0] - __bfloat162float(h0));
                pal[2 * t2 + 1] = packbf(sv[3] - __bfloat162float(h3), sv[2] - __bfloat162float(h2));
            }
            #pragma unroll
            for (int dg = 0; dg < 4; dg++) {
                uint32_t vo = (kc2 * 16 + (lane & 15)) * QROWB + dg * 32 + (lane >> 4) * 16;
                uint32_t vh_[4], vl_[4];
                ldsm4t(vh_, st + OFF_VH + vo);
                ldsm4t(vl_, st + OFF_VL + vo);
                uint32_t b0h[2] = {vh_[0], vh_[1]}, b1h[2] = {vh_[2], vh_[3]};
                uint32_t b0l[2] = {vl_[0], vl_[1]}, b1l[2] = {vl_[2], vl_[3]};
                mma_bf16(o[2 * dg],     pah, b0h);
                mma_bf16(o[2 * dg],     pal, b0h);
                mma_bf16(o[2 * dg],     pah, b0l);
                mma_bf16(o[2 * dg + 1], pah, b1h);
                mma_bf16(o[2 * dg + 1], pal, b1h);
                mma_bf16(o[2 * dg + 1], pah, b1l);
            }
        }
        __syncthreads();
        if (kt + 2 <= qt)
            attn_ldkv(sb, kt & 1, ck0h, ck0l, cv0h, cv0l,
                      kvb2 + (size_t)(kt + 2) * BKEY * 128, tid);
    }

    #pragma unroll 1
    for (int e = 0; e < 2; e++) {
        const float* tk; const float* tv; int stride;
        if (e == 0) {
            size_t off = (((size_t)BB + b) * HH + h) * QQ * HD + (size_t)qb * HD;
            tk = cache_k + off; tv = cache_v + off; stride = 64;
        } else {
            size_t off = ((size_t)(b * QQ + qb)) * 512 + (h >> 2) * 64;
            tk = gk + off; tv = gv + off; stride = 512;
        }
        #pragma unroll
        for (int half = 0; half < 2; half++) {
            int rl = wid * 16 + lg + half * 8;
            const __nv_bfloat16* qhp = (const __nv_bfloat16*)(smp + SM_QH + rl * QROWB);
            const __nv_bfloat16* qlp = (const __nv_bfloat16*)(smp + SM_QL + rl * QROWB);
            float dot = 0.f;
            #pragma unroll
            for (int dd = 0; dd < 16; dd++) {
                int d = lq * 16 + dd;
                float qv = __bfloat162float(qhp[d]) + __bfloat162float(qlp[d]);
                dot += qv * tk[(size_t)rl * stride + d];
            }
            dot += __shfl_xor_sync(0xffffffffu, dot, 1);
            dot += __shfl_xor_sync(0xffffffffu, dot, 2);
            float mo = half ? mr1 : mr0;
            float mn = fmaxf(mo, dot);
            float a = __expf(mo - mn), p = __expf(dot - mn);
            if (half) { mr1 = mn; lr1 = lr1 * a + p; }
            else      { mr0 = mn; lr0 = lr0 * a + p; }
            #pragma unroll
            for (int nf = 0; nf < 8; nf++) {
                int d0 = nf * 8 + 2 * lq;
                float v0 = tv[(size_t)rl * stride + d0];
                float v1 = tv[(size_t)rl * stride + d0 + 1];
                o[nf][2 * half]     = o[nf][2 * half]     * a + p * v0;
                o[nf][2 * half + 1] = o[nf][2 * half + 1] * a + p * v1;
            }
        }
    }

    float inv0 = 1.f / lr0, inv1 = 1.f / lr1;
    #pragma unroll
    for (int half = 0; half < 2; half++) {
        int qrow = qb + wid * 16 + lg + half * 8;
        float inv = half ? inv1 : inv0;
        size_t base = ((size_t)(b * QQ) + qrow) * 2048 + h * 64;
        #pragma unroll
        for (int nf = 0; nf < 8; nf++) {
            float x0 = o[nf][2 * half] * inv;
            float x1 = o[nf][2 * half + 1] * inv;
            __nv_bfloat16 h0 = __float2bfloat16(x0), h1 = __float2bfloat16(x1);
            __nv_bfloat162 hp; hp.x = h0; hp.y = h1;
            *(__nv_bfloat162*)(outh + base + nf * 8 + 2 * lq) = hp;
            __nv_bfloat162 lp;
            lp.x = __float2bfloat16(x0 - __bfloat162float(h0));
            lp.y = __float2bfloat16(x1 - __bfloat162float(h1));
            *(__nv_bfloat162*)(outl + base + nf * 8 + 2 * lq) = lp;
        }
    }
}

// ---------------------------------------------------------------------------
// Launch
// ---------------------------------------------------------------------------
extern "C" void kernel_launch(void* const* d_in, const int* in_sizes, int n_in,
                              void* d_out, int out_size)
{
    (void)in_sizes; (void)n_in; (void)out_size;

    const float* hidden = (const float*)d_in[0];
    const float* Wq     = (const float*)d_in[1];
    const float* Wk     = (const float*)d_in[2];
    const float* Wv     = (const float*)d_in[3];
    const float* Wo     = (const float*)d_in[4];
    const float* ck     = (const float*)d_in[5];
    const float* cv     = (const float*)d_in[6];
    const int*   pos    = (const int*)d_in[8];
    float* out = (float*)d_out;

    float *gq, *gk, *gv;
    cudaGetSymbolAddress((void**)&gq, g_q);
    cudaGetSymbolAddress((void**)&gk, g_k);
    cudaGetSymbolAddress((void**)&gv, g_v);

    __nv_bfloat16 *hid_h, *hid_l, *wq_h, *wq_l, *wk_h, *wk_l, *wv_h, *wv_l;
    __nv_bfloat16 *wo_h, *wo_l, *at_h, *at_l, *qh, *ql, *k0h, *k0l, *v0h, *v0l;
    cudaGetSymbolAddress((void**)&hid_h, c_hid_h);
    cudaGetSymbolAddress((void**)&hid_l, c_hid_l);
    cudaGetSymbolAddress((void**)&wq_h,  c_wq_h);
    cudaGetSymbolAddress((void**)&wq_l,  c_wq_l);
    cudaGetSymbolAddress((void**)&wk_h,  c_wk_h);
    cudaGetSymbolAddress((void**)&wk_l,  c_wk_l);
    cudaGetSymbolAddress((void**)&wv_h,  c_wv_h);
    cudaGetSymbolAddress((void**)&wv_l,  c_wv_l);
    cudaGetSymbolAddress((void**)&wo_h,  c_wo_h);
    cudaGetSymbolAddress((void**)&wo_l,  c_wo_l);
    cudaGetSymbolAddress((void**)&at_h,  c_at_h);
    cudaGetSymbolAddress((void**)&at_l,  c_at_l);
    cudaGetSymbolAddress((void**)&qh,    c_qh);
    cudaGetSymbolAddress((void**)&ql,    c_ql);
    cudaGetSymbolAddress((void**)&k0h,   c_k0h);
    cudaGetSymbolAddress((void**)&k0l,   c_k0l);
    cudaGetSymbolAddress((void**)&v0h,   c_v0h);
    cudaGetSymbolAddress((void**)&v0l,   c_v0l);

    cudaFuncSetAttribute(gemm_tc,
                         cudaFuncAttributeMaxDynamicSharedMemorySize, GSMEM_BYTES);
    cudaFuncSetAttribute(attn_mma,
                         cudaFuncAttributeMaxDynamicSharedMemorySize, ATTN_SMEM2);

    const int M = BB * QQ;   // 2048
    const int NK0 = BB * HH * QQ * HD;

    {
        int n;
        n = 2048 * 4096; convert_hl<<<(n / 4 + 255) / 256, 256>>>(hidden, hid_h, hid_l, n / 4, 1.f);
        n = 2048 * 4096; convert_hl<<<(n / 4 + 255) / 256, 256>>>(Wq, wq_h, wq_l, n / 4, 1.f);
        n = 512  * 4096; convert_hl<<<(n / 4 + 255) / 256, 256>>>(Wk, wk_h, wk_l, n / 4, 1.f);
        n = 512  * 4096; convert_hl<<<(n / 4 + 255) / 256, 256>>>(Wv, wv_h, wv_l, n / 4, 1.f);
        n = 2048 * 2048; convert_hl<<<(n / 4 + 255) / 256, 256>>>(Wo, wo_h, wo_l, n / 4, 1.f);
        convert_hl<<<(NK0 / 4 + 255) / 256, 256>>>(ck, k0h, k0l, NK0 / 4, 1.f);
        convert_hl<<<(NK0 / 4 + 255) / 256, 256>>>(cv, v0h, v0l, NK0 / 4, 1.f);
    }

    gemm_tc<<<dim3(24, M / 128), 256, GSMEM_BYTES>>>(
        hid_h, hid_l,
        wq_h, wq_l, gq, HH * HD,
        wk_h, wk_l, gk, KVH * HD,
        wv_h, wv_l, gv, KVH * HD,
        K2HS);

    {
        int total = BB * QQ * (HH + KVH) * 32;
        rope_kernel<<<(total + 255) / 256, 256>>>(gq, gk, pos);
        int n = 2048 * 2048;
        convert_hl<<<(n / 4 + 255) / 256, 256>>>(gq, qh, ql, n / 4, SCALE);
    }

    attn_mma<<<dim3(QQ / BQ, HH, BB), 256, ATTN_SMEM2>>>(
        qh, ql, k0h, k0l, v0h, v0l, ck, cv, gk, gv, at_h, at_l);

    gemm_tc<<<dim3(16, M / 128), 256, GSMEM_BYTES>>>(
        at_h, at_l,
        wo_h, wo_l, out, HS,
        (const __nv_bfloat16*)0, (const __nv_bfloat16*)0, (float*)0, 0,
        (const __nv_bfloat16*)0, (const __nv_bfloat16*)0, (float*)0, 0,
        HH * HD);
}

// round 8
// speedup vs baseline: 2.9978x; 1.0243x over previous
#include <cuda_runtime.h>
#include <cuda_bf16.h>
#include <math.h>
#include <stdint.h>

// ---------------------------------------------------------------------------
// Problem constants
// ---------------------------------------------------------------------------
#define BB    2
#define QQ    1024
#define HH    32
#define KVH   8
#define HD    64
#define HS    2048
#define K2HS  4096
#define LCK   2
#define SCALE 0.125f

#define NEG_INF (__int_as_float(0xff800000))

// ---------------------------------------------------------------------------
// Scratch (no cudaMalloc allowed)
// ---------------------------------------------------------------------------
__device__ float g_q  [BB * QQ * HH  * HD];
__device__ float g_k  [BB * QQ * KVH * HD];
__device__ float g_v  [BB * QQ * KVH * HD];
__device__ double g_invf[32];

// bf16 split-precision operands
__device__ __nv_bfloat16 c_hid_h[2048 * 4096];
__device__ __nv_bfloat16 c_hid_l[2048 * 4096];
__device__ __nv_bfloat16 c_wq_h [2048 * 4096];
__device__ __nv_bfloat16 c_wq_l [2048 * 4096];
__device__ __nv_bfloat16 c_wk_h [512  * 4096];
__device__ __nv_bfloat16 c_wk_l [512  * 4096];
__device__ __nv_bfloat16 c_wv_h [512  * 4096];
__device__ __nv_bfloat16 c_wv_l [512  * 4096];
__device__ __nv_bfloat16 c_wo_h [2048 * 2048];
__device__ __nv_bfloat16 c_wo_l [2048 * 2048];
__device__ __nv_bfloat16 c_at_h [2048 * 2048];
__device__ __nv_bfloat16 c_at_l [2048 * 2048];
__device__ __nv_bfloat16 c_qh [2048 * 2048];
__device__ __nv_bfloat16 c_ql [2048 * 2048];
__device__ __nv_bfloat16 c_k0h[BB * HH * QQ * HD];
__device__ __nv_bfloat16 c_k0l[BB * HH * QQ * HD];
__device__ __nv_bfloat16 c_v0h[BB * HH * QQ * HD];
__device__ __nv_bfloat16 c_v0l[BB * HH * QQ * HD];

// ---------------------------------------------------------------------------
// PTX helpers — plain-sm_100 legal only
// ---------------------------------------------------------------------------
__device__ __forceinline__ uint32_t smem_u32(const void* p) {
    uint32_t a;
    asm("{ .reg .u64 t; cvta.to.shared.u64 t, %1; cvt.u32.u64 %0, t; }"
        : "=r"(a) : "l"(p));
    return a;
}

#define CP_ASYNC16(dst, src) \
    asm volatile("cp.async.cg.shared.global [%0], [%1], 16;" \
                 :: "r"((uint32_t)(dst)), "l"(src))
#define CP_COMMIT() asm volatile("cp.async.commit_group;" ::: "memory")
#define CP_WAIT0()  asm volatile("cp.async.wait_group 0;" ::: "memory")
#define CP_WAIT1()  asm volatile("cp.async.wait_group 1;" ::: "memory")

__device__ __forceinline__ void ldsm4(uint32_t* r, uint32_t addr) {
    asm volatile("ldmatrix.sync.aligned.m8n8.x4.shared.b16 {%0,%1,%2,%3}, [%4];"
        : "=r"(r[0]), "=r"(r[1]), "=r"(r[2]), "=r"(r[3]) : "r"(addr));
}
__device__ __forceinline__ void ldsm4t(uint32_t* r, uint32_t addr) {
    asm volatile("ldmatrix.sync.aligned.m8n8.x4.trans.shared.b16 {%0,%1,%2,%3}, [%4];"
        : "=r"(r[0]), "=r"(r[1]), "=r"(r[2]), "=r"(r[3]) : "r"(addr));
}

__device__ __forceinline__ void mma_bf16(float* d, const uint32_t* a, const uint32_t* b) {
    asm volatile(
        "mma.sync.aligned.m16n8k16.row.col.f32.bf16.bf16.f32 "
        "{%0,%1,%2,%3}, {%4,%5,%6,%7}, {%8,%9}, {%0,%1,%2,%3};"
        : "+f"(d[0]), "+f"(d[1]), "+f"(d[2]), "+f"(d[3])
        : "r"(a[0]), "r"(a[1]), "r"(a[2]), "r"(a[3]), "r"(b[0]), "r"(b[1]));
}

__device__ __forceinline__ uint32_t packbf(float hi, float lo) {
    uint32_t r;
    asm("cvt.rn.bf16x2.f32 %0, %1, %2;" : "=r"(r) : "f"(hi), "f"(lo));
    return r;
}

// ---------------------------------------------------------------------------
// inv_freq table setup (exact double pow, once)
// ---------------------------------------------------------------------------
__global__ void setup_invf()
{
    int d = threadIdx.x;
    if (d < 32) g_invf[d] = pow(10000.0, -(double)d / 32.0);
}

// ---------------------------------------------------------------------------
// fp32 -> (bf16 hi, bf16 lo) split conversion; 4 float4 per thread (MLP=4).
// Requires n4 % 1024 == 0 (true for all call sites); grid = n4/1024.
// ---------------------------------------------------------------------------
__global__ void convert_hl(const float* __restrict__ x, __nv_bfloat16* __restrict__ h,
                           __nv_bfloat16* __restrict__ l, int n4, float scale)
{
    int i0 = blockIdx.x * 1024 + threadIdx.x;
    float4 v[4];
    #pragma unroll
    for (int u = 0; u < 4; u++)
        v[u] = ((const float4*)x)[i0 + u * 256];
    #pragma unroll
    for (int u = 0; u < 4; u++) {
        int i = i0 + u * 256;
        float x0 = v[u].x * scale, x1 = v[u].y * scale;
        float x2 = v[u].z * scale, x3 = v[u].w * scale;
        __nv_bfloat16 h0 = __float2bfloat16(x0);
        __nv_bfloat16 h1 = __float2bfloat16(x1);
        __nv_bfloat16 h2 = __float2bfloat16(x2);
        __nv_bfloat16 h3 = __float2bfloat16(x3);
        __nv_bfloat162* hp = (__nv_bfloat162*)h + i * 2;
        __nv_bfloat162* lp = (__nv_bfloat162*)l + i * 2;
        hp[0] = __halves2bfloat162(h0, h1);
        hp[1] = __halves2bfloat162(h2, h3);
        lp[0] = __halves2bfloat162(__float2bfloat16(x0 - __bfloat162float(h0)),
                                   __float2bfloat16(x1 - __bfloat162float(h1)));
        lp[1] = __halves2bfloat162(__float2bfloat16(x2 - __bfloat162float(h2)),
                                   __float2bfloat16(x3 - __bfloat162float(h3)));
    }
}

// ---------------------------------------------------------------------------
// Fused RoPE (+ Q scale + bf16 hi/lo split).
// q: rotate, scale by 1/8, split -> qh/ql.   k: rotate in place (fp32).
// Angle: double pos*invf, mod-2pi reduced in double, fp32 sincos.
// ---------------------------------------------------------------------------
__global__ void rope_conv(float* __restrict__ q, float* __restrict__ k,
                          const int* __restrict__ pos_ids,
                          __nv_bfloat16* __restrict__ qh, __nv_bfloat16* __restrict__ ql)
{
    const int NQ = BB * QQ * HH  * 32;   // 2,097,152
    const int NK = BB * QQ * KVH * 32;   //   524,288
    int i = blockIdx.x * blockDim.x + threadIdx.x;
    if (i >= NQ + NK) return;

    const double TWO_PI  = 6.283185307179586476925286766559;
    const double INV_2PI = 0.15915494309189533576888376337251;

    if (i < NQ) {
        int d = i & 31;
        int m = i >> 10;                          // token index b*Q+q
        size_t off = (size_t)m * (HH * HD) + ((i >> 5) & (HH - 1)) * HD + d;
        double ang = (double)(pos_ids[m] + LCK) * g_invf[d];
        double r = fma(-rint(ang * INV_2PI), TWO_PI, ang);
        float s, c;
        sincosf((float)r, &s, &c);
        float a = q[off], b2 = q[off + 32];
        float r0 = (a * c - b2 * s) * SCALE;
        float r1 = (b2 * c + a * s) * SCALE;
        __nv_bfloat16 h0 = __float2bfloat16(r0);
        __nv_bfloat16 h1 = __float2bfloat16(r1);
        qh[off]      = h0;
        qh[off + 32] = h1;
        ql[off]      = __float2bfloat16(r0 - __bfloat162float(h0));
        ql[off + 32] = __float2bfloat16(r1 - __bfloat162float(h1));
    } else {
        int j = i - NQ;
        int d = j & 31;
        int m = j >> 8;
        size_t off = (size_t)m * (KVH * HD) + ((j >> 5) & (KVH - 1)) * HD + d;
        double ang = (double)(pos_ids[m] + LCK) * g_invf[d];
        double r = fma(-rint(ang * INV_2PI), TWO_PI, ang);
        float s, c;
        sincosf((float)r, &s, &c);
        float a = k[off], b2 = k[off + 32];
        k[off]      = a  * c - b2 * s;
        k[off + 32] = b2 * c + a  * s;
    }
}

// ---------------------------------------------------------------------------
// split-bf16 NT GEMM via mma.sync (unchanged round-7 winner).
// BK=64, 3 stages, one __syncthreads per K-step, loads overlap MMA.
// ---------------------------------------------------------------------------
#define ROWB   144
#define TILEB  (128 * ROWB)          // 18432
#define STAGEB (4 * TILEB)           // 73728
#define GSMEM_BYTES (3 * STAGEB)     // 221184

__device__ __forceinline__ void load_stage(
    uint32_t sb, int buf, const char* Ah, const char* Al,
    const char* Bh, const char* Bl, int bm, int bn, int kb, int K, int tid)
{
    uint32_t st = sb + buf * STAGEB;
    #pragma unroll
    for (int j = 0; j < 16; j++) {
        int c    = tid + 256 * j;
        int tile = c >> 10;
        int row  = (c >> 3) & 127;
        int ch   = c & 7;
        const char* base = (tile == 0) ? Ah : (tile == 1) ? Al : (tile == 2) ? Bh : Bl;
        int rb = (tile < 2) ? bm : bn;
        uint32_t sa = st + tile * TILEB + row * ROWB + ch * 16;
        const char* ga = base + ((size_t)(rb + row) * K + kb + ch * 8) * 2;
        CP_ASYNC16(sa, ga);
    }
    CP_COMMIT();
}

__global__ __launch_bounds__(256, 1)
void gemm_tc(const __nv_bfloat16* __restrict__ Ah_, const __nv_bfloat16* __restrict__ Al_,
             const __nv_bfloat16* B0h, const __nv_bfloat16* B0l, float* C0, int N0,
             const __nv_bfloat16* B1h, const __nv_bfloat16* B1l, float* C1, int N1,
             const __nv_bfloat16* B2h, const __nv_bfloat16* B2l, float* C2, int N2,
             int K)
{
    extern __shared__ __align__(16) char smx[];
    uint32_t sb = smem_u32(smx);
    const int tid  = threadIdx.x;
    const int wid  = tid >> 5;
    const int lane = tid & 31;
    const int wm   = wid >> 1;
    const int wn   = wid & 1;
    const int bm   = blockIdx.y * 128;

    int xt = blockIdx.x;
    const __nv_bfloat16 *Bh, *Bl; float* C; int ldc, bn;
    int t0 = N0 >> 7, t1 = N1 >> 7;
    if (xt < t0)           { Bh = B0h; Bl = B0l; C = C0; ldc = N0; bn = xt << 7; }
    else if (xt < t0 + t1) { Bh = B1h; Bl = B1l; C = C1; ldc = N1; bn = (xt - t0) << 7; }
    else                   { Bh = B2h; Bl = B2l; C = C2; ldc = N2; bn = (xt - t0 - t1) << 7; }

    const char* cAh = (const char*)Ah_;
    const char* cAl = (const char*)Al_;
    const char* cBh = (const char*)Bh;
    const char* cBl = (const char*)Bl;

    float acc[2][8][4];
    #pragma unroll
    for (int i = 0; i < 2; i++)
        #pragma unroll
        for (int j = 0; j < 8; j++)
            #pragma unroll
            for (int q = 0; q < 4; q++) acc[i][j][q] = 0.f;

    const int nk = K >> 6;
    load_stage(sb, 0, cAh, cAl, cBh, cBl, bm, bn, 0,  K, tid);
    load_stage(sb, 1, cAh, cAl, cBh, cBl, bm, bn, 64, K, tid);

    const int lr = lane & 15;
    const int lc = lane >> 4;

    for (int t = 0; t < nk; t++) {
        CP_WAIT1();
        __syncthreads();
        if (t + 2 < nk)
            load_stage(sb, (t + 2) % 3, cAh, cAl, cBh, cBl, bm, bn, (t + 2) * 64, K, tid);
        else
            CP_COMMIT();
        uint32_t st = sb + (t % 3) * STAGEB;

        #pragma unroll
        for (int k0 = 0; k0 < 64; k0 += 16) {
            uint32_t ah[2][4], al[2][4], bh[4][4], bl[4][4];
            uint32_t ao = (uint32_t)((wm * 32 + lr) * ROWB + (k0 + lc * 8) * 2);
            ldsm4(ah[0], st + ao);
            ldsm4(ah[1], st + ao + 16 * ROWB);
            ldsm4(al[0], st + TILEB + ao);
            ldsm4(al[1], st + TILEB + ao + 16 * ROWB);
            uint32_t bo = (uint32_t)((wn * 64 + lr) * ROWB + (k0 + lc * 8) * 2);
            #pragma unroll
            for (int nt = 0; nt < 4; nt++) {
                ldsm4(bh[nt], st + 2 * TILEB + bo + nt * 16 * ROWB);
                ldsm4(bl[nt], st + 3 * TILEB + bo + nt * 16 * ROWB);
            }
            #pragma unroll
            for (int mt = 0; mt < 2; mt++) {
                #pragma unroll
                for (int nt = 0; nt < 4; nt++) {
                    uint32_t b0h[2] = {bh[nt][0], bh[nt][2]};
                    uint32_t b1h[2] = {bh[nt][1], bh[nt][3]};
                    uint32_t b0l[2] = {bl[nt][0], bl[nt][2]};
                    uint32_t b1l[2] = {bl[nt][1], bl[nt][3]};
                    mma_bf16(acc[mt][2 * nt],     ah[mt], b0h);
                    mma_bf16(acc[mt][2 * nt],     al[mt], b0h);
                    mma_bf16(acc[mt][2 * nt],     ah[mt], b0l);
                    mma_bf16(acc[mt][2 * nt + 1], ah[mt], b1h);
                    mma_bf16(acc[mt][2 * nt + 1], al[mt], b1h);
                    mma_bf16(acc[mt][2 * nt + 1], ah[mt], b1l);
                }
            }
        }
    }

    const int lg = lane >> 2;
    const int lq = lane & 3;
    #pragma unroll
    for (int mt = 0; mt < 2; mt++) {
        int row = bm + wm * 32 + mt * 16 + lg;
        #pragma unroll
        for (int nf = 0; nf < 8; nf++) {
            float* p = C + (size_t)row * ldc + bn + wn * 64 + nf * 8 + 2 * lq;
            *(float2*)p               = make_float2(acc[mt][nf][0], acc[mt][nf][1]);
            *(float2*)(p + 8 * ldc)   = make_float2(acc[mt][nf][2], acc[mt][nf][3]);
        }
    }
}

// ---------------------------------------------------------------------------
// Tensor-core flash attention (split-bf16 mma.sync), unchanged.
// ---------------------------------------------------------------------------
#define BQ    128
#define BKEY  128
#define QROWB 144
#define SM_QH 0
#define SM_QL 18432
#define SM_ST 36864
#define STG_SZ 73728
#define OFF_KH 0
#define OFF_KL 18432
#define OFF_VH 36864
#define OFF_VL 55296
#define ATTN_SMEM2 (SM_ST + 2 * STG_SZ)   // 184320

__device__ __forceinline__ void attn_ldkv(uint32_t sb, int stg,
    const char* kh, const char* kl, const char* vh, const char* vl,
    size_t base2, int tid)
{
    uint32_t st = sb + SM_ST + stg * STG_SZ;
    #pragma unroll
    for (int j = 0; j < 4; j++) {
        int c = tid + 256 * j;
        int row = c >> 3, ch = c & 7;
        size_t off = base2 + (size_t)row * 128 + ch * 16;
        uint32_t d = row * QROWB + ch * 16;
        CP_ASYNC16(st + OFF_KH + d, kh + off);
        CP_ASYNC16(st + OFF_KL + d, kl + off);
        CP_ASYNC16(st + OFF_VH + d, vh + off);
        CP_ASYNC16(st + OFF_VL + d, vl + off);
    }
    CP_COMMIT();
}

__global__ __launch_bounds__(256, 1)
void attn_mma(const __nv_bfloat16* __restrict__ qh_g, const __nv_bfloat16* __restrict__ ql_g,
              const __nv_bfloat16* __restrict__ k0h, const __nv_bfloat16* __restrict__ k0l,
              const __nv_bfloat16* __restrict__ v0h, const __nv_bfloat16* __restrict__ v0l,
              const float* __restrict__ cache_k, const float* __restrict__ cache_v,
              const float* __restrict__ gk, const float* __restrict__ gv,
              __nv_bfloat16* __restrict__ outh, __nv_bfloat16* __restrict__ outl)
{
    extern __shared__ __align__(16) char smp[];
    uint32_t sb = smem_u32(smp);
    const int tid = threadIdx.x, wid = tid >> 5, lane = tid & 31;
    const int lg = lane >> 2, lq = lane & 3;
    const int qt = blockIdx.x, h = blockIdx.y, b = blockIdx.z;
    const int qb = qt * BQ;

    {
        const char* ch_ = (const char*)qh_g;
        const char* cl_ = (const char*)ql_g;
        #pragma unroll
        for (int j = 0; j < 4; j++) {
            int c = tid + 256 * j;
            int row = c >> 3, ch = c & 7;
            size_t off = (((size_t)(b * QQ + qb + row)) * 2048 + h * 64 + ch * 8) * 2;
            uint32_t d = row * QROWB + ch * 16;
            CP_ASYNC16(sb + SM_QH + d, ch_ + off);
            CP_ASYNC16(sb + SM_QL + d, cl_ + off);
        }
        CP_COMMIT();
    }

    const char* ck0h = (const char*)k0h;
    const char* ck0l = (const char*)k0l;
    const char* cv0h = (const char*)v0h;
    const char* cv0l = (const char*)v0l;
    size_t kvb2 = ((size_t)(b * HH + h)) * QQ * 64 * 2;
    attn_ldkv(sb, 0, ck0h, ck0l, cv0h, cv0l, kvb2, tid);
    if (qt >= 1)
        attn_ldkv(sb, 1, ck0h, ck0l, cv0h, cv0l, kvb2 + (size_t)BKEY * 128, tid);

    float s[16][4], o[8][4];
    #pragma unroll
    for (int nf = 0; nf < 8; nf++)
        #pragma unroll
        for (int c = 0; c < 4; c++) o[nf][c] = 0.f;
    float mr0 = NEG_INF, mr1 = NEG_INF, lr0 = 0.f, lr1 = 0.f;
    uint32_t qah[4][4], qal[4][4];

    for (int kt = 0; kt <= qt; kt++) {
        if (kt < qt) { CP_WAIT1(); } else { CP_WAIT0(); }
        __syncthreads();
        uint32_t st = sb + SM_ST + (kt & 1) * STG_SZ;

        if (kt == 0) {
            #pragma unroll
            for (int kc = 0; kc < 4; kc++) {
                uint32_t ao = (wid * 16 + (lane & 15)) * QROWB + (kc * 16 + (lane >> 4) * 8) * 2;
                ldsm4(qah[kc], sb + SM_QH + ao);
                ldsm4(qal[kc], sb + SM_QL + ao);
            }
        }

        #pragma unroll
        for (int nf = 0; nf < 16; nf++)
            #pragma unroll
            for (int c = 0; c < 4; c++) s[nf][c] = 0.f;
        #pragma unroll
        for (int kc = 0; kc < 4; kc++) {
            #pragma unroll
            for (int kg = 0; kg < 8; kg++) {
                uint32_t bo = (kg * 16 + (lane & 15)) * QROWB + (kc * 16 + (lane >> 4) * 8) * 2;
                uint32_t bh_[4], bl_[4];
                ldsm4(bh_, st + OFF_KH + bo);
                ldsm4(bl_, st + OFF_KL + bo);
                uint32_t b0h[2] = {bh_[0], bh_[2]}, b1h[2] = {bh_[1], bh_[3]};
                uint32_t b0l[2] = {bl_[0], bl_[2]}, b1l[2] = {bl_[1], bl_[3]};
                mma_bf16(s[2 * kg],     qah[kc], b0h);
                mma_bf16(s[2 * kg],     qal[kc], b0h);
                mma_bf16(s[2 * kg],     qah[kc], b0l);
                mma_bf16(s[2 * kg + 1], qah[kc], b1h);
                mma_bf16(s[2 * kg + 1], qal[kc], b1h);
                mma_bf16(s[2 * kg + 1], qah[kc], b1l);
            }
        }

        if (kt == qt) {
            int r0 = wid * 16 + lg;
            #pragma unroll
            for (int nf = 0; nf < 16; nf++) {
                int k0c = nf * 8 + 2 * lq;
                if (k0c     > r0)     s[nf][0] = -1e30f;
                if (k0c + 1 > r0)     s[nf][1] = -1e30f;
                if (k0c     > r0 + 8) s[nf][2] = -1e30f;
                if (k0c + 1 > r0 + 8) s[nf][3] = -1e30f;
            }
        }

        float mx0 = NEG_INF, mx1 = NEG_INF;
        #pragma unroll
        for (int nf = 0; nf < 16; nf++) {
            mx0 = fmaxf(mx0, fmaxf(s[nf][0], s[nf][1]));
            mx1 = fmaxf(mx1, fmaxf(s[nf][2], s[nf][3]));
        }
        mx0 = fmaxf(mx0, __shfl_xor_sync(0xffffffffu, mx0, 1));
        mx0 = fmaxf(mx0, __shfl_xor_sync(0xffffffffu, mx0, 2));
        mx1 = fmaxf(mx1, __shfl_xor_sync(0xffffffffu, mx1, 1));
        mx1 = fmaxf(mx1, __shfl_xor_sync(0xffffffffu, mx1, 2));
        float mn0 = fmaxf(mr0, mx0), mn1 = fmaxf(mr1, mx1);
        float al0 = __expf(mr0 - mn0), al1 = __expf(mr1 - mn1);
        mr0 = mn0; mr1 = mn1;
        float sum0 = 0.f, sum1 = 0.f;
        #pragma unroll
        for (int nf = 0; nf < 16; nf++) {
            s[nf][0] = __expf(s[nf][0] - mn0); sum0 += s[nf][0];
            s[nf][1] = __expf(s[nf][1] - mn0); sum0 += s[nf][1];
            s[nf][2] = __expf(s[nf][2] - mn1); sum1 += s[nf][2];
            s[nf][3] = __expf(s[nf][3] - mn1); sum1 += s[nf][3];
        }
        sum0 += __shfl_xor_sync(0xffffffffu, sum0, 1);
        sum0 += __shfl_xor_sync(0xffffffffu, sum0, 2);
        sum1 += __shfl_xor_sync(0xffffffffu, sum1, 1);
        sum1 += __shfl_xor_sync(0xffffffffu, sum1, 2);
        lr0 = lr0 * al0 + sum0;
        lr1 = lr1 * al1 + sum1;
        #pragma unroll
        for (int nf = 0; nf < 8; nf++) {
            o[nf][0] *= al0; o[nf][1] *= al0; o[nf][2] *= al1; o[nf][3] *= al1;
        }

        #pragma unroll
        for (int kc2 = 0; kc2 < 8; kc2++) {
            uint32_t pah[4], pal[4];
            #pragma unroll
            for (int t2 = 0; t2 < 2; t2++) {
                float* sv = s[2 * kc2 + t2];
                __nv_bfloat16 h0 = __float2bfloat16(sv[0]);
                __nv_bfloat16 h1 = __float2bfloat16(sv[1]);
                __nv_bfloat16 h2 = __float2bfloat16(sv[2]);
                __nv_bfloat16 h3 = __float2bfloat16(sv[3]);
                pah[2 * t2]     = ((uint32_t)__bfloat16_as_ushort(h1) << 16) | __bfloat16_as_ushort(h0);
                pah[2 * t2 + 1] = ((uint32_t)__bfloat16_as_ushort(h3) << 16) | __bfloat16_as_ushort(h2);
                pal[2 * t2]     = packbf(sv[1] - __bfloat162float(h1), sv[0] - __bfloat162float(h0));
                pal[2 * t2 + 1] = packbf(sv[3] - __bfloat162float(h3), sv[2] - __bfloat162float(h2));
            }
            #pragma unroll
            for (int dg = 0; dg < 4; dg++) {
                uint32_t vo = (kc2 * 16 + (lane & 15)) * QROWB + dg * 32 + (lane >> 4) * 16;
                uint32_t vh_[4], vl_[4];
                ldsm4t(vh_, st + OFF_VH + vo);
                ldsm4t(vl_, st + OFF_VL + vo);
                uint32_t b0h[2] = {vh_[0], vh_[1]}, b1h[2] = {vh_[2], vh_[3]};
                uint32_t b0l[2] = {vl_[0], vl_[1]}, b1l[2] = {vl_[2], vl_[3]};
                mma_bf16(o[2 * dg],     pah, b0h);
                mma_bf16(o[2 * dg],     pal, b0h);
                mma_bf16(o[2 * dg],     pah, b0l);
                mma_bf16(o[2 * dg + 1], pah, b1h);
                mma_bf16(o[2 * dg + 1], pal, b1h);
                mma_bf16(o[2 * dg + 1], pah, b1l);
            }
        }
        __syncthreads();
        if (kt + 2 <= qt)
            attn_ldkv(sb, kt & 1, ck0h, ck0l, cv0h, cv0l,
                      kvb2 + (size_t)(kt + 2) * BKEY * 128, tid);
    }

    #pragma unroll 1
    for (int e = 0; e < 2; e++) {
        const float* tk; const float* tv; int stride;
        if (e == 0) {
            size_t off = (((size_t)BB + b) * HH + h) * QQ * HD + (size_t)qb * HD;
            tk = cache_k + off; tv = cache_v + off; stride = 64;
        } else {
            size_t off = ((size_t)(b * QQ + qb)) * 512 + (h >> 2) * 64;
            tk = gk + off; tv = gv + off; stride = 512;
        }
        #pragma unroll
        for (int half = 0; half < 2; half++) {
            int rl = wid * 16 + lg + half * 8;
            const __nv_bfloat16* qhp = (const __nv_bfloat16*)(smp + SM_QH + rl * QROWB);
            const __nv_bfloat16* qlp = (const __nv_bfloat16*)(smp + SM_QL + rl * QROWB);
            float dot = 0.f;
            #pragma unroll
            for (int dd = 0; dd < 16; dd++) {
                int d = lq * 16 + dd;
                float qv = __bfloat162float(qhp[d]) + __bfloat162float(qlp[d]);
                dot += qv * tk[(size_t)rl * stride + d];
            }
            dot += __shfl_xor_sync(0xffffffffu, dot, 1);
            dot += __shfl_xor_sync(0xffffffffu, dot, 2);
            float mo = half ? mr1 : mr0;
            float mn = fmaxf(mo, dot);
            float a = __expf(mo - mn), p = __expf(dot - mn);
            if (half) { mr1 = mn; lr1 = lr1 * a + p; }
            else      { mr0 = mn; lr0 = lr0 * a + p; }
            #pragma unroll
            for (int nf = 0; nf < 8; nf++) {
                int d0 = nf * 8 + 2 * lq;
                float v0 = tv[(size_t)rl * stride + d0];
                float v1 = tv[(size_t)rl * stride + d0 + 1];
                o[nf][2 * half]     = o[nf][2 * half]     * a + p * v0;
                o[nf][2 * half + 1] = o[nf][2 * half + 1] * a + p * v1;
            }
        }
    }

    float inv0 = 1.f / lr0, inv1 = 1.f / lr1;
    #pragma unroll
    for (int half = 0; half < 2; half++) {
        int qrow = qb + wid * 16 + lg + half * 8;
        float inv = half ? inv1 : inv0;
        size_t base = ((size_t)(b * QQ) + qrow) * 2048 + h * 64;
        #pragma unroll
        for (int nf = 0; nf < 8; nf++) {
            float x0 = o[nf][2 * half] * inv;
            float x1 = o[nf][2 * half + 1] * inv;
            __nv_bfloat16 h0 = __float2bfloat16(x0), h1 = __float2bfloat16(x1);
            __nv_bfloat162 hp; hp.x = h0; hp.y = h1;
            *(__nv_bfloat162*)(outh + base + nf * 8 + 2 * lq) = hp;
            __nv_bfloat162 lp;
            lp.x = __float2bfloat16(x0 - __bfloat162float(h0));
            lp.y = __float2bfloat16(x1 - __bfloat162float(h1));
            *(__nv_bfloat162*)(outl + base + nf * 8 + 2 * lq) = lp;
        }
    }
}

// ---------------------------------------------------------------------------
// Launch
// ---------------------------------------------------------------------------
extern "C" void kernel_launch(void* const* d_in, const int* in_sizes, int n_in,
                              void* d_out, int out_size)
{
    (void)in_sizes; (void)n_in; (void)out_size;

    const float* hidden = (const float*)d_in[0];
    const float* Wq     = (const float*)d_in[1];
    const float* Wk     = (const float*)d_in[2];
    const float* Wv     = (const float*)d_in[3];
    const float* Wo     = (const float*)d_in[4];
    const float* ck     = (const float*)d_in[5];
    const float* cv     = (const float*)d_in[6];
    const int*   pos    = (const int*)d_in[8];
    float* out = (float*)d_out;

    float *gq, *gk, *gv;
    cudaGetSymbolAddress((void**)&gq, g_q);
    cudaGetSymbolAddress((void**)&gk, g_k);
    cudaGetSymbolAddress((void**)&gv, g_v);

    __nv_bfloat16 *hid_h, *hid_l, *wq_h, *wq_l, *wk_h, *wk_l, *wv_h, *wv_l;
    __nv_bfloat16 *wo_h, *wo_l, *at_h, *at_l, *qh, *ql, *k0h, *k0l, *v0h, *v0l;
    cudaGetSymbolAddress((void**)&hid_h, c_hid_h);
    cudaGetSymbolAddress((void**)&hid_l, c_hid_l);
    cudaGetSymbolAddress((void**)&wq_h,  c_wq_h);
    cudaGetSymbolAddress((void**)&wq_l,  c_wq_l);
    cudaGetSymbolAddress((void**)&wk_h,  c_wk_h);
    cudaGetSymbolAddress((void**)&wk_l,  c_wk_l);
    cudaGetSymbolAddress((void**)&wv_h,  c_wv_h);
    cudaGetSymbolAddress((void**)&wv_l,  c_wv_l);
    cudaGetSymbolAddress((void**)&wo_h,  c_wo_h);
    cudaGetSymbolAddress((void**)&wo_l,  c_wo_l);
    cudaGetSymbolAddress((void**)&at_h,  c_at_h);
    cudaGetSymbolAddress((void**)&at_l,  c_at_l);
    cudaGetSymbolAddress((void**)&qh,    c_qh);
    cudaGetSymbolAddress((void**)&ql,    c_ql);
    cudaGetSymbolAddress((void**)&k0h,   c_k0h);
    cudaGetSymbolAddress((void**)&k0l,   c_k0l);
    cudaGetSymbolAddress((void**)&v0h,   c_v0h);
    cudaGetSymbolAddress((void**)&v0l,   c_v0l);

    cudaFuncSetAttribute(gemm_tc,
                         cudaFuncAttributeMaxDynamicSharedMemorySize, GSMEM_BYTES);
    cudaFuncSetAttribute(attn_mma,
                         cudaFuncAttributeMaxDynamicSharedMemorySize, ATTN_SMEM2);

    const int M = BB * QQ;   // 2048
    const int NK0 = BB * HH * QQ * HD;

    setup_invf<<<1, 32>>>();

    {
        int n;
        n = 2048 * 4096; convert_hl<<<n / 4096, 256>>>(hidden, hid_h, hid_l, n / 4, 1.f);
        n = 2048 * 4096; convert_hl<<<n / 4096, 256>>>(Wq, wq_h, wq_l, n / 4, 1.f);
        n = 512  * 4096; convert_hl<<<n / 4096, 256>>>(Wk, wk_h, wk_l, n / 4, 1.f);
        n = 512  * 4096; convert_hl<<<n / 4096, 256>>>(Wv, wv_h, wv_l, n / 4, 1.f);
        n = 2048 * 2048; convert_hl<<<n / 4096, 256>>>(Wo, wo_h, wo_l, n / 4, 1.f);
        convert_hl<<<NK0 / 4096, 256>>>(ck, k0h, k0l, NK0 / 4, 1.f);
        convert_hl<<<NK0 / 4096, 256>>>(cv, v0h, v0l, NK0 / 4, 1.f);
    }

    gemm_tc<<<dim3(24, M / 128), 256, GSMEM_BYTES>>>(
        hid_h, hid_l,
        wq_h, wq_l, gq, HH * HD,
        wk_h, wk_l, gk, KVH * HD,
        wv_h, wv_l, gv, KVH * HD,
        K2HS);

    // fused RoPE + Q split (k rotated in place, fp32)
    {
        int total = BB * QQ * (HH + KVH) * 32;
        rope_conv<<<(total + 255) / 256, 256>>>(gq, gk, pos, qh, ql);
    }

    attn_mma<<<dim3(QQ / BQ, HH, BB), 256, ATTN_SMEM2>>>(
        qh, ql, k0h, k0l, v0h, v0l, ck, cv, gk, gv, at_h, at_l);

    gemm_tc<<<dim3(16, M / 128), 256, GSMEM_BYTES>>>(
        at_h, at_l,
        wo_h, wo_l, out, HS,
        (const __nv_bfloat16*)0, (const __nv_bfloat16*)0, (float*)0, 0,
        (const __nv_bfloat16*)0, (const __nv_bfloat16*)0, (float*)0, 0,
        HH * HD);
}

// round 9
// speedup vs baseline: 4.0108x; 1.3379x over previous
#include <cuda_runtime.h>
#include <cuda_fp16.h>
#include <math.h>
#include <stdint.h>

// ---------------------------------------------------------------------------
// Problem constants
// ---------------------------------------------------------------------------
#define BB    2
#define QQ    1024
#define HH    32
#define KVH   8
#define HD    64
#define HS    2048
#define K2HS  4096
#define LCK   2
#define SCALE 0.125f

#define NEG_INF (__int_as_float(0xff800000))

// ---------------------------------------------------------------------------
// Scratch (no cudaMalloc allowed)
// ---------------------------------------------------------------------------
__device__ float g_q  [BB * QQ * HH  * HD];
__device__ float g_k  [BB * QQ * KVH * HD];
__device__ float g_v  [BB * QQ * KVH * HD];
__device__ double g_invf[32];

// fp16 operands: A-side split (hi/lo), B-side single
__device__ __half c_hid_h[2048 * 4096];
__device__ __half c_hid_l[2048 * 4096];
__device__ __half c_wq [2048 * 4096];
__device__ __half c_wk [512  * 4096];
__device__ __half c_wv [512  * 4096];
__device__ __half c_wo [2048 * 2048];
__device__ __half c_at_h[2048 * 2048];
__device__ __half c_at_l[2048 * 2048];
__device__ __half c_qh [2048 * 2048];
__device__ __half c_ql [2048 * 2048];
__device__ __half c_k0 [BB * HH * QQ * HD];
__device__ __half c_v0 [BB * HH * QQ * HD];

// ---------------------------------------------------------------------------
// PTX helpers — plain-sm_100 legal only
// ---------------------------------------------------------------------------
__device__ __forceinline__ uint32_t smem_u32(const void* p) {
    uint32_t a;
    asm("{ .reg .u64 t; cvta.to.shared.u64 t, %1; cvt.u32.u64 %0, t; }"
        : "=r"(a) : "l"(p));
    return a;
}

#define CP_ASYNC16(dst, src) \
    asm volatile("cp.async.cg.shared.global [%0], [%1], 16;" \
                 :: "r"((uint32_t)(dst)), "l"(src))
#define CP_COMMIT() asm volatile("cp.async.commit_group;" ::: "memory")
#define CP_WAIT0()  asm volatile("cp.async.wait_group 0;" ::: "memory")
#define CP_WAIT1()  asm volatile("cp.async.wait_group 1;" ::: "memory")
#define CP_WAIT2()  asm volatile("cp.async.wait_group 2;" ::: "memory")

__device__ __forceinline__ void ldsm4(uint32_t* r, uint32_t addr) {
    asm volatile("ldmatrix.sync.aligned.m8n8.x4.shared.b16 {%0,%1,%2,%3}, [%4];"
        : "=r"(r[0]), "=r"(r[1]), "=r"(r[2]), "=r"(r[3]) : "r"(addr));
}
__device__ __forceinline__ void ldsm4t(uint32_t* r, uint32_t addr) {
    asm volatile("ldmatrix.sync.aligned.m8n8.x4.trans.shared.b16 {%0,%1,%2,%3}, [%4];"
        : "=r"(r[0]), "=r"(r[1]), "=r"(r[2]), "=r"(r[3]) : "r"(addr));
}

__device__ __forceinline__ void mma_tc(float* d, const uint32_t* a, const uint32_t* b) {
    asm volatile(
        "mma.sync.aligned.m16n8k16.row.col.f32.f16.f16.f32 "
        "{%0,%1,%2,%3}, {%4,%5,%6,%7}, {%8,%9}, {%0,%1,%2,%3};"
        : "+f"(d[0]), "+f"(d[1]), "+f"(d[2]), "+f"(d[3])
        : "r"(a[0]), "r"(a[1]), "r"(a[2]), "r"(a[3]), "r"(b[0]), "r"(b[1]));
}

// packhf(hi, lo): hi -> upper 16 bits, lo -> lower 16 bits
__device__ __forceinline__ uint32_t packhf(float hi, float lo) {
    uint32_t r;
    asm("cvt.rn.f16x2.f32 %0, %1, %2;" : "=r"(r) : "f"(hi), "f"(lo));
    return r;
}

// ---------------------------------------------------------------------------
// inv_freq table setup (exact double pow, once)
// ---------------------------------------------------------------------------
__global__ void setup_invf()
{
    int d = threadIdx.x;
    if (d < 32) g_invf[d] = pow(10000.0, -(double)d / 32.0);
}

// ---------------------------------------------------------------------------
// fp32 -> (fp16 hi, fp16 lo) split conversion (hidden, scale=1).
// 4 float4 per thread; grid = n_floats/4096.
// ---------------------------------------------------------------------------
__global__ void convert_hl16(const float* __restrict__ x, __half* __restrict__ h,
                             __half* __restrict__ l)
{
    int i0 = blockIdx.x * 1024 + threadIdx.x;
    float4 v[4];
    #pragma unroll
    for (int u = 0; u < 4; u++)
        v[u] = ((const float4*)x)[i0 + u * 256];
    #pragma unroll
    for (int u = 0; u < 4; u++) {
        int i = i0 + u * 256;
        __half h0 = __float2half(v[u].x);
        __half h1 = __float2half(v[u].y);
        __half h2 = __float2half(v[u].z);
        __half h3 = __float2half(v[u].w);
        __half2* hp = (__half2*)h + i * 2;
        __half2* lp = (__half2*)l + i * 2;
        hp[0] = __halves2half2(h0, h1);
        hp[1] = __halves2half2(h2, h3);
        lp[0] = __halves2half2(__float2half(v[u].x - __half2float(h0)),
                               __float2half(v[u].y - __half2float(h1)));
        lp[1] = __halves2half2(__float2half(v[u].z - __half2float(h2)),
                               __float2half(v[u].w - __half2float(h3)));
    }
}

// ---------------------------------------------------------------------------
// Batched fp32 -> fp16 single conversion (weights + kv cache): 6 jobs, one
// launch. Each block = 1024 float4. start[] = prefix sums of per-job blocks.
// ---------------------------------------------------------------------------
struct BatchJobs {
    const float* x[6];
    __half*      h[6];
    int          start[6];
};

__global__ void convert_batch(BatchJobs jb)
{
    int bid = blockIdx.x;
    int s = 0;
    #pragma unroll
    for (int k = 1; k < 6; k++)
        if (bid >= jb.start[k]) s = k;
    const float4* xp = (const float4*)jb.x[s];
    __half2* hp = (__half2*)jb.h[s];
    int i0 = (bid - jb.start[s]) * 1024 + threadIdx.x;
    float4 v[4];
    #pragma unroll
    for (int u = 0; u < 4; u++)
        v[u] = xp[i0 + u * 256];
    #pragma unroll
    for (int u = 0; u < 4; u++) {
        int i = i0 + u * 256;
        hp[2 * i]     = __halves2half2(__float2half(v[u].x), __float2half(v[u].y));
        hp[2 * i + 1] = __halves2half2(__float2half(v[u].z), __float2half(v[u].w));
    }
}

// ---------------------------------------------------------------------------
// Fused RoPE (+ Q scale + fp16 hi/lo split). k rotated in place (fp32).
// ---------------------------------------------------------------------------
__global__ void rope_conv(float* __restrict__ q, float* __restrict__ k,
                          const int* __restrict__ pos_ids,
                          __half* __restrict__ qh, __half* __restrict__ ql)
{
    const int NQ = BB * QQ * HH  * 32;
    const int NK = BB * QQ * KVH * 32;
    int i = blockIdx.x * blockDim.x + threadIdx.x;
    if (i >= NQ + NK) return;

    const double TWO_PI  = 6.283185307179586476925286766559;
    const double INV_2PI = 0.15915494309189533576888376337251;

    if (i < NQ) {
        int d = i & 31;
        int m = i >> 10;
        size_t off = (size_t)m * (HH * HD) + ((i >> 5) & (HH - 1)) * HD + d;
        double ang = (double)(pos_ids[m] + LCK) * g_invf[d];
        double r = fma(-rint(ang * INV_2PI), TWO_PI, ang);
        float s, c;
        sincosf((float)r, &s, &c);
        float a = q[off], b2 = q[off + 32];
        float r0 = (a * c - b2 * s) * SCALE;
        float r1 = (b2 * c + a * s) * SCALE;
        __half h0 = __float2half(r0);
        __half h1 = __float2half(r1);
        qh[off]      = h0;
        qh[off + 32] = h1;
        ql[off]      = __float2half(r0 - __half2float(h0));
        ql[off + 32] = __float2half(r1 - __half2float(h1));
    } else {
        int j = i - NQ;
        int d = j & 31;
        int m = j >> 8;
        size_t off = (size_t)m * (KVH * HD) + ((j >> 5) & (KVH - 1)) * HD + d;
        double ang = (double)(pos_ids[m] + LCK) * g_invf[d];
        double r = fma(-rint(ang * INV_2PI), TWO_PI, ang);
        float s, c;
        sincosf((float)r, &s, &c);
        float a = k[off], b2 = k[off + 32];
        k[off]      = a  * c - b2 * s;
        k[off + 32] = b2 * c + a  * s;
    }
}

// ---------------------------------------------------------------------------
// 2-product split-fp16 NT GEMM: C = (Ah+Al) @ B^T, B single fp16.
// BK=64, 4 stages, one __syncthreads per K-step.
// Stage = 3 tiles (Ah, Al, B) x 18432B; row stride 144B.
// ---------------------------------------------------------------------------
#define ROWB   144
#define TILEB  (128 * ROWB)          // 18432
#define STAGEB (3 * TILEB)           // 55296
#define GSMEM_BYTES (4 * STAGEB)     // 221184

__device__ __forceinline__ void load_stage(
    uint32_t sb, int buf, const char* Ah, const char* Al, const char* Bh,
    int bm, int bn, int kb, int K, int tid)
{
    uint32_t st = sb + buf * STAGEB;
    #pragma unroll
    for (int j = 0; j < 12; j++) {
        int c    = tid + 256 * j;           // 0..3071
        int tile = c >> 10;                 // 0..2
        int row  = (c >> 3) & 127;
        int ch   = c & 7;
        const char* base = (tile == 0) ? Ah : (tile == 1) ? Al : Bh;
        int rb = (tile < 2) ? bm : bn;
        uint32_t sa = st + tile * TILEB + row * ROWB + ch * 16;
        const char* ga = base + ((size_t)(rb + row) * K + kb + ch * 8) * 2;
        CP_ASYNC16(sa, ga);
    }
    CP_COMMIT();
}

__global__ __launch_bounds__(256, 1)
void gemm_tc(const __half* __restrict__ Ah_, const __half* __restrict__ Al_,
             const __half* B0, float* C0, int N0,
             const __half* B1, float* C1, int N1,
             const __half* B2, float* C2, int N2,
             int K)
{
    extern __shared__ __align__(16) char smx[];
    uint32_t sb = smem_u32(smx);
    const int tid  = threadIdx.x;
    const int wid  = tid >> 5;
    const int lane = tid & 31;
    const int wm   = wid >> 1;
    const int wn   = wid & 1;
    const int bm   = blockIdx.y * 128;

    int xt = blockIdx.x;
    const __half* Bh; float* C; int ldc, bn;
    int t0 = N0 >> 7, t1 = N1 >> 7;
    if (xt < t0)           { Bh = B0; C = C0; ldc = N0; bn = xt << 7; }
    else if (xt < t0 + t1) { Bh = B1; C = C1; ldc = N1; bn = (xt - t0) << 7; }
    else                   { Bh = B2; C = C2; ldc = N2; bn = (xt - t0 - t1) << 7; }

    const char* cAh = (const char*)Ah_;
    const char* cAl = (const char*)Al_;
    const char* cBh = (const char*)Bh;

    float acc[2][8][4];
    #pragma unroll
    for (int i = 0; i < 2; i++)
        #pragma unroll
        for (int j = 0; j < 8; j++)
            #pragma unroll
            for (int q = 0; q < 4; q++) acc[i][j][q] = 0.f;

    const int nk = K >> 6;
    load_stage(sb, 0, cAh, cAl, cBh, bm, bn, 0,   K, tid);
    load_stage(sb, 1, cAh, cAl, cBh, bm, bn, 64,  K, tid);
    load_stage(sb, 2, cAh, cAl, cBh, bm, bn, 128, K, tid);

    const int lr = lane & 15;
    const int lc = lane >> 4;

    for (int t = 0; t < nk; t++) {
        CP_WAIT2();
        __syncthreads();
        if (t + 3 < nk)
            load_stage(sb, (t + 3) & 3, cAh, cAl, cBh, bm, bn, (t + 3) * 64, K, tid);
        else
            CP_COMMIT();
        uint32_t st = sb + (t & 3) * STAGEB;

        #pragma unroll
        for (int k0 = 0; k0 < 64; k0 += 16) {
            uint32_t ah[2][4], al[2][4], bh[4][4];
            uint32_t ao = (uint32_t)((wm * 32 + lr) * ROWB + (k0 + lc * 8) * 2);
            ldsm4(ah[0], st + ao);
            ldsm4(ah[1], st + ao + 16 * ROWB);
            ldsm4(al[0], st + TILEB + ao);
            ldsm4(al[1], st + TILEB + ao + 16 * ROWB);
            uint32_t bo = (uint32_t)((wn * 64 + lr) * ROWB + (k0 + lc * 8) * 2);
            #pragma unroll
            for (int nt = 0; nt < 4; nt++)
                ldsm4(bh[nt], st + 2 * TILEB + bo + nt * 16 * ROWB);
            #pragma unroll
            for (int mt = 0; mt < 2; mt++) {
                #pragma unroll
                for (int nt = 0; nt < 4; nt++) {
                    uint32_t b0[2] = {bh[nt][0], bh[nt][2]};
                    uint32_t b1[2] = {bh[nt][1], bh[nt][3]};
                    mma_tc(acc[mt][2 * nt],     ah[mt], b0);
                    mma_tc(acc[mt][2 * nt],     al[mt], b0);
                    mma_tc(acc[mt][2 * nt + 1], ah[mt], b1);
                    mma_tc(acc[mt][2 * nt + 1], al[mt], b1);
                }
            }
        }
    }

    const int lg = lane >> 2;
    const int lq = lane & 3;
    #pragma unroll
    for (int mt = 0; mt < 2; mt++) {
        int row = bm + wm * 32 + mt * 16 + lg;
        #pragma unroll
        for (int nf = 0; nf < 8; nf++) {
            float* p = C + (size_t)row * ldc + bn + wn * 64 + nf * 8 + 2 * lq;
            *(float2*)p               = make_float2(acc[mt][nf][0], acc[mt][nf][1]);
            *(float2*)(p + 8 * ldc)   = make_float2(acc[mt][nf][2], acc[mt][nf][3]);
        }
    }
}

// ---------------------------------------------------------------------------
// Tensor-core flash attention, 2-product fp16.
// Q split (hi/lo), K/V single fp16. Stage = K tile + V tile (36.9KB), 2 stages.
// ---------------------------------------------------------------------------
#define BQ    128
#define BKEY  128
#define QROWB 144
#define SM_QH 0
#define SM_QL 18432
#define SM_ST 36864
#define STG_SZ 36864
#define OFF_KH 0
#define OFF_VH 18432
#define ATTN_SMEM2 (SM_ST + 2 * STG_SZ)   // 110592

__device__ __forceinline__ void attn_ldkv(uint32_t sb, int stg,
    const char* kh, const char* vh, size_t base2, int tid)
{
    uint32_t st = sb + SM_ST + stg * STG_SZ;
    #pragma unroll
    for (int j = 0; j < 4; j++) {
        int c = tid + 256 * j;
        int row = c >> 3, ch = c & 7;
        size_t off = base2 + (size_t)row * 128 + ch * 16;
        uint32_t d = row * QROWB + ch * 16;
        CP_ASYNC16(st + OFF_KH + d, kh + off);
        CP_ASYNC16(st + OFF_VH + d, vh + off);
    }
    CP_COMMIT();
}

__global__ __launch_bounds__(256, 1)
void attn_mma(const __half* __restrict__ qh_g, const __half* __restrict__ ql_g,
              const __half* __restrict__ k0, const __half* __restrict__ v0,
              const float* __restrict__ cache_k, const float* __restrict__ cache_v,
              const float* __restrict__ gk, const float* __restrict__ gv,
              __half* __restrict__ outh, __half* __restrict__ outl)
{
    extern __shared__ __align__(16) char smp[];
    uint32_t sb = smem_u32(smp);
    const int tid = threadIdx.x, wid = tid >> 5, lane = tid & 31;
    const int lg = lane >> 2, lq = lane & 3;
    const int qt = blockIdx.x, h = blockIdx.y, b = blockIdx.z;
    const int qb = qt * BQ;

    {
        const char* ch_ = (const char*)qh_g;
        const char* cl_ = (const char*)ql_g;
        #pragma unroll
        for (int j = 0; j < 4; j++) {
            int c = tid + 256 * j;
            int row = c >> 3, ch = c & 7;
            size_t off = (((size_t)(b * QQ + qb + row)) * 2048 + h * 64 + ch * 8) * 2;
            uint32_t d = row * QROWB + ch * 16;
            CP_ASYNC16(sb + SM_QH + d, ch_ + off);
            CP_ASYNC16(sb + SM_QL + d, cl_ + off);
        }
        CP_COMMIT();
    }

    const char* ck0 = (const char*)k0;
    const char* cv0 = (const char*)v0;
    size_t kvb2 = ((size_t)(b * HH + h)) * QQ * 64 * 2;
    attn_ldkv(sb, 0, ck0, cv0, kvb2, tid);
    if (qt >= 1)
        attn_ldkv(sb, 1, ck0, cv0, kvb2 + (size_t)BKEY * 128, tid);

    float s[16][4], o[8][4];
    #pragma unroll
    for (int nf = 0; nf < 8; nf++)
        #pragma unroll
        for (int c = 0; c < 4; c++) o[nf][c] = 0.f;
    float mr0 = NEG_INF, mr1 = NEG_INF, lr0 = 0.f, lr1 = 0.f;
    uint32_t qah[4][4], qal[4][4];

    for (int kt = 0; kt <= qt; kt++) {
        if (kt < qt) { CP_WAIT1(); } else { CP_WAIT0(); }
        __syncthreads();
        uint32_t st = sb + SM_ST + (kt & 1) * STG_SZ;

        if (kt == 0) {
            #pragma unroll
            for (int kc = 0; kc < 4; kc++) {
                uint32_t ao = (wid * 16 + (lane & 15)) * QROWB + (kc * 16 + (lane >> 4) * 8) * 2;
                ldsm4(qah[kc], sb + SM_QH + ao);
                ldsm4(qal[kc], sb + SM_QL + ao);
            }
        }

        #pragma unroll
        for (int nf = 0; nf < 16; nf++)
            #pragma unroll
            for (int c = 0; c < 4; c++) s[nf][c] = 0.f;
        #pragma unroll
        for (int kc = 0; kc < 4; kc++) {
            #pragma unroll
            for (int kg = 0; kg < 8; kg++) {
                uint32_t bo = (kg * 16 + (lane & 15)) * QROWB + (kc * 16 + (lane >> 4) * 8) * 2;
                uint32_t bh_[4];
                ldsm4(bh_, st + OFF_KH + bo);
                uint32_t b0[2] = {bh_[0], bh_[2]}, b1[2] = {bh_[1], bh_[3]};
                mma_tc(s[2 * kg],     qah[kc], b0);
                mma_tc(s[2 * kg],     qal[kc], b0);
                mma_tc(s[2 * kg + 1], qah[kc], b1);
                mma_tc(s[2 * kg + 1], qal[kc], b1);
            }
        }

        if (kt == qt) {
            int r0 = wid * 16 + lg;
            #pragma unroll
            for (int nf = 0; nf < 16; nf++) {
                int k0c = nf * 8 + 2 * lq;
                if (k0c     > r0)     s[nf][0] = -1e30f;
                if (k0c + 1 > r0)     s[nf][1] = -1e30f;
                if (k0c     > r0 + 8) s[nf][2] = -1e30f;
                if (k0c + 1 > r0 + 8) s[nf][3] = -1e30f;
            }
        }

        float mx0 = NEG_INF, mx1 = NEG_INF;
        #pragma unroll
        for (int nf = 0; nf < 16; nf++) {
            mx0 = fmaxf(mx0, fmaxf(s[nf][0], s[nf][1]));
            mx1 = fmaxf(mx1, fmaxf(s[nf][2], s[nf][3]));
        }
        mx0 = fmaxf(mx0, __shfl_xor_sync(0xffffffffu, mx0, 1));
        mx0 = fmaxf(mx0, __shfl_xor_sync(0xffffffffu, mx0, 2));
        mx1 = fmaxf(mx1, __shfl_xor_sync(0xffffffffu, mx1, 1));
        mx1 = fmaxf(mx1, __shfl_xor_sync(0xffffffffu, mx1, 2));
        float mn0 = fmaxf(mr0, mx0), mn1 = fmaxf(mr1, mx1);
        float al0 = __expf(mr0 - mn0), al1 = __expf(mr1 - mn1);
        mr0 = mn0; mr1 = mn1;
        float sum0 = 0.f, sum1 = 0.f;
        #pragma unroll
        for (int nf = 0; nf < 16; nf++) {
            s[nf][0] = __expf(s[nf][0] - mn0); sum0 += s[nf][0];
            s[nf][1] = __expf(s[nf][1] - mn0); sum0 += s[nf][1];
            s[nf][2] = __expf(s[nf][2] - mn1); sum1 += s[nf][2];
            s[nf][3] = __expf(s[nf][3] - mn1); sum1 += s[nf][3];
        }
        sum0 += __shfl_xor_sync(0xffffffffu, sum0, 1);
        sum0 += __shfl_xor_sync(0xffffffffu, sum0, 2);
        sum1 += __shfl_xor_sync(0xffffffffu, sum1, 1);
        sum1 += __shfl_xor_sync(0xffffffffu, sum1, 2);
        lr0 = lr0 * al0 + sum0;
        lr1 = lr1 * al1 + sum1;
        #pragma unroll
        for (int nf = 0; nf < 8; nf++) {
            o[nf][0] *= al0; o[nf][1] *= al0; o[nf][2] *= al1; o[nf][3] *= al1;
        }

        #pragma unroll
        for (int kc2 = 0; kc2 < 8; kc2++) {
            uint32_t pah[4], pal[4];
            #pragma unroll
            for (int t2 = 0; t2 < 2; t2++) {
                float* sv = s[2 * kc2 + t2];
                __half h0 = __float2half(sv[0]);
                __half h1 = __float2half(sv[1]);
                __half h2 = __float2half(sv[2]);
                __half h3 = __float2half(sv[3]);
                pah[2 * t2]     = ((uint32_t)__half_as_ushort(h1) << 16) | __half_as_ushort(h0);
                pah[2 * t2 + 1] = ((uint32_t)__half_as_ushort(h3) << 16) | __half_as_ushort(h2);
                pal[2 * t2]     = packhf(sv[1] - __half2float(h1), sv[0] - __half2float(h0));
                pal[2 * t2 + 1] = packhf(sv[3] - __half2float(h3), sv[2] - __half2float(h2));
            }
            #pragma unroll
            for (int dg = 0; dg < 4; dg++) {
                uint32_t vo = (kc2 * 16 + (lane & 15)) * QROWB + dg * 32 + (lane >> 4) * 16;
                uint32_t vh_[4];
                ldsm4t(vh_, st + OFF_VH + vo);
                uint32_t b0[2] = {vh_[0], vh_[1]}, b1[2] = {vh_[2], vh_[3]};
                mma_tc(o[2 * dg],     pah, b0);
                mma_tc(o[2 * dg],     pal, b0);
                mma_tc(o[2 * dg + 1], pah, b1);
                mma_tc(o[2 * dg + 1], pal, b1);
            }
        }
        __syncthreads();
        if (kt + 2 <= qt)
            attn_ldkv(sb, kt & 1, ck0, cv0,
                      kvb2 + (size_t)(kt + 2) * BKEY * 128, tid);
    }

    // ---- two diagonal tail keys per row ----
    #pragma unroll 1
    for (int e = 0; e < 2; e++) {
        const float* tk; const float* tv; int stride;
        if (e == 0) {
            size_t off = (((size_t)BB + b) * HH + h) * QQ * HD + (size_t)qb * HD;
            tk = cache_k + off; tv = cache_v + off; stride = 64;
        } else {
            size_t off = ((size_t)(b * QQ + qb)) * 512 + (h >> 2) * 64;
            tk = gk + off; tv = gv + off; stride = 512;
        }
        #pragma unroll
        for (int half = 0; half < 2; half++) {
            int rl = wid * 16 + lg + half * 8;
            const __half* qhp = (const __half*)(smp + SM_QH + rl * QROWB);
            const __half* qlp = (const __half*)(smp + SM_QL + rl * QROWB);
            float dot = 0.f;
            #pragma unroll
            for (int dd = 0; dd < 16; dd++) {
                int d = lq * 16 + dd;
                float qv = __half2float(qhp[d]) + __half2float(qlp[d]);
                dot += qv * tk[(size_t)rl * stride + d];
            }
            dot += __shfl_xor_sync(0xffffffffu, dot, 1);
            dot += __shfl_xor_sync(0xffffffffu, dot, 2);
            float mo = half ? mr1 : mr0;
            float mn = fmaxf(mo, dot);
            float a = __expf(mo - mn), p = __expf(dot - mn);
            if (half) { mr1 = mn; lr1 = lr1 * a + p; }
            else      { mr0 = mn; lr0 = lr0 * a + p; }
            #pragma unroll
            for (int nf = 0; nf < 8; nf++) {
                int d0 = nf * 8 + 2 * lq;
                float v0_ = tv[(size_t)rl * stride + d0];
                float v1_ = tv[(size_t)rl * stride + d0 + 1];
                o[nf][2 * half]     = o[nf][2 * half]     * a + p * v0_;
                o[nf][2 * half + 1] = o[nf][2 * half + 1] * a + p * v1_;
            }
        }
    }

    float inv0 = 1.f / lr0, inv1 = 1.f / lr1;
    #pragma unroll
    for (int half = 0; half < 2; half++) {
        int qrow = qb + wid * 16 + lg + half * 8;
        float inv = half ? inv1 : inv0;
        size_t base = ((size_t)(b * QQ) + qrow) * 2048 + h * 64;
        #pragma unroll
        for (int nf = 0; nf < 8; nf++) {
            float x0 = o[nf][2 * half] * inv;
            float x1 = o[nf][2 * half + 1] * inv;
            __half h0 = __float2half(x0), h1 = __float2half(x1);
            *(__half2*)(outh + base + nf * 8 + 2 * lq) = __halves2half2(h0, h1);
            *(__half2*)(outl + base + nf * 8 + 2 * lq) =
                __halves2half2(__float2half(x0 - __half2float(h0)),
                               __float2half(x1 - __half2float(h1)));
        }
    }
}

// ---------------------------------------------------------------------------
// Launch
// ---------------------------------------------------------------------------
extern "C" void kernel_launch(void* const* d_in, const int* in_sizes, int n_in,
                              void* d_out, int out_size)
{
    (void)in_sizes; (void)n_in; (void)out_size;

    const float* hidden = (const float*)d_in[0];
    const float* Wq     = (const float*)d_in[1];
    const float* Wk     = (const float*)d_in[2];
    const float* Wv     = (const float*)d_in[3];
    const float* Wo     = (const float*)d_in[4];
    const float* ck     = (const float*)d_in[5];
    const float* cv     = (const float*)d_in[6];
    const int*   pos    = (const int*)d_in[8];
    float* out = (float*)d_out;

    float *gq, *gk, *gv;
    cudaGetSymbolAddress((void**)&gq, g_q);
    cudaGetSymbolAddress((void**)&gk, g_k);
    cudaGetSymbolAddress((void**)&gv, g_v);

    __half *hid_h, *hid_l, *wq, *wk, *wv, *wo, *at_h, *at_l, *qh, *ql, *k0, *v0;
    cudaGetSymbolAddress((void**)&hid_h, c_hid_h);
    cudaGetSymbolAddress((void**)&hid_l, c_hid_l);
    cudaGetSymbolAddress((void**)&wq,    c_wq);
    cudaGetSymbolAddress((void**)&wk,    c_wk);
    cudaGetSymbolAddress((void**)&wv,    c_wv);
    cudaGetSymbolAddress((void**)&wo,    c_wo);
    cudaGetSymbolAddress((void**)&at_h,  c_at_h);
    cudaGetSymbolAddress((void**)&at_l,  c_at_l);
    cudaGetSymbolAddress((void**)&qh,    c_qh);
    cudaGetSymbolAddress((void**)&ql,    c_ql);
    cudaGetSymbolAddress((void**)&k0,    c_k0);
    cudaGetSymbolAddress((void**)&v0,    c_v0);

    cudaFuncSetAttribute(gemm_tc,
                         cudaFuncAttributeMaxDynamicSharedMemorySize, GSMEM_BYTES);
    cudaFuncSetAttribute(attn_mma,
                         cudaFuncAttributeMaxDynamicSharedMemorySize, ATTN_SMEM2);

    const int M = BB * QQ;   // 2048

    setup_invf<<<1, 32>>>();

    // hidden -> fp16 hi/lo split
    convert_hl16<<<2048 * 4096 / 4096, 256>>>(hidden, hid_h, hid_l);

    // weights + kv cache -> single fp16, one batched launch
    {
        BatchJobs jb;
        jb.x[0] = Wq; jb.h[0] = wq;   // 2048*4096 -> 2048 blocks
        jb.x[1] = Wk; jb.h[1] = wk;   //  512*4096 ->  512
        jb.x[2] = Wv; jb.h[2] = wv;   //  512*4096 ->  512
        jb.x[3] = Wo; jb.h[3] = wo;   // 2048*2048 -> 1024
        jb.x[4] = ck; jb.h[4] = k0;   // 4M        -> 1024
        jb.x[5] = cv; jb.h[5] = v0;   // 4M        -> 1024
        jb.start[0] = 0;    jb.start[1] = 2048; jb.start[2] = 2560;
        jb.start[3] = 3072; jb.start[4] = 4096; jb.start[5] = 5120;
        convert_batch<<<6144, 256>>>(jb);
    }

    // fused QKV projection (A = hidden split, B = weights single)
    gemm_tc<<<dim3(24, M / 128), 256, GSMEM_BYTES>>>(
        hid_h, hid_l,
        wq, gq, HH * HD,
        wk, gk, KVH * HD,
        wv, gv, KVH * HD,
        K2HS);

    // fused RoPE + Q split
    {
        int total = BB * QQ * (HH + KVH) * 32;
        rope_conv<<<(total + 255) / 256, 256>>>(gq, gk, pos, qh, ql);
    }

    attn_mma<<<dim3(QQ / BQ, HH, BB), 256, ATTN_SMEM2>>>(
        qh, ql, k0, v0, ck, cv, gk, gv, at_h, at_l);

    // output projection (A = attention out split, B = Wo single)
    gemm_tc<<<dim3(16, M / 128), 256, GSMEM_BYTES>>>(
        at_h, at_l,
        wo, out, HS,
        (const __half*)0, (float*)0, 0,
        (const __half*)0, (float*)0, 0,
        HH * HD);
}

// round 10
// speedup vs baseline: 4.2943x; 1.0707x over previous
#include <cuda_runtime.h>
#include <cuda_fp16.h>
#include <math.h>
#include <stdint.h>

// ---------------------------------------------------------------------------
// Problem constants
// ---------------------------------------------------------------------------
#define BB    2
#define QQ    1024
#define HH    32
#define KVH   8
#define HD    64
#define HS    2048
#define K2HS  4096
#define LCK   2
#define SCALE 0.125f

#define NEG_INF (__int_as_float(0xff800000))

// ---------------------------------------------------------------------------
// Scratch (no cudaMalloc allowed)
// ---------------------------------------------------------------------------
__device__ float g_q  [BB * QQ * HH  * HD];
__device__ float g_k  [BB * QQ * KVH * HD];
__device__ float g_v  [BB * QQ * KVH * HD];
__device__ double g_invf[32];

// fp16 operands: A-side split (hi/lo), B-side single
__device__ __half c_hid_h[2048 * 4096];
__device__ __half c_hid_l[2048 * 4096];
__device__ __half c_wq [2048 * 4096];
__device__ __half c_wk [512  * 4096];
__device__ __half c_wv [512  * 4096];
__device__ __half c_wo [2048 * 2048];
__device__ __half c_at_h[2048 * 2048];
__device__ __half c_at_l[2048 * 2048];
__device__ __half c_qh [2048 * 2048];
__device__ __half c_ql [2048 * 2048];
__device__ __half c_k0 [BB * HH * QQ * HD];
__device__ __half c_v0 [BB * HH * QQ * HD];

// ---------------------------------------------------------------------------
// PTX helpers — plain-sm_100 legal only
// ---------------------------------------------------------------------------
__device__ __forceinline__ uint32_t smem_u32(const void* p) {
    uint32_t a;
    asm("{ .reg .u64 t; cvta.to.shared.u64 t, %1; cvt.u32.u64 %0, t; }"
        : "=r"(a) : "l"(p));
    return a;
}

#define CP_ASYNC16(dst, src) \
    asm volatile("cp.async.cg.shared.global [%0], [%1], 16;" \
                 :: "r"((uint32_t)(dst)), "l"(src))
#define CP_COMMIT() asm volatile("cp.async.commit_group;" ::: "memory")
#define CP_WAIT0()  asm volatile("cp.async.wait_group 0;" ::: "memory")
#define CP_WAIT1()  asm volatile("cp.async.wait_group 1;" ::: "memory")

__device__ __forceinline__ void ldsm4(uint32_t* r, uint32_t addr) {
    asm volatile("ldmatrix.sync.aligned.m8n8.x4.shared.b16 {%0,%1,%2,%3}, [%4];"
        : "=r"(r[0]), "=r"(r[1]), "=r"(r[2]), "=r"(r[3]) : "r"(addr));
}
__device__ __forceinline__ void ldsm4t(uint32_t* r, uint32_t addr) {
    asm volatile("ldmatrix.sync.aligned.m8n8.x4.trans.shared.b16 {%0,%1,%2,%3}, [%4];"
        : "=r"(r[0]), "=r"(r[1]), "=r"(r[2]), "=r"(r[3]) : "r"(addr));
}

__device__ __forceinline__ void mma_tc(float* d, const uint32_t* a, const uint32_t* b) {
    asm volatile(
        "mma.sync.aligned.m16n8k16.row.col.f32.f16.f16.f32 "
        "{%0,%1,%2,%3}, {%4,%5,%6,%7}, {%8,%9}, {%0,%1,%2,%3};"
        : "+f"(d[0]), "+f"(d[1]), "+f"(d[2]), "+f"(d[3])
        : "r"(a[0]), "r"(a[1]), "r"(a[2]), "r"(a[3]), "r"(b[0]), "r"(b[1]));
}

__device__ __forceinline__ uint32_t packhf(float hi, float lo) {
    uint32_t r;
    asm("cvt.rn.f16x2.f32 %0, %1, %2;" : "=r"(r) : "f"(hi), "f"(lo));
    return r;
}

// ---------------------------------------------------------------------------
// inv_freq table setup (exact double pow, once)
// ---------------------------------------------------------------------------
__global__ void setup_invf()
{
    int d = threadIdx.x;
    if (d < 32) g_invf[d] = pow(10000.0, -(double)d / 32.0);
}

// ---------------------------------------------------------------------------
// fp32 -> (fp16 hi, fp16 lo) split conversion (hidden, scale=1).
// ---------------------------------------------------------------------------
__global__ void convert_hl16(const float* __restrict__ x, __half* __restrict__ h,
                             __half* __restrict__ l)
{
    int i0 = blockIdx.x * 1024 + threadIdx.x;
    float4 v[4];
    #pragma unroll
    for (int u = 0; u < 4; u++)
        v[u] = ((const float4*)x)[i0 + u * 256];
    #pragma unroll
    for (int u = 0; u < 4; u++) {
        int i = i0 + u * 256;
        __half h0 = __float2half(v[u].x);
        __half h1 = __float2half(v[u].y);
        __half h2 = __float2half(v[u].z);
        __half h3 = __float2half(v[u].w);
        __half2* hp = (__half2*)h + i * 2;
        __half2* lp = (__half2*)l + i * 2;
        hp[0] = __halves2half2(h0, h1);
        hp[1] = __halves2half2(h2, h3);
        lp[0] = __halves2half2(__float2half(v[u].x - __half2float(h0)),
                               __float2half(v[u].y - __half2float(h1)));
        lp[1] = __halves2half2(__float2half(v[u].z - __half2float(h2)),
                               __float2half(v[u].w - __half2float(h3)));
    }
}

// ---------------------------------------------------------------------------
// Batched fp32 -> fp16 single conversion (weights + kv cache): 6 jobs.
// ---------------------------------------------------------------------------
struct BatchJobs {
    const float* x[6];
    __half*      h[6];
    int          start[6];
};

__global__ void convert_batch(BatchJobs jb)
{
    int bid = blockIdx.x;
    int s = 0;
    #pragma unroll
    for (int k = 1; k < 6; k++)
        if (bid >= jb.start[k]) s = k;
    const float4* xp = (const float4*)jb.x[s];
    __half2* hp = (__half2*)jb.h[s];
    int i0 = (bid - jb.start[s]) * 1024 + threadIdx.x;
    float4 v[4];
    #pragma unroll
    for (int u = 0; u < 4; u++)
        v[u] = xp[i0 + u * 256];
    #pragma unroll
    for (int u = 0; u < 4; u++) {
        int i = i0 + u * 256;
        hp[2 * i]     = __halves2half2(__float2half(v[u].x), __float2half(v[u].y));
        hp[2 * i + 1] = __halves2half2(__float2half(v[u].z), __float2half(v[u].w));
    }
}

// ---------------------------------------------------------------------------
// Fused RoPE (+ Q scale + fp16 hi/lo split). k rotated in place (fp32).
// ---------------------------------------------------------------------------
__global__ void rope_conv(float* __restrict__ q, float* __restrict__ k,
                          const int* __restrict__ pos_ids,
                          __half* __restrict__ qh, __half* __restrict__ ql)
{
    const int NQ = BB * QQ * HH  * 32;
    const int NK = BB * QQ * KVH * 32;
    int i = blockIdx.x * blockDim.x + threadIdx.x;
    if (i >= NQ + NK) return;

    const double TWO_PI  = 6.283185307179586476925286766559;
    const double INV_2PI = 0.15915494309189533576888376337251;

    if (i < NQ) {
        int d = i & 31;
        int m = i >> 10;
        size_t off = (size_t)m * (HH * HD) + ((i >> 5) & (HH - 1)) * HD + d;
        double ang = (double)(pos_ids[m] + LCK) * g_invf[d];
        double r = fma(-rint(ang * INV_2PI), TWO_PI, ang);
        float s, c;
        sincosf((float)r, &s, &c);
        float a = q[off], b2 = q[off + 32];
        float r0 = (a * c - b2 * s) * SCALE;
        float r1 = (b2 * c + a * s) * SCALE;
        __half h0 = __float2half(r0);
        __half h1 = __float2half(r1);
        qh[off]      = h0;
        qh[off + 32] = h1;
        ql[off]      = __float2half(r0 - __half2float(h0));
        ql[off + 32] = __float2half(r1 - __half2float(h1));
    } else {
        int j = i - NQ;
        int d = j & 31;
        int m = j >> 8;
        size_t off = (size_t)m * (KVH * HD) + ((j >> 5) & (KVH - 1)) * HD + d;
        double ang = (double)(pos_ids[m] + LCK) * g_invf[d];
        double r = fma(-rint(ang * INV_2PI), TWO_PI, ang);
        float s, c;
        sincosf((float)r, &s, &c);
        float a = k[off], b2 = k[off + 32];
        k[off]      = a  * c - b2 * s;
        k[off + 32] = b2 * c + a  * s;
    }
}

// ---------------------------------------------------------------------------
// 2-product split-fp16 NT GEMM, 2-stage ring, 2 CTAs/SM co-resident.
// BK=64; stage = 3 tiles (Ah, Al, B) x 18432B = 55296B; 2 stages = 110592B.
// ---------------------------------------------------------------------------
#define ROWB   144
#define TILEB  (128 * ROWB)          // 18432
#define STAGEB (3 * TILEB)           // 55296
#define GSMEM_BYTES (2 * STAGEB)     // 110592

__device__ __forceinline__ void load_stage(
    uint32_t sb, int buf, const char* Ah, const char* Al, const char* Bh,
    int bm, int bn, int kb, int K, int tid)
{
    uint32_t st = sb + buf * STAGEB;
    #pragma unroll
    for (int j = 0; j < 12; j++) {
        int c    = tid + 256 * j;           // 0..3071
        int tile = c >> 10;                 // 0..2
        int row  = (c >> 3) & 127;
        int ch   = c & 7;
        const char* base = (tile == 0) ? Ah : (tile == 1) ? Al : Bh;
        int rb = (tile < 2) ? bm : bn;
        uint32_t sa = st + tile * TILEB + row * ROWB + ch * 16;
        const char* ga = base + ((size_t)(rb + row) * K + kb + ch * 8) * 2;
        CP_ASYNC16(sa, ga);
    }
    CP_COMMIT();
}

__global__ __launch_bounds__(256, 2)
void gemm_tc(const __half* __restrict__ Ah_, const __half* __restrict__ Al_,
             const __half* B0, float* C0, int N0,
             const __half* B1, float* C1, int N1,
             const __half* B2, float* C2, int N2,
             int K)
{
    extern __shared__ __align__(16) char smx[];
    uint32_t sb = smem_u32(smx);
    const int tid  = threadIdx.x;
    const int wid  = tid >> 5;
    const int lane = tid & 31;
    const int wm   = wid >> 1;
    const int wn   = wid & 1;
    const int bm   = blockIdx.y * 128;

    int xt = blockIdx.x;
    const __half* Bh; float* C; int ldc, bn;
    int t0 = N0 >> 7, t1 = N1 >> 7;
    if (xt < t0)           { Bh = B0; C = C0; ldc = N0; bn = xt << 7; }
    else if (xt < t0 + t1) { Bh = B1; C = C1; ldc = N1; bn = (xt - t0) << 7; }
    else                   { Bh = B2; C = C2; ldc = N2; bn = (xt - t0 - t1) << 7; }

    const char* cAh = (const char*)Ah_;
    const char* cAl = (const char*)Al_;
    const char* cBh = (const char*)Bh;

    float acc[2][8][4];
    #pragma unroll
    for (int i = 0; i < 2; i++)
        #pragma unroll
        for (int j = 0; j < 8; j++)
            #pragma unroll
            for (int q = 0; q < 4; q++) acc[i][j][q] = 0.f;

    const int nk = K >> 6;
    load_stage(sb, 0, cAh, cAl, cBh, bm, bn, 0,  K, tid);
    load_stage(sb, 1, cAh, cAl, cBh, bm, bn, 64, K, tid);

    const int lr = lane & 15;
    const int lc = lane >> 4;

    for (int t = 0; t < nk; t++) {
        CP_WAIT1();
        __syncthreads();
        uint32_t st = sb + (t & 1) * STAGEB;

        #pragma unroll
        for (int k0 = 0; k0 < 64; k0 += 16) {
            uint32_t ah[2][4], al[2][4], bh[4][4];
            uint32_t ao = (uint32_t)((wm * 32 + lr) * ROWB + (k0 + lc * 8) * 2);
            ldsm4(ah[0], st + ao);
            ldsm4(ah[1], st + ao + 16 * ROWB);
            ldsm4(al[0], st + TILEB + ao);
            ldsm4(al[1], st + TILEB + ao + 16 * ROWB);
            uint32_t bo = (uint32_t)((wn * 64 + lr) * ROWB + (k0 + lc * 8) * 2);
            #pragma unroll
            for (int nt = 0; nt < 4; nt++)
                ldsm4(bh[nt], st + 2 * TILEB + bo + nt * 16 * ROWB);
            #pragma unroll
            for (int mt = 0; mt < 2; mt++) {
                #pragma unroll
                for (int nt = 0; nt < 4; nt++) {
                    uint32_t b0[2] = {bh[nt][0], bh[nt][2]};
                    uint32_t b1[2] = {bh[nt][1], bh[nt][3]};
                    mma_tc(acc[mt][2 * nt],     ah[mt], b0);
                    mma_tc(acc[mt][2 * nt],     al[mt], b0);
                    mma_tc(acc[mt][2 * nt + 1], ah[mt], b1);
                    mma_tc(acc[mt][2 * nt + 1], al[mt], b1);
                }
            }
        }
        __syncthreads();
        if (t + 2 < nk)
            load_stage(sb, t & 1, cAh, cAl, cBh, bm, bn, (t + 2) * 64, K, tid);
        else
            CP_COMMIT();
    }

    const int lg = lane >> 2;
    const int lq = lane & 3;
    #pragma unroll
    for (int mt = 0; mt < 2; mt++) {
        int row = bm + wm * 32 + mt * 16 + lg;
        #pragma unroll
        for (int nf = 0; nf < 8; nf++) {
            float* p = C + (size_t)row * ldc + bn + wn * 64 + nf * 8 + 2 * lq;
            *(float2*)p               = make_float2(acc[mt][nf][0], acc[mt][nf][1]);
            *(float2*)(p + 8 * ldc)   = make_float2(acc[mt][nf][2], acc[mt][nf][3]);
        }
    }
}

// ---------------------------------------------------------------------------
// Tensor-core flash attention, 2-product fp16 (unchanged round-9 winner).
// ---------------------------------------------------------------------------
#define BQ    128
#define BKEY  128
#define QROWB 144
#define SM_QH 0
#define SM_QL 18432
#define SM_ST 36864
#define STG_SZ 36864
#define OFF_KH 0
#define OFF_VH 18432
#define ATTN_SMEM2 (SM_ST + 2 * STG_SZ)   // 110592

__device__ __forceinline__ void attn_ldkv(uint32_t sb, int stg,
    const char* kh, const char* vh, size_t base2, int tid)
{
    uint32_t st = sb + SM_ST + stg * STG_SZ;
    #pragma unroll
    for (int j = 0; j < 4; j++) {
        int c = tid + 256 * j;
        int row = c >> 3, ch = c & 7;
        size_t off = base2 + (size_t)row * 128 + ch * 16;
        uint32_t d = row * QROWB + ch * 16;
        CP_ASYNC16(st + OFF_KH + d, kh + off);
        CP_ASYNC16(st + OFF_VH + d, vh + off);
    }
    CP_COMMIT();
}

__global__ __launch_bounds__(256, 1)
void attn_mma(const __half* __restrict__ qh_g, const __half* __restrict__ ql_g,
              const __half* __restrict__ k0, const __half* __restrict__ v0,
              const float* __restrict__ cache_k, const float* __restrict__ cache_v,
              const float* __restrict__ gk, const float* __restrict__ gv,
              __half* __restrict__ outh, __half* __restrict__ outl)
{
    extern __shared__ __align__(16) char smp[];
    uint32_t sb = smem_u32(smp);
    const int tid = threadIdx.x, wid = tid >> 5, lane = tid & 31;
    const int lg = lane >> 2, lq = lane & 3;
    const int qt = blockIdx.x, h = blockIdx.y, b = blockIdx.z;
    const int qb = qt * BQ;

    {
        const char* ch_ = (const char*)qh_g;
        const char* cl_ = (const char*)ql_g;
        #pragma unroll
        for (int j = 0; j < 4; j++) {
            int c = tid + 256 * j;
            int row = c >> 3, ch = c & 7;
            size_t off = (((size_t)(b * QQ + qb + row)) * 2048 + h * 64 + ch * 8) * 2;
            uint32_t d = row * QROWB + ch * 16;
            CP_ASYNC16(sb + SM_QH + d, ch_ + off);
            CP_ASYNC16(sb + SM_QL + d, cl_ + off);
        }
        CP_COMMIT();
    }

    const char* ck0 = (const char*)k0;
    const char* cv0 = (const char*)v0;
    size_t kvb2 = ((size_t)(b * HH + h)) * QQ * 64 * 2;
    attn_ldkv(sb, 0, ck0, cv0, kvb2, tid);
    if (qt >= 1)
        attn_ldkv(sb, 1, ck0, cv0, kvb2 + (size_t)BKEY * 128, tid);

    float s[16][4], o[8][4];
    #pragma unroll
    for (int nf = 0; nf < 8; nf++)
        #pragma unroll
        for (int c = 0; c < 4; c++) o[nf][c] = 0.f;
    float mr0 = NEG_INF, mr1 = NEG_INF, lr0 = 0.f, lr1 = 0.f;
    uint32_t qah[4][4], qal[4][4];

    for (int kt = 0; kt <= qt; kt++) {
        if (kt < qt) { CP_WAIT1(); } else { CP_WAIT0(); }
        __syncthreads();
        uint32_t st = sb + SM_ST + (kt & 1) * STG_SZ;

        if (kt == 0) {
            #pragma unroll
            for (int kc = 0; kc < 4; kc++) {
                uint32_t ao = (wid * 16 + (lane & 15)) * QROWB + (kc * 16 + (lane >> 4) * 8) * 2;
                ldsm4(qah[kc], sb + SM_QH + ao);
                ldsm4(qal[kc], sb + SM_QL + ao);
            }
        }

        #pragma unroll
        for (int nf = 0; nf < 16; nf++)
            #pragma unroll
            for (int c = 0; c < 4; c++) s[nf][c] = 0.f;
        #pragma unroll
        for (int kc = 0; kc < 4; kc++) {
            #pragma unroll
            for (int kg = 0; kg < 8; kg++) {
                uint32_t bo = (kg * 16 + (lane & 15)) * QROWB + (kc * 16 + (lane >> 4) * 8) * 2;
                uint32_t bh_[4];
                ldsm4(bh_, st + OFF_KH + bo);
                uint32_t b0[2] = {bh_[0], bh_[2]}, b1[2] = {bh_[1], bh_[3]};
                mma_tc(s[2 * kg],     qah[kc], b0);
                mma_tc(s[2 * kg],     qal[kc], b0);
                mma_tc(s[2 * kg + 1], qah[kc], b1);
                mma_tc(s[2 * kg + 1], qal[kc], b1);
            }
        }

        if (kt == qt) {
            int r0 = wid * 16 + lg;
            #pragma unroll
            for (int nf = 0; nf < 16; nf++) {
                int k0c = nf * 8 + 2 * lq;
                if (k0c     > r0)     s[nf][0] = -1e30f;
                if (k0c + 1 > r0)     s[nf][1] = -1e30f;
                if (k0c     > r0 + 8) s[nf][2] = -1e30f;
                if (k0c + 1 > r0 + 8) s[nf][3] = -1e30f;
            }
        }

        float mx0 = NEG_INF, mx1 = NEG_INF;
        #pragma unroll
        for (int nf = 0; nf < 16; nf++) {
            mx0 = fmaxf(mx0, fmaxf(s[nf][0], s[nf][1]));
            mx1 = fmaxf(mx1, fmaxf(s[nf][2], s[nf][3]));
        }
        mx0 = fmaxf(mx0, __shfl_xor_sync(0xffffffffu, mx0, 1));
        mx0 = fmaxf(mx0, __shfl_xor_sync(0xffffffffu, mx0, 2));
        mx1 = fmaxf(mx1, __shfl_xor_sync(0xffffffffu, mx1, 1));
        mx1 = fmaxf(mx1, __shfl_xor_sync(0xffffffffu, mx1, 2));
        float mn0 = fmaxf(mr0, mx0), mn1 = fmaxf(mr1, mx1);
        float al0 = __expf(mr0 - mn0), al1 = __expf(mr1 - mn1);
        mr0 = mn0; mr1 = mn1;
        float sum0 = 0.f, sum1 = 0.f;
        #pragma unroll
        for (int nf = 0; nf < 16; nf++) {
            s[nf][0] = __expf(s[nf][0] - mn0); sum0 += s[nf][0];
            s[nf][1] = __expf(s[nf][1] - mn0); sum0 += s[nf][1];
            s[nf][2] = __expf(s[nf][2] - mn1); sum1 += s[nf][2];
            s[nf][3] = __expf(s[nf][3] - mn1); sum1 += s[nf][3];
        }
        sum0 += __shfl_xor_sync(0xffffffffu, sum0, 1);
        sum0 += __shfl_xor_sync(0xffffffffu, sum0, 2);
        sum1 += __shfl_xor_sync(0xffffffffu, sum1, 1);
        sum1 += __shfl_xor_sync(0xffffffffu, sum1, 2);
        lr0 = lr0 * al0 + sum0;
        lr1 = lr1 * al1 + sum1;
        #pragma unroll
        for (int nf = 0; nf < 8; nf++) {
            o[nf][0] *= al0; o[nf][1] *= al0; o[nf][2] *= al1; o[nf][3] *= al1;
        }

        #pragma unroll
        for (int kc2 = 0; kc2 < 8; kc2++) {
            uint32_t pah[4], pal[4];
            #pragma unroll
            for (int t2 = 0; t2 < 2; t2++) {
                float* sv = s[2 * kc2 + t2];
                __half h0 = __float2half(sv[0]);
                __half h1 = __float2half(sv[1]);
                __half h2 = __float2half(sv[2]);
                __half h3 = __float2half(sv[3]);
                pah[2 * t2]     = ((uint32_t)__half_as_ushort(h1) << 16) | __half_as_ushort(h0);
                pah[2 * t2 + 1] = ((uint32_t)__half_as_ushort(h3) << 16) | __half_as_ushort(h2);
                pal[2 * t2]     = packhf(sv[1] - __half2float(h1), sv[0] - __half2float(h0));
                pal[2 * t2 + 1] = packhf(sv[3] - __half2float(h3), sv[2] - __half2float(h2));
            }
            #pragma unroll
            for (int dg = 0; dg < 4; dg++) {
                uint32_t vo = (kc2 * 16 + (lane & 15)) * QROWB + dg * 32 + (lane >> 4) * 16;
                uint32_t vh_[4];
                ldsm4t(vh_, st + OFF_VH + vo);
                uint32_t b0[2] = {vh_[0], vh_[1]}, b1[2] = {vh_[2], vh_[3]};
                mma_tc(o[2 * dg],     pah, b0);
                mma_tc(o[2 * dg],     pal, b0);
                mma_tc(o[2 * dg + 1], pah, b1);
                mma_tc(o[2 * dg + 1], pal, b1);
            }
        }
        __syncthreads();
        if (kt + 2 <= qt)
            attn_ldkv(sb, kt & 1, ck0, cv0,
                      kvb2 + (size_t)(kt + 2) * BKEY * 128, tid);
    }

    // ---- two diagonal tail keys per row ----
    #pragma unroll 1
    for (int e = 0; e < 2; e++) {
        const float* tk; const float* tv; int stride;
        if (e == 0) {
            size_t off = (((size_t)BB + b) * HH + h) * QQ * HD + (size_t)qb * HD;
            tk = cache_k + off; tv = cache_v + off; stride = 64;
        } else {
            size_t off = ((size_t)(b * QQ + qb)) * 512 + (h >> 2) * 64;
            tk = gk + off; tv = gv + off; stride = 512;
        }
        #pragma unroll
        for (int half = 0; half < 2; half++) {
            int rl = wid * 16 + lg + half * 8;
            const __half* qhp = (const __half*)(smp + SM_QH + rl * QROWB);
            const __half* qlp = (const __half*)(smp + SM_QL + rl * QROWB);
            float dot = 0.f;
            #pragma unroll
            for (int dd = 0; dd < 16; dd++) {
                int d = lq * 16 + dd;
                float qv = __half2float(qhp[d]) + __half2float(qlp[d]);
                dot += qv * tk[(size_t)rl * stride + d];
            }
            dot += __shfl_xor_sync(0xffffffffu, dot, 1);
            dot += __shfl_xor_sync(0xffffffffu, dot, 2);
            float mo = half ? mr1 : mr0;
            float mn = fmaxf(mo, dot);
            float a = __expf(mo - mn), p = __expf(dot - mn);
            if (half) { mr1 = mn; lr1 = lr1 * a + p; }
            else      { mr0 = mn; lr0 = lr0 * a + p; }
            #pragma unroll
            for (int nf = 0; nf < 8; nf++) {
                int d0 = nf * 8 + 2 * lq;
                float v0_ = tv[(size_t)rl * stride + d0];
                float v1_ = tv[(size_t)rl * stride + d0 + 1];
                o[nf][2 * half]     = o[nf][2 * half]     * a + p * v0_;
                o[nf][2 * half + 1] = o[nf][2 * half + 1] * a + p * v1_;
            }
        }
    }

    float inv0 = 1.f / lr0, inv1 = 1.f / lr1;
    #pragma unroll
    for (int half = 0; half < 2; half++) {
        int qrow = qb + wid * 16 + lg + half * 8;
        float inv = half ? inv1 : inv0;
        size_t base = ((size_t)(b * QQ) + qrow) * 2048 + h * 64;
        #pragma unroll
        for (int nf = 0; nf < 8; nf++) {
            float x0 = o[nf][2 * half] * inv;
            float x1 = o[nf][2 * half + 1] * inv;
            __half h0 = __float2half(x0), h1 = __float2half(x1);
            *(__half2*)(outh + base + nf * 8 + 2 * lq) = __halves2half2(h0, h1);
            *(__half2*)(outl + base + nf * 8 + 2 * lq) =
                __halves2half2(__float2half(x0 - __half2float(h0)),
                               __float2half(x1 - __half2float(h1)));
        }
    }
}

// ---------------------------------------------------------------------------
// Launch
// ---------------------------------------------------------------------------
extern "C" void kernel_launch(void* const* d_in, const int* in_sizes, int n_in,
                              void* d_out, int out_size)
{
    (void)in_sizes; (void)n_in; (void)out_size;

    const float* hidden = (const float*)d_in[0];
    const float* Wq     = (const float*)d_in[1];
    const float* Wk     = (const float*)d_in[2];
    const float* Wv     = (const float*)d_in[3];
    const float* Wo     = (const float*)d_in[4];
    const float* ck     = (const float*)d_in[5];
    const float* cv     = (const float*)d_in[6];
    const int*   pos    = (const int*)d_in[8];
    float* out = (float*)d_out;

    float *gq, *gk, *gv;
    cudaGetSymbolAddress((void**)&gq, g_q);
    cudaGetSymbolAddress((void**)&gk, g_k);
    cudaGetSymbolAddress((void**)&gv, g_v);

    __half *hid_h, *hid_l, *wq, *wk, *wv, *wo, *at_h, *at_l, *qh, *ql, *k0, *v0;
    cudaGetSymbolAddress((void**)&hid_h, c_hid_h);
    cudaGetSymbolAddress((void**)&hid_l, c_hid_l);
    cudaGetSymbolAddress((void**)&wq,    c_wq);
    cudaGetSymbolAddress((void**)&wk,    c_wk);
    cudaGetSymbolAddress((void**)&wv,    c_wv);
    cudaGetSymbolAddress((void**)&wo,    c_wo);
    cudaGetSymbolAddress((void**)&at_h,  c_at_h);
    cudaGetSymbolAddress((void**)&at_l,  c_at_l);
    cudaGetSymbolAddress((void**)&qh,    c_qh);
    cudaGetSymbolAddress((void**)&ql,    c_ql);
    cudaGetSymbolAddress((void**)&k0,    c_k0);
    cudaGetSymbolAddress((void**)&v0,    c_v0);

    cudaFuncSetAttribute(gemm_tc,
                         cudaFuncAttributeMaxDynamicSharedMemorySize, GSMEM_BYTES);
    cudaFuncSetAttribute(attn_mma,
                         cudaFuncAttributeMaxDynamicSharedMemorySize, ATTN_SMEM2);

    const int M = BB * QQ;   // 2048

    setup_invf<<<1, 32>>>();

    // hidden -> fp16 hi/lo split
    convert_hl16<<<2048 * 4096 / 4096, 256>>>(hidden, hid_h, hid_l);

    // weights + kv cache -> single fp16, one batched launch
    {
        BatchJobs jb;
        jb.x[0] = Wq; jb.h[0] = wq;
        jb.x[1] = Wk; jb.h[1] = wk;
        jb.x[2] = Wv; jb.h[2] = wv;
        jb.x[3] = Wo; jb.h[3] = wo;
        jb.x[4] = ck; jb.h[4] = k0;
        jb.x[5] = cv; jb.h[5] = v0;
        jb.start[0] = 0;    jb.start[1] = 2048; jb.start[2] = 2560;
        jb.start[3] = 3072; jb.start[4] = 4096; jb.start[5] = 5120;
        convert_batch<<<6144, 256>>>(jb);
    }

    // fused QKV projection (A = hidden split, B = weights single)
    gemm_tc<<<dim3(24, M / 128), 256, GSMEM_BYTES>>>(
        hid_h, hid_l,
        wq, gq, HH * HD,
        wk, gk, KVH * HD,
        wv, gv, KVH * HD,
        K2HS);

    // fused RoPE + Q split
    {
        int total = BB * QQ * (HH + KVH) * 32;
        rope_conv<<<(total + 255) / 256, 256>>>(gq, gk, pos, qh, ql);
    }

    attn_mma<<<dim3(QQ / BQ, HH, BB), 256, ATTN_SMEM2>>>(
        qh, ql, k0, v0, ck, cv, gk, gv, at_h, at_l);

    // output projection (A = attention out split, B = Wo single)
    gemm_tc<<<dim3(16, M / 128), 256, GSMEM_BYTES>>>(
        at_h, at_l,
        wo, out, HS,
        (const __half*)0, (float*)0, 0,
        (const __half*)0, (float*)0, 0,
        HH * HD);
}